// round 9
// baseline (speedup 1.0000x reference)
#include <cuda_runtime.h>
#include <math.h>
#include <cstdint>

#define NB 4
#define TT 2048
#define DM 512
#define NH 8
#define HD 64
#define SCALE 0.125f

// Scratch (no allocation allowed)
__device__ float g_q[NB * NH * TT * HD];
__device__ float g_k[NB * NH * TT * HD];
__device__ float g_v[NB * NH * TT * HD];
__device__ float g_ctx[NB * TT * DM];
__device__ float g_rc[TT * 32];
__device__ float g_rs[TT * 32];

// pack two floats -> bf16x2 (e0 in low half), rne
__device__ __forceinline__ unsigned pack2(float e0, float e1) {
    unsigned r;
    asm("cvt.rn.bf16x2.f32 %0, %1, %2;" : "=r"(r) : "f"(e1), "f"(e0));
    return r;
}
__device__ __forceinline__ void split2(float f0, float f1, unsigned& hi, unsigned& lo) {
    unsigned h = pack2(f0, f1);
    float h0 = __uint_as_float(h << 16);
    float h1 = __uint_as_float(h & 0xFFFF0000u);
    lo = pack2(f0 - h0, f1 - h1);
    hi = h;
}
__device__ __forceinline__ void mmabf(float* c, const unsigned* a, const unsigned* b) {
    asm volatile(
        "mma.sync.aligned.m16n8k16.row.col.f32.bf16.bf16.f32 "
        "{%0,%1,%2,%3},{%4,%5,%6,%7},{%8,%9},{%0,%1,%2,%3};"
        : "+f"(c[0]), "+f"(c[1]), "+f"(c[2]), "+f"(c[3])
        : "r"(a[0]), "r"(a[1]), "r"(a[2]), "r"(a[3]), "r"(b[0]), "r"(b[1]));
}
__device__ __forceinline__ uint32_t smem_u32(const void* p) {
    uint32_t a;
    asm("{ .reg .u64 t; cvta.to.shared.u64 t, %1; cvt.u32.u64 %0, t; }" : "=r"(a) : "l"(p));
    return a;
}
__device__ __forceinline__ void ldsm_x4(unsigned* r, uint32_t addr) {
    asm volatile("ldmatrix.sync.aligned.m8n8.x4.shared.b16 {%0,%1,%2,%3}, [%4];"
                 : "=r"(r[0]), "=r"(r[1]), "=r"(r[2]), "=r"(r[3]) : "r"(addr));
}

// ---------------------------------------------------------------------------
// BF16x3 GEMM, block 128m x 128e, 8 warps (2m x 4e), warp tile 64m x 32e.
// K-chunk 32 (2 k16 steps), double-buffered smem, stride 20 u32 (80B).
// R6-style flow: LDG prefetch -> MMA -> split/STS -> sync.
// ---------------------------------------------------------------------------
#define GAH 0
#define GAL 2560
#define GWH 5120
#define GWL 7680
#define GBUF 10240

template <bool QKV>
__global__ void __launch_bounds__(256) gemm_bf(const float* __restrict__ A,
                                               const float* __restrict__ W,
                                               const float* __restrict__ bias,
                                               float* __restrict__ out) {
    extern __shared__ unsigned gsm[];
    const uint32_t sbase = smem_u32(gsm);

    const int e0 = blockIdx.x * 128;
    const int m0 = blockIdx.y * 128;
    const int tid = threadIdx.x;
    const int wid = tid >> 5, lane = tid & 31;
    const int wm = wid >> 2, wn = wid & 3;   // 2m x 4e
    const int g = lane >> 2, t4 = lane & 3;

    const float* Ap = QKV ? A : (const float*)g_ctx;

    float acc[4][4][4];
#pragma unroll
    for (int mt = 0; mt < 4; mt++)
#pragma unroll
        for (int nt = 0; nt < 4; nt++)
#pragma unroll
            for (int r = 0; r < 4; r++) acc[mt][nt][r] = 0.f;

    float4 av[4], wv[4];

#define LDG_CHUNK(KC)                                                              \
    do {                                                                           \
        _Pragma("unroll") for (int i = 0; i < 4; i++) {                            \
            int idx = tid + i * 256;                                               \
            int r = idx >> 3, k4 = idx & 7;                                        \
            av[i] = *(const float4*)(Ap + (size_t)(m0 + r) * 512 + (KC) + k4 * 4); \
        }                                                                          \
        _Pragma("unroll") for (int i = 0; i < 4; i++) {                            \
            int idx = tid + i * 256;                                               \
            int r = idx >> 3, k4 = idx & 7;                                        \
            wv[i] = *(const float4*)(W + (size_t)(e0 + r) * 512 + (KC) + k4 * 4);  \
        }                                                                          \
    } while (0)

#define STS_CHUNK(BUF)                                                    \
    do {                                                                  \
        unsigned* b_ = (BUF);                                             \
        _Pragma("unroll") for (int i = 0; i < 4; i++) {                   \
            int idx = tid + i * 256;                                      \
            int r = idx >> 3, k4 = idx & 7;                               \
            unsigned h0, l0, h1, l1;                                      \
            split2(av[i].x, av[i].y, h0, l0);                             \
            split2(av[i].z, av[i].w, h1, l1);                             \
            *(uint2*)&b_[GAH + r * 20 + k4 * 2] = make_uint2(h0, h1);     \
            *(uint2*)&b_[GAL + r * 20 + k4 * 2] = make_uint2(l0, l1);     \
        }                                                                 \
        _Pragma("unroll") for (int i = 0; i < 4; i++) {                   \
            int idx = tid + i * 256;                                      \
            int r = idx >> 3, k4 = idx & 7;                               \
            unsigned h0, l0, h1, l1;                                      \
            split2(wv[i].x, wv[i].y, h0, l0);                             \
            split2(wv[i].z, wv[i].w, h1, l1);                             \
            *(uint2*)&b_[GWH + r * 20 + k4 * 2] = make_uint2(h0, h1);     \
            *(uint2*)&b_[GWL + r * 20 + k4 * 2] = make_uint2(l0, l1);     \
        }                                                                 \
    } while (0)

    LDG_CHUNK(0);
    STS_CHUNK(gsm);
    __syncthreads();

    const uint32_t aRowOff = (uint32_t)(lane & 15) * 80;
    const uint32_t aColOff = (uint32_t)(lane >> 4) * 16;
    const uint32_t bRowOff = (uint32_t)((lane & 7) + ((lane >> 4) << 3)) * 80;
    const uint32_t bColOff = (uint32_t)((lane >> 3) & 1) * 16;

    int cur = 0;
    for (int kc = 0; kc < 512; kc += 32) {
        if (kc + 32 < 512) LDG_CHUNK(kc + 32);
        const uint32_t bb = sbase + cur * (GBUF * 4);
#pragma unroll
        for (int ks = 0; ks < 2; ks++) {
            const uint32_t kOff = ks * 32;
            unsigned bh[2][4], bl[2][4];
#pragma unroll
            for (int ntp = 0; ntp < 2; ntp++) {
                uint32_t base = bb + (wn * 32 + ntp * 16) * 80 + bRowOff + kOff + bColOff;
                ldsm_x4(bh[ntp], base + GWH * 4);
                ldsm_x4(bl[ntp], base + GWL * 4);
            }
#pragma unroll
            for (int mtp = 0; mtp < 2; mtp++) {
                unsigned ah[2][4], al[2][4];
#pragma unroll
                for (int mt2 = 0; mt2 < 2; mt2++) {
                    uint32_t base = bb + (wm * 64 + mtp * 32 + mt2 * 16) * 80 + aRowOff +
                                    kOff + aColOff;
                    ldsm_x4(ah[mt2], base + GAH * 4);
                    ldsm_x4(al[mt2], base + GAL * 4);
                }
#pragma unroll
                for (int mt2 = 0; mt2 < 2; mt2++)
#pragma unroll
                    for (int nt = 0; nt < 4; nt++) {
                        const unsigned* BH = &bh[nt >> 1][(nt & 1) * 2];
                        const unsigned* BL = &bl[nt >> 1][(nt & 1) * 2];
                        float* C = acc[mtp * 2 + mt2][nt];
                        mmabf(C, ah[mt2], BH);
                        mmabf(C, al[mt2], BH);
                        mmabf(C, ah[mt2], BL);
                    }
            }
        }
        if (kc + 32 < 512) STS_CHUNK(gsm + (cur ^ 1) * GBUF);
        __syncthreads();
        cur ^= 1;
    }

    if (QKV) {
#pragma unroll
        for (int mt = 0; mt < 4; mt++)
#pragma unroll
            for (int half = 0; half < 2; half++) {
                int m = m0 + wm * 64 + mt * 16 + g + half * 8;
                int nbt = m >> 11, tt = m & 2047;
#pragma unroll
                for (int nt = 0; nt < 4; nt++) {
                    int e = e0 + wn * 32 + nt * 8 + t4 * 2;
                    int sec = e >> 9;
                    int h = (e >> 6) & 7;
                    int d = e & 63;
                    float* buf = (sec == 0) ? g_q : (sec == 1) ? g_k : g_v;
                    *(float2*)(buf + (((size_t)(nbt * NH + h)) * TT + tt) * HD + d) =
                        make_float2(acc[mt][nt][half * 2], acc[mt][nt][half * 2 + 1]);
                }
            }
    } else {
#pragma unroll
        for (int mt = 0; mt < 4; mt++)
#pragma unroll
            for (int half = 0; half < 2; half++) {
                int m = m0 + wm * 64 + mt * 16 + g + half * 8;
#pragma unroll
                for (int nt = 0; nt < 4; nt++) {
                    int e = e0 + wn * 32 + nt * 8 + t4 * 2;
                    float2 bv = *(const float2*)(bias + e);
                    *(float2*)(out + (size_t)m * 512 + e) =
                        make_float2(acc[mt][nt][half * 2] + bv.x,
                                    acc[mt][nt][half * 2 + 1] + bv.y);
                }
            }
    }
}

// ---------------------------------------------------------------------------
// RoPE trig table
// ---------------------------------------------------------------------------
__global__ void __launch_bounds__(256) rope_table_kernel() {
    int idx = blockIdx.x * 256 + threadIdx.x;
    if (idx >= TT * 32) return;
    int t = idx >> 5, lane = idx & 31;
    double inv_freq = pow(10000.0, -((double)(2 * lane) / 64.0));
    float ang = (float)t * (float)inv_freq;
    g_rc[idx] = (float)cos((double)ang);
    g_rs[idx] = (float)sin((double)ang);
}

// ---------------------------------------------------------------------------
// Sliding-window attention (R8 known-good: bf16x3, ldmatrix, fused RoPE,
// register-resident P).
// ---------------------------------------------------------------------------
#define KHI 0
#define KLO 4608
#define VHI 9216
#define VLO 13568
#define ATT_SMEM_U32 17920

__global__ void __launch_bounds__(256) attn_kernel() {
    extern __shared__ unsigned sv[];
    const uint32_t sbase = smem_u32(sv);

    const int qt = blockIdx.x;
    const int h = blockIdx.y;
    const int n = blockIdx.z;
    const int q0 = qt * 128;
    const int tid = threadIdx.x;
    const int wid = tid >> 5, lane = tid & 31;
    const int g = lane >> 2, t4 = lane & 3;
    const int qr = wid * 16 + g;

    const size_t hb = ((size_t)(n * NH + h)) * TT * HD;
    const float* qg = g_q + hb;
    const float* kg = g_k + hb;
    const float* vg = g_v + hb;

    const uint32_t aRow36 = (uint32_t)(lane & 15) * 144;
    const uint32_t aColH = (uint32_t)(lane >> 4) * 16;
    const uint32_t bRow36 = (uint32_t)((lane & 7) + ((lane >> 4) << 3)) * 144;
    const uint32_t bRow68 = (uint32_t)((lane & 7) + ((lane >> 4) << 3)) * 272;
    const uint32_t bColH = (uint32_t)((lane >> 3) & 1) * 16;

    // stage Q with fused RoPE into the K region (freed before the loop)
#pragma unroll
    for (int i = 0; i < 4; i++) {
        int idx = tid + i * 256;
        int r = idx >> 3, d4 = idx & 7;
        const float* row = qg + (size_t)(q0 + r) * HD;
        float4 a = *(const float4*)(row + d4 * 4);
        float4 b = *(const float4*)(row + d4 * 4 + 32);
        const float4 cv = *(const float4*)(g_rc + (size_t)(q0 + r) * 32 + d4 * 4);
        const float4 sn = *(const float4*)(g_rs + (size_t)(q0 + r) * 32 + d4 * 4);
        float4 lo = make_float4(a.x * cv.x - b.x * sn.x, a.y * cv.y - b.y * sn.y,
                                a.z * cv.z - b.z * sn.z, a.w * cv.w - b.w * sn.w);
        float4 hi = make_float4(b.x * cv.x + a.x * sn.x, b.y * cv.y + a.y * sn.y,
                                b.z * cv.z + a.z * sn.z, b.w * cv.w + a.w * sn.w);
        unsigned h0, l0, h1, l1;
        split2(lo.x, lo.y, h0, l0);
        split2(lo.z, lo.w, h1, l1);
        *(uint2*)&sv[KHI + r * 36 + d4 * 2] = make_uint2(h0, h1);
        *(uint2*)&sv[KLO + r * 36 + d4 * 2] = make_uint2(l0, l1);
        split2(hi.x, hi.y, h0, l0);
        split2(hi.z, hi.w, h1, l1);
        *(uint2*)&sv[KHI + r * 36 + (d4 + 8) * 2] = make_uint2(h0, h1);
        *(uint2*)&sv[KLO + r * 36 + (d4 + 8) * 2] = make_uint2(l0, l1);
    }
    __syncthreads();

    unsigned aqh[4][4], aql[4][4];
#pragma unroll
    for (int ks = 0; ks < 4; ks++) {
        uint32_t base = sbase + (wid * 16) * 144 + aRow36 + ks * 32 + aColH;
        ldsm_x4(aqh[ks], base + KHI * 4);
        ldsm_x4(aql[ks], base + KLO * 4);
    }
    __syncthreads();

    float m_i[2] = {-1e30f, -1e30f};
    float l_i[2] = {0.f, 0.f};
    float o[8][4];
#pragma unroll
    for (int nt = 0; nt < 8; nt++)
#pragma unroll
        for (int r = 0; r < 4; r++) o[nt][r] = 0.f;

    int c0 = qt - 1; if (c0 < 0) c0 = 0;
    int c1 = qt + 1; if (c1 > 15) c1 = 15;

    for (int c = c0; c <= c1; c++) {
        const int j0 = c * 128;

        const int rowlo = q0 + wid * 16;
        int ntLo = (rowlo - 127 - j0) >> 3;
        if (ntLo < 0) ntLo = 0;
        ntLo &= ~1;
        int ntHi = (rowlo + 15 + 128 - j0) >> 3;
        if (ntHi > 15) ntHi = 15;
        ntHi |= 1;
        const int kspLo = ntLo >> 1, kspHi = ntHi >> 1;

        // stage K with fused RoPE
#pragma unroll
        for (int i = 0; i < 4; i++) {
            int idx = tid + i * 256;
            int r = idx >> 3, d4 = idx & 7;
            const float* row = kg + (size_t)(j0 + r) * HD;
            float4 a = *(const float4*)(row + d4 * 4);
            float4 b = *(const float4*)(row + d4 * 4 + 32);
            const float4 cv = *(const float4*)(g_rc + (size_t)(j0 + r) * 32 + d4 * 4);
            const float4 sn = *(const float4*)(g_rs + (size_t)(j0 + r) * 32 + d4 * 4);
            float4 lo = make_float4(a.x * cv.x - b.x * sn.x, a.y * cv.y - b.y * sn.y,
                                    a.z * cv.z - b.z * sn.z, a.w * cv.w - b.w * sn.w);
            float4 hi = make_float4(b.x * cv.x + a.x * sn.x, b.y * cv.y + a.y * sn.y,
                                    b.z * cv.z + a.z * sn.z, b.w * cv.w + a.w * sn.w);
            unsigned h0, l0, h1, l1;
            split2(lo.x, lo.y, h0, l0);
            split2(lo.z, lo.w, h1, l1);
            *(uint2*)&sv[KHI + r * 36 + d4 * 2] = make_uint2(h0, h1);
            *(uint2*)&sv[KLO + r * 36 + d4 * 2] = make_uint2(l0, l1);
            split2(hi.x, hi.y, h0, l0);
            split2(hi.z, hi.w, h1, l1);
            *(uint2*)&sv[KHI + r * 36 + (d4 + 8) * 2] = make_uint2(h0, h1);
            *(uint2*)&sv[KLO + r * 36 + (d4 + 8) * 2] = make_uint2(l0, l1);
        }
        // stage V transposed: Vt[dim][keypair], stride 68
#pragma unroll
        for (int i = 0; i < 4; i++) {
            int idx = tid + i * 256;
            int rp = idx >> 4, d4 = idx & 15;
            float4 va = *(const float4*)(vg + (size_t)(j0 + 2 * rp) * HD + d4 * 4);
            float4 vb = *(const float4*)(vg + (size_t)(j0 + 2 * rp + 1) * HD + d4 * 4);
            unsigned hh, ll;
            split2(va.x, vb.x, hh, ll);
            sv[VHI + (d4 * 4 + 0) * 68 + rp] = hh; sv[VLO + (d4 * 4 + 0) * 68 + rp] = ll;
            split2(va.y, vb.y, hh, ll);
            sv[VHI + (d4 * 4 + 1) * 68 + rp] = hh; sv[VLO + (d4 * 4 + 1) * 68 + rp] = ll;
            split2(va.z, vb.z, hh, ll);
            sv[VHI + (d4 * 4 + 2) * 68 + rp] = hh; sv[VLO + (d4 * 4 + 2) * 68 + rp] = ll;
            split2(va.w, vb.w, hh, ll);
            sv[VHI + (d4 * 4 + 3) * 68 + rp] = hh; sv[VLO + (d4 * 4 + 3) * 68 + rp] = ll;
        }
        __syncthreads();

        // S = Q . K^T (live n-tile pairs, ldmatrix x4)
        float s[16][4];
#pragma unroll
        for (int nt = 0; nt < 16; nt++)
#pragma unroll
            for (int r = 0; r < 4; r++) s[nt][r] = 0.f;

#pragma unroll
        for (int ntp = 0; ntp < 8; ntp++) {
            if (ntp * 2 < ntLo || ntp * 2 > ntHi) continue;
#pragma unroll
            for (int ks = 0; ks < 4; ks++) {
                unsigned bh4[4], bl4[4];
                uint32_t base = sbase + (ntp * 16) * 144 + bRow36 + ks * 32 + bColH;
                ldsm_x4(bh4, base + KHI * 4);
                ldsm_x4(bl4, base + KLO * 4);
                mmabf(s[ntp * 2], aqh[ks], bh4);
                mmabf(s[ntp * 2], aql[ks], bh4);
                mmabf(s[ntp * 2], aqh[ks], bl4);
                mmabf(s[ntp * 2 + 1], aqh[ks], bh4 + 2);
                mmabf(s[ntp * 2 + 1], aql[ks], bh4 + 2);
                mmabf(s[ntp * 2 + 1], aqh[ks], bl4 + 2);
            }
        }

        // mask + online softmax (P stays in s[] registers)
#pragma unroll
        for (int half = 0; half < 2; half++) {
            const int rowg = q0 + qr + half * 8;
            float mx = -1e30f;
#pragma unroll
            for (int nt = 0; nt < 16; nt++) {
                if (nt < ntLo || nt > ntHi) continue;
#pragma unroll
                for (int cc = 0; cc < 2; cc++) {
                    int colg = j0 + nt * 8 + t4 * 2 + cc;
                    bool valid = (colg >= rowg - 127) && (colg <= rowg + 128);
                    float v = valid ? s[nt][half * 2 + cc] * SCALE : -1e30f;
                    s[nt][half * 2 + cc] = v;
                    mx = fmaxf(mx, v);
                }
            }
            mx = fmaxf(mx, __shfl_xor_sync(0xffffffffu, mx, 1));
            mx = fmaxf(mx, __shfl_xor_sync(0xffffffffu, mx, 2));
            float mnew = fmaxf(m_i[half], mx);
            float alpha = __expf(m_i[half] - mnew);
            float sum = 0.f;
#pragma unroll
            for (int nt = 0; nt < 16; nt++) {
                if (nt < ntLo || nt > ntHi) continue;
#pragma unroll
                for (int cc = 0; cc < 2; cc++) {
                    float v = s[nt][half * 2 + cc];
                    float p = (v > -1e29f) ? __expf(v - mnew) : 0.f;
                    sum += p;
                    s[nt][half * 2 + cc] = p;
                }
            }
            sum += __shfl_xor_sync(0xffffffffu, sum, 1);
            sum += __shfl_xor_sync(0xffffffffu, sum, 2);
            l_i[half] = l_i[half] * alpha + sum;
            m_i[half] = mnew;
#pragma unroll
            for (int nt = 0; nt < 8; nt++) {
                o[nt][half * 2] *= alpha;
                o[nt][half * 2 + 1] *= alpha;
            }
        }

        // O += P . V (P repacked from score C-frags in registers)
#pragma unroll
        for (int ksp = 0; ksp < 8; ksp++) {
            if (ksp < kspLo || ksp > kspHi) continue;
            unsigned aph[4], apl[4];
            split2(s[2 * ksp][0], s[2 * ksp][1], aph[0], apl[0]);
            split2(s[2 * ksp][2], s[2 * ksp][3], aph[1], apl[1]);
            split2(s[2 * ksp + 1][0], s[2 * ksp + 1][1], aph[2], apl[2]);
            split2(s[2 * ksp + 1][2], s[2 * ksp + 1][3], aph[3], apl[3]);
#pragma unroll
            for (int ntp = 0; ntp < 4; ntp++) {
                unsigned bh4[4], bl4[4];
                uint32_t vbase = sbase + (ntp * 16) * 272 + bRow68 + ksp * 32 + bColH;
                ldsm_x4(bh4, vbase + VHI * 4);
                ldsm_x4(bl4, vbase + VLO * 4);
                mmabf(o[ntp * 2], aph, bh4);
                mmabf(o[ntp * 2], apl, bh4);
                mmabf(o[ntp * 2], aph, bl4);
                mmabf(o[ntp * 2 + 1], aph, bh4 + 2);
                mmabf(o[ntp * 2 + 1], apl, bh4 + 2);
                mmabf(o[ntp * 2 + 1], aph, bl4 + 2);
            }
        }
        __syncthreads();
    }

    // epilogue
#pragma unroll
    for (int half = 0; half < 2; half++) {
        const int rowg = q0 + qr + half * 8;
        const float invl = 1.f / l_i[half];
        const size_t ob = ((size_t)n * TT + rowg) * DM + h * HD;
#pragma unroll
        for (int nt = 0; nt < 8; nt++) {
            int d = nt * 8 + t4 * 2;
            *(float2*)(g_ctx + ob + d) =
                make_float2(o[nt][half * 2] * invl, o[nt][half * 2 + 1] * invl);
        }
    }
}

// ---------------------------------------------------------------------------
extern "C" void kernel_launch(void* const* d_in, const int* in_sizes, int n_in,
                              void* d_out, int out_size) {
    const float* x    = (const float*)d_in[0];   // [4,2048,512]
    const float* wqkv = (const float*)d_in[1];   // [1536,512]
    const float* outw = (const float*)d_in[2];   // [512,512]
    const float* outb = (const float*)d_in[3];   // [512]
    float* out = (float*)d_out;

    const int gemm_smem = 2 * GBUF * sizeof(unsigned);        // 81920
    const int att_smem = ATT_SMEM_U32 * sizeof(unsigned);     // 71680

    cudaFuncSetAttribute(gemm_bf<true>, cudaFuncAttributeMaxDynamicSharedMemorySize, gemm_smem);
    cudaFuncSetAttribute(gemm_bf<false>, cudaFuncAttributeMaxDynamicSharedMemorySize, gemm_smem);
    cudaFuncSetAttribute(attn_kernel, cudaFuncAttributeMaxDynamicSharedMemorySize, att_smem);

    rope_table_kernel<<<(TT * 32 + 255) / 256, 256>>>();
    gemm_bf<true><<<dim3(1536 / 128, 8192 / 128), 256, gemm_smem>>>(x, wqkv, nullptr, nullptr);
    attn_kernel<<<dim3(TT / 128, NH, NB), 256, att_smem>>>();
    gemm_bf<false><<<dim3(512 / 128, 8192 / 128), 256, gemm_smem>>>(nullptr, outw, outb, out);
}

// round 10
// speedup vs baseline: 1.0017x; 1.0017x over previous
#include <cuda_runtime.h>
#include <math.h>
#include <cstdint>

#define NB 4
#define TT 2048
#define DM 512
#define NH 8
#define HD 64
#define SCALE 0.125f

// Scratch (no allocation allowed)
__device__ float g_q[NB * NH * TT * HD];
__device__ float g_k[NB * NH * TT * HD];
__device__ float g_v[NB * NH * TT * HD];
__device__ float g_ctx[NB * TT * DM];
__device__ float g_rc[TT * 32];
__device__ float g_rs[TT * 32];

// pack two floats -> bf16x2 (e0 in low half), rne
__device__ __forceinline__ unsigned pack2(float e0, float e1) {
    unsigned r;
    asm("cvt.rn.bf16x2.f32 %0, %1, %2;" : "=r"(r) : "f"(e1), "f"(e0));
    return r;
}
__device__ __forceinline__ void split2(float f0, float f1, unsigned& hi, unsigned& lo) {
    unsigned h = pack2(f0, f1);
    float h0 = __uint_as_float(h << 16);
    float h1 = __uint_as_float(h & 0xFFFF0000u);
    lo = pack2(f0 - h0, f1 - h1);
    hi = h;
}
__device__ __forceinline__ void mmabf(float* c, const unsigned* a, const unsigned* b) {
    asm volatile(
        "mma.sync.aligned.m16n8k16.row.col.f32.bf16.bf16.f32 "
        "{%0,%1,%2,%3},{%4,%5,%6,%7},{%8,%9},{%0,%1,%2,%3};"
        : "+f"(c[0]), "+f"(c[1]), "+f"(c[2]), "+f"(c[3])
        : "r"(a[0]), "r"(a[1]), "r"(a[2]), "r"(a[3]), "r"(b[0]), "r"(b[1]));
}
__device__ __forceinline__ uint32_t smem_u32(const void* p) {
    uint32_t a;
    asm("{ .reg .u64 t; cvta.to.shared.u64 t, %1; cvt.u32.u64 %0, t; }" : "=r"(a) : "l"(p));
    return a;
}
__device__ __forceinline__ void ldsm_x4(unsigned* r, uint32_t addr) {
    asm volatile("ldmatrix.sync.aligned.m8n8.x4.shared.b16 {%0,%1,%2,%3}, [%4];"
                 : "=r"(r[0]), "=r"(r[1]), "=r"(r[2]), "=r"(r[3]) : "r"(addr));
}

// ---------------------------------------------------------------------------
// BF16x3 GEMM, block 128m x 128e, 512 threads = 16 warps (4m x 4e),
// warp tile 32m x 32e. K-chunk 32 (2 k16 steps), double-buffered smem,
// stride 20 u32 (80B). LDG prefetch -> MMA -> split/STS -> sync.
// ---------------------------------------------------------------------------
#define GAH 0
#define GAL 2560
#define GWH 5120
#define GWL 7680
#define GBUF 10240

template <bool QKV>
__global__ void __launch_bounds__(512, 1) gemm_bf(const float* __restrict__ A,
                                                  const float* __restrict__ W,
                                                  const float* __restrict__ bias,
                                                  float* __restrict__ out) {
    extern __shared__ unsigned gsm[];
    const uint32_t sbase = smem_u32(gsm);

    const int e0 = blockIdx.x * 128;
    const int m0 = blockIdx.y * 128;
    const int tid = threadIdx.x;
    const int wid = tid >> 5, lane = tid & 31;
    const int wm = wid >> 2, wn = wid & 3;   // 4m x 4e
    const int g = lane >> 2, t4 = lane & 3;

    const float* Ap = QKV ? A : (const float*)g_ctx;

    float acc[2][4][4];
#pragma unroll
    for (int mt = 0; mt < 2; mt++)
#pragma unroll
        for (int nt = 0; nt < 4; nt++)
#pragma unroll
            for (int r = 0; r < 4; r++) acc[mt][nt][r] = 0.f;

    float4 av[2], wv[2];

#define LDG_CHUNK(KC)                                                              \
    do {                                                                           \
        _Pragma("unroll") for (int i = 0; i < 2; i++) {                            \
            int idx = tid + i * 512;                                               \
            int r = idx >> 3, k4 = idx & 7;                                        \
            av[i] = *(const float4*)(Ap + (size_t)(m0 + r) * 512 + (KC) + k4 * 4); \
        }                                                                          \
        _Pragma("unroll") for (int i = 0; i < 2; i++) {                            \
            int idx = tid + i * 512;                                               \
            int r = idx >> 3, k4 = idx & 7;                                        \
            wv[i] = *(const float4*)(W + (size_t)(e0 + r) * 512 + (KC) + k4 * 4);  \
        }                                                                          \
    } while (0)

#define STS_CHUNK(BUF)                                                    \
    do {                                                                  \
        unsigned* b_ = (BUF);                                             \
        _Pragma("unroll") for (int i = 0; i < 2; i++) {                   \
            int idx = tid + i * 512;                                      \
            int r = idx >> 3, k4 = idx & 7;                               \
            unsigned h0, l0, h1, l1;                                      \
            split2(av[i].x, av[i].y, h0, l0);                             \
            split2(av[i].z, av[i].w, h1, l1);                             \
            *(uint2*)&b_[GAH + r * 20 + k4 * 2] = make_uint2(h0, h1);     \
            *(uint2*)&b_[GAL + r * 20 + k4 * 2] = make_uint2(l0, l1);     \
        }                                                                 \
        _Pragma("unroll") for (int i = 0; i < 2; i++) {                   \
            int idx = tid + i * 512;                                      \
            int r = idx >> 3, k4 = idx & 7;                               \
            unsigned h0, l0, h1, l1;                                      \
            split2(wv[i].x, wv[i].y, h0, l0);                             \
            split2(wv[i].z, wv[i].w, h1, l1);                             \
            *(uint2*)&b_[GWH + r * 20 + k4 * 2] = make_uint2(h0, h1);     \
            *(uint2*)&b_[GWL + r * 20 + k4 * 2] = make_uint2(l0, l1);     \
        }                                                                 \
    } while (0)

    LDG_CHUNK(0);
    STS_CHUNK(gsm);
    __syncthreads();

    const uint32_t aRowOff = (uint32_t)(lane & 15) * 80;
    const uint32_t aColOff = (uint32_t)(lane >> 4) * 16;
    const uint32_t bRowOff = (uint32_t)((lane & 7) + ((lane >> 4) << 3)) * 80;
    const uint32_t bColOff = (uint32_t)((lane >> 3) & 1) * 16;

    int cur = 0;
    for (int kc = 0; kc < 512; kc += 32) {
        if (kc + 32 < 512) LDG_CHUNK(kc + 32);
        const uint32_t bb = sbase + cur * (GBUF * 4);
#pragma unroll
        for (int ks = 0; ks < 2; ks++) {
            const uint32_t kOff = ks * 32;
            unsigned ah[2][4], al[2][4], bh[2][4], bl[2][4];
#pragma unroll
            for (int mt = 0; mt < 2; mt++) {
                uint32_t base = bb + (wm * 32 + mt * 16) * 80 + aRowOff + kOff + aColOff;
                ldsm_x4(ah[mt], base + GAH * 4);
                ldsm_x4(al[mt], base + GAL * 4);
            }
#pragma unroll
            for (int ntp = 0; ntp < 2; ntp++) {
                uint32_t base = bb + (wn * 32 + ntp * 16) * 80 + bRowOff + kOff + bColOff;
                ldsm_x4(bh[ntp], base + GWH * 4);
                ldsm_x4(bl[ntp], base + GWL * 4);
            }
#pragma unroll
            for (int mt = 0; mt < 2; mt++)
#pragma unroll
                for (int nt = 0; nt < 4; nt++) {
                    const unsigned* BH = &bh[nt >> 1][(nt & 1) * 2];
                    const unsigned* BL = &bl[nt >> 1][(nt & 1) * 2];
                    mmabf(acc[mt][nt], ah[mt], BH);
                    mmabf(acc[mt][nt], al[mt], BH);
                    mmabf(acc[mt][nt], ah[mt], BL);
                }
        }
        if (kc + 32 < 512) STS_CHUNK(gsm + (cur ^ 1) * GBUF);
        __syncthreads();
        cur ^= 1;
    }

    if (QKV) {
#pragma unroll
        for (int mt = 0; mt < 2; mt++)
#pragma unroll
            for (int half = 0; half < 2; half++) {
                int m = m0 + wm * 32 + mt * 16 + g + half * 8;
                int nbt = m >> 11, tt = m & 2047;
#pragma unroll
                for (int nt = 0; nt < 4; nt++) {
                    int e = e0 + wn * 32 + nt * 8 + t4 * 2;
                    int sec = e >> 9;
                    int h = (e >> 6) & 7;
                    int d = e & 63;
                    float* buf = (sec == 0) ? g_q : (sec == 1) ? g_k : g_v;
                    *(float2*)(buf + (((size_t)(nbt * NH + h)) * TT + tt) * HD + d) =
                        make_float2(acc[mt][nt][half * 2], acc[mt][nt][half * 2 + 1]);
                }
            }
    } else {
#pragma unroll
        for (int mt = 0; mt < 2; mt++)
#pragma unroll
            for (int half = 0; half < 2; half++) {
                int m = m0 + wm * 32 + mt * 16 + g + half * 8;
#pragma unroll
                for (int nt = 0; nt < 4; nt++) {
                    int e = e0 + wn * 32 + nt * 8 + t4 * 2;
                    float2 bv = *(const float2*)(bias + e);
                    *(float2*)(out + (size_t)m * 512 + e) =
                        make_float2(acc[mt][nt][half * 2] + bv.x,
                                    acc[mt][nt][half * 2 + 1] + bv.y);
                }
            }
    }
}

// ---------------------------------------------------------------------------
// RoPE trig table
// ---------------------------------------------------------------------------
__global__ void __launch_bounds__(256) rope_table_kernel() {
    int idx = blockIdx.x * 256 + threadIdx.x;
    if (idx >= TT * 32) return;
    int t = idx >> 5, lane = idx & 31;
    double inv_freq = pow(10000.0, -((double)(2 * lane) / 64.0));
    float ang = (float)t * (float)inv_freq;
    g_rc[idx] = (float)cos((double)ang);
    g_rs[idx] = (float)sin((double)ang);
}

// ---------------------------------------------------------------------------
// Sliding-window attention (R8 known-good: bf16x3, ldmatrix, fused RoPE,
// register-resident P).
// ---------------------------------------------------------------------------
#define KHI 0
#define KLO 4608
#define VHI 9216
#define VLO 13568
#define ATT_SMEM_U32 17920

__global__ void __launch_bounds__(256) attn_kernel() {
    extern __shared__ unsigned sv[];
    const uint32_t sbase = smem_u32(sv);

    const int qt = blockIdx.x;
    const int h = blockIdx.y;
    const int n = blockIdx.z;
    const int q0 = qt * 128;
    const int tid = threadIdx.x;
    const int wid = tid >> 5, lane = tid & 31;
    const int g = lane >> 2, t4 = lane & 3;
    const int qr = wid * 16 + g;

    const size_t hb = ((size_t)(n * NH + h)) * TT * HD;
    const float* qg = g_q + hb;
    const float* kg = g_k + hb;
    const float* vg = g_v + hb;

    const uint32_t aRow36 = (uint32_t)(lane & 15) * 144;
    const uint32_t aColH = (uint32_t)(lane >> 4) * 16;
    const uint32_t bRow36 = (uint32_t)((lane & 7) + ((lane >> 4) << 3)) * 144;
    const uint32_t bRow68 = (uint32_t)((lane & 7) + ((lane >> 4) << 3)) * 272;
    const uint32_t bColH = (uint32_t)((lane >> 3) & 1) * 16;

    // stage Q with fused RoPE into the K region (freed before the loop)
#pragma unroll
    for (int i = 0; i < 4; i++) {
        int idx = tid + i * 256;
        int r = idx >> 3, d4 = idx & 7;
        const float* row = qg + (size_t)(q0 + r) * HD;
        float4 a = *(const float4*)(row + d4 * 4);
        float4 b = *(const float4*)(row + d4 * 4 + 32);
        const float4 cv = *(const float4*)(g_rc + (size_t)(q0 + r) * 32 + d4 * 4);
        const float4 sn = *(const float4*)(g_rs + (size_t)(q0 + r) * 32 + d4 * 4);
        float4 lo = make_float4(a.x * cv.x - b.x * sn.x, a.y * cv.y - b.y * sn.y,
                                a.z * cv.z - b.z * sn.z, a.w * cv.w - b.w * sn.w);
        float4 hi = make_float4(b.x * cv.x + a.x * sn.x, b.y * cv.y + a.y * sn.y,
                                b.z * cv.z + a.z * sn.z, b.w * cv.w + a.w * sn.w);
        unsigned h0, l0, h1, l1;
        split2(lo.x, lo.y, h0, l0);
        split2(lo.z, lo.w, h1, l1);
        *(uint2*)&sv[KHI + r * 36 + d4 * 2] = make_uint2(h0, h1);
        *(uint2*)&sv[KLO + r * 36 + d4 * 2] = make_uint2(l0, l1);
        split2(hi.x, hi.y, h0, l0);
        split2(hi.z, hi.w, h1, l1);
        *(uint2*)&sv[KHI + r * 36 + (d4 + 8) * 2] = make_uint2(h0, h1);
        *(uint2*)&sv[KLO + r * 36 + (d4 + 8) * 2] = make_uint2(l0, l1);
    }
    __syncthreads();

    unsigned aqh[4][4], aql[4][4];
#pragma unroll
    for (int ks = 0; ks < 4; ks++) {
        uint32_t base = sbase + (wid * 16) * 144 + aRow36 + ks * 32 + aColH;
        ldsm_x4(aqh[ks], base + KHI * 4);
        ldsm_x4(aql[ks], base + KLO * 4);
    }
    __syncthreads();

    float m_i[2] = {-1e30f, -1e30f};
    float l_i[2] = {0.f, 0.f};
    float o[8][4];
#pragma unroll
    for (int nt = 0; nt < 8; nt++)
#pragma unroll
        for (int r = 0; r < 4; r++) o[nt][r] = 0.f;

    int c0 = qt - 1; if (c0 < 0) c0 = 0;
    int c1 = qt + 1; if (c1 > 15) c1 = 15;

    for (int c = c0; c <= c1; c++) {
        const int j0 = c * 128;

        const int rowlo = q0 + wid * 16;
        int ntLo = (rowlo - 127 - j0) >> 3;
        if (ntLo < 0) ntLo = 0;
        ntLo &= ~1;
        int ntHi = (rowlo + 15 + 128 - j0) >> 3;
        if (ntHi > 15) ntHi = 15;
        ntHi |= 1;
        const int kspLo = ntLo >> 1, kspHi = ntHi >> 1;

        // stage K with fused RoPE
#pragma unroll
        for (int i = 0; i < 4; i++) {
            int idx = tid + i * 256;
            int r = idx >> 3, d4 = idx & 7;
            const float* row = kg + (size_t)(j0 + r) * HD;
            float4 a = *(const float4*)(row + d4 * 4);
            float4 b = *(const float4*)(row + d4 * 4 + 32);
            const float4 cv = *(const float4*)(g_rc + (size_t)(j0 + r) * 32 + d4 * 4);
            const float4 sn = *(const float4*)(g_rs + (size_t)(j0 + r) * 32 + d4 * 4);
            float4 lo = make_float4(a.x * cv.x - b.x * sn.x, a.y * cv.y - b.y * sn.y,
                                    a.z * cv.z - b.z * sn.z, a.w * cv.w - b.w * sn.w);
            float4 hi = make_float4(b.x * cv.x + a.x * sn.x, b.y * cv.y + a.y * sn.y,
                                    b.z * cv.z + a.z * sn.z, b.w * cv.w + a.w * sn.w);
            unsigned h0, l0, h1, l1;
            split2(lo.x, lo.y, h0, l0);
            split2(lo.z, lo.w, h1, l1);
            *(uint2*)&sv[KHI + r * 36 + d4 * 2] = make_uint2(h0, h1);
            *(uint2*)&sv[KLO + r * 36 + d4 * 2] = make_uint2(l0, l1);
            split2(hi.x, hi.y, h0, l0);
            split2(hi.z, hi.w, h1, l1);
            *(uint2*)&sv[KHI + r * 36 + (d4 + 8) * 2] = make_uint2(h0, h1);
            *(uint2*)&sv[KLO + r * 36 + (d4 + 8) * 2] = make_uint2(l0, l1);
        }
        // stage V transposed: Vt[dim][keypair], stride 68
#pragma unroll
        for (int i = 0; i < 4; i++) {
            int idx = tid + i * 256;
            int rp = idx >> 4, d4 = idx & 15;
            float4 va = *(const float4*)(vg + (size_t)(j0 + 2 * rp) * HD + d4 * 4);
            float4 vb = *(const float4*)(vg + (size_t)(j0 + 2 * rp + 1) * HD + d4 * 4);
            unsigned hh, ll;
            split2(va.x, vb.x, hh, ll);
            sv[VHI + (d4 * 4 + 0) * 68 + rp] = hh; sv[VLO + (d4 * 4 + 0) * 68 + rp] = ll;
            split2(va.y, vb.y, hh, ll);
            sv[VHI + (d4 * 4 + 1) * 68 + rp] = hh; sv[VLO + (d4 * 4 + 1) * 68 + rp] = ll;
            split2(va.z, vb.z, hh, ll);
            sv[VHI + (d4 * 4 + 2) * 68 + rp] = hh; sv[VLO + (d4 * 4 + 2) * 68 + rp] = ll;
            split2(va.w, vb.w, hh, ll);
            sv[VHI + (d4 * 4 + 3) * 68 + rp] = hh; sv[VLO + (d4 * 4 + 3) * 68 + rp] = ll;
        }
        __syncthreads();

        // S = Q . K^T (live n-tile pairs, ldmatrix x4)
        float s[16][4];
#pragma unroll
        for (int nt = 0; nt < 16; nt++)
#pragma unroll
            for (int r = 0; r < 4; r++) s[nt][r] = 0.f;

#pragma unroll
        for (int ntp = 0; ntp < 8; ntp++) {
            if (ntp * 2 < ntLo || ntp * 2 > ntHi) continue;
#pragma unroll
            for (int ks = 0; ks < 4; ks++) {
                unsigned bh4[4], bl4[4];
                uint32_t base = sbase + (ntp * 16) * 144 + bRow36 + ks * 32 + bColH;
                ldsm_x4(bh4, base + KHI * 4);
                ldsm_x4(bl4, base + KLO * 4);
                mmabf(s[ntp * 2], aqh[ks], bh4);
                mmabf(s[ntp * 2], aql[ks], bh4);
                mmabf(s[ntp * 2], aqh[ks], bl4);
                mmabf(s[ntp * 2 + 1], aqh[ks], bh4 + 2);
                mmabf(s[ntp * 2 + 1], aql[ks], bh4 + 2);
                mmabf(s[ntp * 2 + 1], aqh[ks], bl4 + 2);
            }
        }

        // mask + online softmax (P stays in s[] registers)
#pragma unroll
        for (int half = 0; half < 2; half++) {
            const int rowg = q0 + qr + half * 8;
            float mx = -1e30f;
#pragma unroll
            for (int nt = 0; nt < 16; nt++) {
                if (nt < ntLo || nt > ntHi) continue;
#pragma unroll
                for (int cc = 0; cc < 2; cc++) {
                    int colg = j0 + nt * 8 + t4 * 2 + cc;
                    bool valid = (colg >= rowg - 127) && (colg <= rowg + 128);
                    float v = valid ? s[nt][half * 2 + cc] * SCALE : -1e30f;
                    s[nt][half * 2 + cc] = v;
                    mx = fmaxf(mx, v);
                }
            }
            mx = fmaxf(mx, __shfl_xor_sync(0xffffffffu, mx, 1));
            mx = fmaxf(mx, __shfl_xor_sync(0xffffffffu, mx, 2));
            float mnew = fmaxf(m_i[half], mx);
            float alpha = __expf(m_i[half] - mnew);
            float sum = 0.f;
#pragma unroll
            for (int nt = 0; nt < 16; nt++) {
                if (nt < ntLo || nt > ntHi) continue;
#pragma unroll
                for (int cc = 0; cc < 2; cc++) {
                    float v = s[nt][half * 2 + cc];
                    float p = (v > -1e29f) ? __expf(v - mnew) : 0.f;
                    sum += p;
                    s[nt][half * 2 + cc] = p;
                }
            }
            sum += __shfl_xor_sync(0xffffffffu, sum, 1);
            sum += __shfl_xor_sync(0xffffffffu, sum, 2);
            l_i[half] = l_i[half] * alpha + sum;
            m_i[half] = mnew;
#pragma unroll
            for (int nt = 0; nt < 8; nt++) {
                o[nt][half * 2] *= alpha;
                o[nt][half * 2 + 1] *= alpha;
            }
        }

        // O += P . V (P repacked from score C-frags in registers)
#pragma unroll
        for (int ksp = 0; ksp < 8; ksp++) {
            if (ksp < kspLo || ksp > kspHi) continue;
            unsigned aph[4], apl[4];
            split2(s[2 * ksp][0], s[2 * ksp][1], aph[0], apl[0]);
            split2(s[2 * ksp][2], s[2 * ksp][3], aph[1], apl[1]);
            split2(s[2 * ksp + 1][0], s[2 * ksp + 1][1], aph[2], apl[2]);
            split2(s[2 * ksp + 1][2], s[2 * ksp + 1][3], aph[3], apl[3]);
#pragma unroll
            for (int ntp = 0; ntp < 4; ntp++) {
                unsigned bh4[4], bl4[4];
                uint32_t vbase = sbase + (ntp * 16) * 272 + bRow68 + ksp * 32 + bColH;
                ldsm_x4(bh4, vbase + VHI * 4);
                ldsm_x4(bl4, vbase + VLO * 4);
                mmabf(o[ntp * 2], aph, bh4);
                mmabf(o[ntp * 2], apl, bh4);
                mmabf(o[ntp * 2], aph, bl4);
                mmabf(o[ntp * 2 + 1], aph, bh4 + 2);
                mmabf(o[ntp * 2 + 1], apl, bh4 + 2);
                mmabf(o[ntp * 2 + 1], aph, bl4 + 2);
            }
        }
        __syncthreads();
    }

    // epilogue
#pragma unroll
    for (int half = 0; half < 2; half++) {
        const int rowg = q0 + qr + half * 8;
        const float invl = 1.f / l_i[half];
        const size_t ob = ((size_t)n * TT + rowg) * DM + h * HD;
#pragma unroll
        for (int nt = 0; nt < 8; nt++) {
            int d = nt * 8 + t4 * 2;
            *(float2*)(g_ctx + ob + d) =
                make_float2(o[nt][half * 2] * invl, o[nt][half * 2 + 1] * invl);
        }
    }
}

// ---------------------------------------------------------------------------
extern "C" void kernel_launch(void* const* d_in, const int* in_sizes, int n_in,
                              void* d_out, int out_size) {
    const float* x    = (const float*)d_in[0];   // [4,2048,512]
    const float* wqkv = (const float*)d_in[1];   // [1536,512]
    const float* outw = (const float*)d_in[2];   // [512,512]
    const float* outb = (const float*)d_in[3];   // [512]
    float* out = (float*)d_out;

    const int gemm_smem = 2 * GBUF * sizeof(unsigned);        // 81920
    const int att_smem = ATT_SMEM_U32 * sizeof(unsigned);     // 71680

    cudaFuncSetAttribute(gemm_bf<true>, cudaFuncAttributeMaxDynamicSharedMemorySize, gemm_smem);
    cudaFuncSetAttribute(gemm_bf<false>, cudaFuncAttributeMaxDynamicSharedMemorySize, gemm_smem);
    cudaFuncSetAttribute(attn_kernel, cudaFuncAttributeMaxDynamicSharedMemorySize, att_smem);

    rope_table_kernel<<<(TT * 32 + 255) / 256, 256>>>();
    gemm_bf<true><<<dim3(1536 / 128, 8192 / 128), 512, gemm_smem>>>(x, wqkv, nullptr, nullptr);
    attn_kernel<<<dim3(TT / 128, NH, NB), 256, att_smem>>>();
    gemm_bf<false><<<dim3(512 / 128, 8192 / 128), 512, gemm_smem>>>(nullptr, outw, outb, out);
}

// round 11
// speedup vs baseline: 1.1841x; 1.1822x over previous
#include <cuda_runtime.h>
#include <math.h>
#include <cstdint>

#define NB 4
#define TT 2048
#define DM 512
#define NH 8
#define HD 64
#define SCALE 0.125f

// Scratch (no allocation allowed)
__device__ float g_q[NB * NH * TT * HD];
__device__ float g_k[NB * NH * TT * HD];
__device__ float g_v[NB * NH * TT * HD];
__device__ float g_ctx[NB * TT * DM];
__device__ float g_rc[TT * 32];
__device__ float g_rs[TT * 32];

// pack two floats -> f16x2 (e0 in low half), rne
__device__ __forceinline__ unsigned pack2f(float e0, float e1) {
    unsigned r;
    asm("cvt.rn.f16x2.f32 %0, %1, %2;" : "=r"(r) : "f"(e1), "f"(e0));
    return r;
}
// split (f0,f1) into hi f16x2 + lo (residual) f16x2
__device__ __forceinline__ void split2f(float f0, float f1, unsigned& hi, unsigned& lo) {
    unsigned h = pack2f(f0, f1);
    float h0, h1;
    asm("{.reg .b16 x, y; mov.b32 {x, y}, %2; cvt.f32.f16 %0, x; cvt.f32.f16 %1, y;}"
        : "=f"(h0), "=f"(h1) : "r"(h));
    lo = pack2f(f0 - h0, f1 - h1);
    hi = h;
}
__device__ __forceinline__ void mmaf(float* c, const unsigned* a, const unsigned* b) {
    asm volatile(
        "mma.sync.aligned.m16n8k16.row.col.f32.f16.f16.f32 "
        "{%0,%1,%2,%3},{%4,%5,%6,%7},{%8,%9},{%0,%1,%2,%3};"
        : "+f"(c[0]), "+f"(c[1]), "+f"(c[2]), "+f"(c[3])
        : "r"(a[0]), "r"(a[1]), "r"(a[2]), "r"(a[3]), "r"(b[0]), "r"(b[1]));
}
__device__ __forceinline__ uint32_t smem_u32(const void* p) {
    uint32_t a;
    asm("{ .reg .u64 t; cvta.to.shared.u64 t, %1; cvt.u32.u64 %0, t; }" : "=r"(a) : "l"(p));
    return a;
}
__device__ __forceinline__ void ldsm_x4(unsigned* r, uint32_t addr) {
    asm volatile("ldmatrix.sync.aligned.m8n8.x4.shared.b16 {%0,%1,%2,%3}, [%4];"
                 : "=r"(r[0]), "=r"(r[1]), "=r"(r[2]), "=r"(r[3]) : "r"(addr));
}

// ---------------------------------------------------------------------------
// FP16x2 GEMM: C = A(split hi/lo) . W(fp16)^T. Block 128m x 128e,
// 512 threads = 16 warps (4m x 4e), warp tile 32x32. K-chunk 32, dbl-buffered.
// smem u32 row stride 20 (80B). 2 MMAs per k16 step.
// ---------------------------------------------------------------------------
#define GAH 0
#define GAL 2560
#define GWH 5120
#define GBUF 7680

template <bool QKV>
__global__ void __launch_bounds__(512, 1) gemm_hx(const float* __restrict__ A,
                                                  const float* __restrict__ W,
                                                  const float* __restrict__ bias,
                                                  float* __restrict__ out) {
    extern __shared__ unsigned gsm[];
    const uint32_t sbase = smem_u32(gsm);

    const int e0 = blockIdx.x * 128;
    const int m0 = blockIdx.y * 128;
    const int tid = threadIdx.x;
    const int wid = tid >> 5, lane = tid & 31;
    const int wm = wid >> 2, wn = wid & 3;   // 4m x 4e
    const int g = lane >> 2, t4 = lane & 3;

    const float* Ap = QKV ? A : (const float*)g_ctx;

    float acc[2][4][4];
#pragma unroll
    for (int mt = 0; mt < 2; mt++)
#pragma unroll
        for (int nt = 0; nt < 4; nt++)
#pragma unroll
            for (int r = 0; r < 4; r++) acc[mt][nt][r] = 0.f;

    float4 av[2], wv[2];

#define LDG_CHUNK(KC)                                                              \
    do {                                                                           \
        _Pragma("unroll") for (int i = 0; i < 2; i++) {                            \
            int idx = tid + i * 512;                                               \
            int r = idx >> 3, k4 = idx & 7;                                        \
            av[i] = *(const float4*)(Ap + (size_t)(m0 + r) * 512 + (KC) + k4 * 4); \
        }                                                                          \
        _Pragma("unroll") for (int i = 0; i < 2; i++) {                            \
            int idx = tid + i * 512;                                               \
            int r = idx >> 3, k4 = idx & 7;                                        \
            wv[i] = *(const float4*)(W + (size_t)(e0 + r) * 512 + (KC) + k4 * 4);  \
        }                                                                          \
    } while (0)

#define STS_CHUNK(BUF)                                                    \
    do {                                                                  \
        unsigned* b_ = (BUF);                                             \
        _Pragma("unroll") for (int i = 0; i < 2; i++) {                   \
            int idx = tid + i * 512;                                      \
            int r = idx >> 3, k4 = idx & 7;                               \
            unsigned h0, l0, h1, l1;                                      \
            split2f(av[i].x, av[i].y, h0, l0);                            \
            split2f(av[i].z, av[i].w, h1, l1);                            \
            *(uint2*)&b_[GAH + r * 20 + k4 * 2] = make_uint2(h0, h1);     \
            *(uint2*)&b_[GAL + r * 20 + k4 * 2] = make_uint2(l0, l1);     \
        }                                                                 \
        _Pragma("unroll") for (int i = 0; i < 2; i++) {                   \
            int idx = tid + i * 512;                                      \
            int r = idx >> 3, k4 = idx & 7;                               \
            unsigned h0 = pack2f(wv[i].x, wv[i].y);                       \
            unsigned h1 = pack2f(wv[i].z, wv[i].w);                       \
            *(uint2*)&b_[GWH + r * 20 + k4 * 2] = make_uint2(h0, h1);     \
        }                                                                 \
    } while (0)

    LDG_CHUNK(0);
    STS_CHUNK(gsm);
    __syncthreads();

    const uint32_t aRowOff = (uint32_t)(lane & 15) * 80;
    const uint32_t aColOff = (uint32_t)(lane >> 4) * 16;
    const uint32_t bRowOff = (uint32_t)((lane & 7) + ((lane >> 4) << 3)) * 80;
    const uint32_t bColOff = (uint32_t)((lane >> 3) & 1) * 16;

    int cur = 0;
    for (int kc = 0; kc < 512; kc += 32) {
        if (kc + 32 < 512) LDG_CHUNK(kc + 32);
        const uint32_t bb = sbase + cur * (GBUF * 4);
#pragma unroll
        for (int ks = 0; ks < 2; ks++) {
            const uint32_t kOff = ks * 32;
            unsigned ah[2][4], al[2][4], bh[2][4];
#pragma unroll
            for (int mt = 0; mt < 2; mt++) {
                uint32_t base = bb + (wm * 32 + mt * 16) * 80 + aRowOff + kOff + aColOff;
                ldsm_x4(ah[mt], base + GAH * 4);
                ldsm_x4(al[mt], base + GAL * 4);
            }
#pragma unroll
            for (int ntp = 0; ntp < 2; ntp++) {
                uint32_t base = bb + (wn * 32 + ntp * 16) * 80 + bRowOff + kOff + bColOff;
                ldsm_x4(bh[ntp], base + GWH * 4);
            }
#pragma unroll
            for (int mt = 0; mt < 2; mt++)
#pragma unroll
                for (int nt = 0; nt < 4; nt++) {
                    const unsigned* BH = &bh[nt >> 1][(nt & 1) * 2];
                    mmaf(acc[mt][nt], ah[mt], BH);
                    mmaf(acc[mt][nt], al[mt], BH);
                }
        }
        if (kc + 32 < 512) STS_CHUNK(gsm + (cur ^ 1) * GBUF);
        __syncthreads();
        cur ^= 1;
    }

    if (QKV) {
#pragma unroll
        for (int mt = 0; mt < 2; mt++)
#pragma unroll
            for (int half = 0; half < 2; half++) {
                int m = m0 + wm * 32 + mt * 16 + g + half * 8;
                int nbt = m >> 11, tt = m & 2047;
#pragma unroll
                for (int nt = 0; nt < 4; nt++) {
                    int e = e0 + wn * 32 + nt * 8 + t4 * 2;
                    int sec = e >> 9;
                    int h = (e >> 6) & 7;
                    int d = e & 63;
                    float* buf = (sec == 0) ? g_q : (sec == 1) ? g_k : g_v;
                    *(float2*)(buf + (((size_t)(nbt * NH + h)) * TT + tt) * HD + d) =
                        make_float2(acc[mt][nt][half * 2], acc[mt][nt][half * 2 + 1]);
                }
            }
    } else {
#pragma unroll
        for (int mt = 0; mt < 2; mt++)
#pragma unroll
            for (int half = 0; half < 2; half++) {
                int m = m0 + wm * 32 + mt * 16 + g + half * 8;
#pragma unroll
                for (int nt = 0; nt < 4; nt++) {
                    int e = e0 + wn * 32 + nt * 8 + t4 * 2;
                    float2 bv = *(const float2*)(bias + e);
                    *(float2*)(out + (size_t)m * 512 + e) =
                        make_float2(acc[mt][nt][half * 2] + bv.x,
                                    acc[mt][nt][half * 2 + 1] + bv.y);
                }
            }
    }
}

// ---------------------------------------------------------------------------
// RoPE trig table
// ---------------------------------------------------------------------------
__global__ void __launch_bounds__(256) rope_table_kernel() {
    int idx = blockIdx.x * 256 + threadIdx.x;
    if (idx >= TT * 32) return;
    int t = idx >> 5, lane = idx & 31;
    double inv_freq = pow(10000.0, -((double)(2 * lane) / 64.0));
    float ang = (float)t * (float)inv_freq;
    g_rc[idx] = (float)cos((double)ang);
    g_rs[idx] = (float)sin((double)ang);
}

// ---------------------------------------------------------------------------
// Sliding-window attention, fp16x2 (Q and P split; K, V single fp16 plane),
// ldmatrix, fused RoPE, register-resident P.
// smem: Q planes [0,4608) + [4608,9216); then K plane [0,4608), V plane [4608..)
// ---------------------------------------------------------------------------
#define KPL 0
#define VPL 4608
#define ATT_SMEM_U32 9216

__global__ void __launch_bounds__(256) attn_kernel() {
    extern __shared__ unsigned sv[];
    const uint32_t sbase = smem_u32(sv);

    const int qt = blockIdx.x;
    const int h = blockIdx.y;
    const int n = blockIdx.z;
    const int q0 = qt * 128;
    const int tid = threadIdx.x;
    const int wid = tid >> 5, lane = tid & 31;
    const int g = lane >> 2, t4 = lane & 3;
    const int qr = wid * 16 + g;

    const size_t hb = ((size_t)(n * NH + h)) * TT * HD;
    const float* qg = g_q + hb;
    const float* kg = g_k + hb;
    const float* vg = g_v + hb;

    const uint32_t aRow36 = (uint32_t)(lane & 15) * 144;
    const uint32_t aColH = (uint32_t)(lane >> 4) * 16;
    const uint32_t bRow36 = (uint32_t)((lane & 7) + ((lane >> 4) << 3)) * 144;
    const uint32_t bRow68 = (uint32_t)((lane & 7) + ((lane >> 4) << 3)) * 272;
    const uint32_t bColH = (uint32_t)((lane >> 3) & 1) * 16;

    // stage Q with fused RoPE: hi plane at KPL, lo plane at VPL (both stride 36)
#pragma unroll
    for (int i = 0; i < 4; i++) {
        int idx = tid + i * 256;
        int r = idx >> 3, d4 = idx & 7;
        const float* row = qg + (size_t)(q0 + r) * HD;
        float4 a = *(const float4*)(row + d4 * 4);
        float4 b = *(const float4*)(row + d4 * 4 + 32);
        const float4 cv = *(const float4*)(g_rc + (size_t)(q0 + r) * 32 + d4 * 4);
        const float4 sn = *(const float4*)(g_rs + (size_t)(q0 + r) * 32 + d4 * 4);
        float4 lo = make_float4(a.x * cv.x - b.x * sn.x, a.y * cv.y - b.y * sn.y,
                                a.z * cv.z - b.z * sn.z, a.w * cv.w - b.w * sn.w);
        float4 hi = make_float4(b.x * cv.x + a.x * sn.x, b.y * cv.y + a.y * sn.y,
                                b.z * cv.z + a.z * sn.z, b.w * cv.w + a.w * sn.w);
        unsigned h0, l0, h1, l1;
        split2f(lo.x, lo.y, h0, l0);
        split2f(lo.z, lo.w, h1, l1);
        *(uint2*)&sv[KPL + r * 36 + d4 * 2] = make_uint2(h0, h1);
        *(uint2*)&sv[VPL + r * 36 + d4 * 2] = make_uint2(l0, l1);
        split2f(hi.x, hi.y, h0, l0);
        split2f(hi.z, hi.w, h1, l1);
        *(uint2*)&sv[KPL + r * 36 + (d4 + 8) * 2] = make_uint2(h0, h1);
        *(uint2*)&sv[VPL + r * 36 + (d4 + 8) * 2] = make_uint2(l0, l1);
    }
    __syncthreads();

    unsigned aqh[4][4], aql[4][4];
#pragma unroll
    for (int ks = 0; ks < 4; ks++) {
        uint32_t base = sbase + (wid * 16) * 144 + aRow36 + ks * 32 + aColH;
        ldsm_x4(aqh[ks], base + KPL * 4);
        ldsm_x4(aql[ks], base + VPL * 4);
    }
    __syncthreads();

    float m_i[2] = {-1e30f, -1e30f};
    float l_i[2] = {0.f, 0.f};
    float o[8][4];
#pragma unroll
    for (int nt = 0; nt < 8; nt++)
#pragma unroll
        for (int r = 0; r < 4; r++) o[nt][r] = 0.f;

    int c0 = qt - 1; if (c0 < 0) c0 = 0;
    int c1 = qt + 1; if (c1 > 15) c1 = 15;

    for (int c = c0; c <= c1; c++) {
        const int j0 = c * 128;

        const int rowlo = q0 + wid * 16;
        int ntLo = (rowlo - 127 - j0) >> 3;
        if (ntLo < 0) ntLo = 0;
        ntLo &= ~1;
        int ntHi = (rowlo + 15 + 128 - j0) >> 3;
        if (ntHi > 15) ntHi = 15;
        ntHi |= 1;
        const int kspLo = ntLo >> 1, kspHi = ntHi >> 1;

        // stage K with fused RoPE: single fp16 plane at KPL (stride 36)
#pragma unroll
        for (int i = 0; i < 4; i++) {
            int idx = tid + i * 256;
            int r = idx >> 3, d4 = idx & 7;
            const float* row = kg + (size_t)(j0 + r) * HD;
            float4 a = *(const float4*)(row + d4 * 4);
            float4 b = *(const float4*)(row + d4 * 4 + 32);
            const float4 cv = *(const float4*)(g_rc + (size_t)(j0 + r) * 32 + d4 * 4);
            const float4 sn = *(const float4*)(g_rs + (size_t)(j0 + r) * 32 + d4 * 4);
            float4 lo = make_float4(a.x * cv.x - b.x * sn.x, a.y * cv.y - b.y * sn.y,
                                    a.z * cv.z - b.z * sn.z, a.w * cv.w - b.w * sn.w);
            float4 hi = make_float4(b.x * cv.x + a.x * sn.x, b.y * cv.y + a.y * sn.y,
                                    b.z * cv.z + a.z * sn.z, b.w * cv.w + a.w * sn.w);
            *(uint2*)&sv[KPL + r * 36 + d4 * 2] =
                make_uint2(pack2f(lo.x, lo.y), pack2f(lo.z, lo.w));
            *(uint2*)&sv[KPL + r * 36 + (d4 + 8) * 2] =
                make_uint2(pack2f(hi.x, hi.y), pack2f(hi.z, hi.w));
        }
        // stage V transposed: single fp16 plane Vt[dim][keypair] at VPL (stride 68)
#pragma unroll
        for (int i = 0; i < 4; i++) {
            int idx = tid + i * 256;
            int rp = idx >> 4, d4 = idx & 15;
            float4 va = *(const float4*)(vg + (size_t)(j0 + 2 * rp) * HD + d4 * 4);
            float4 vb = *(const float4*)(vg + (size_t)(j0 + 2 * rp + 1) * HD + d4 * 4);
            sv[VPL + (d4 * 4 + 0) * 68 + rp] = pack2f(va.x, vb.x);
            sv[VPL + (d4 * 4 + 1) * 68 + rp] = pack2f(va.y, vb.y);
            sv[VPL + (d4 * 4 + 2) * 68 + rp] = pack2f(va.z, vb.z);
            sv[VPL + (d4 * 4 + 3) * 68 + rp] = pack2f(va.w, vb.w);
        }
        __syncthreads();

        // S = (Qh+Ql) . Kh^T (live n-tile pairs)
        float s[16][4];
#pragma unroll
        for (int nt = 0; nt < 16; nt++)
#pragma unroll
            for (int r = 0; r < 4; r++) s[nt][r] = 0.f;

#pragma unroll
        for (int ntp = 0; ntp < 8; ntp++) {
            if (ntp * 2 < ntLo || ntp * 2 > ntHi) continue;
#pragma unroll
            for (int ks = 0; ks < 4; ks++) {
                unsigned bh4[4];
                uint32_t base = sbase + (ntp * 16) * 144 + bRow36 + ks * 32 + bColH;
                ldsm_x4(bh4, base + KPL * 4);
                mmaf(s[ntp * 2], aqh[ks], bh4);
                mmaf(s[ntp * 2], aql[ks], bh4);
                mmaf(s[ntp * 2 + 1], aqh[ks], bh4 + 2);
                mmaf(s[ntp * 2 + 1], aql[ks], bh4 + 2);
            }
        }

        // mask + online softmax (P stays in s[] registers)
#pragma unroll
        for (int half = 0; half < 2; half++) {
            const int rowg = q0 + qr + half * 8;
            float mx = -1e30f;
#pragma unroll
            for (int nt = 0; nt < 16; nt++) {
                if (nt < ntLo || nt > ntHi) continue;
#pragma unroll
                for (int cc = 0; cc < 2; cc++) {
                    int colg = j0 + nt * 8 + t4 * 2 + cc;
                    bool valid = (colg >= rowg - 127) && (colg <= rowg + 128);
                    float v = valid ? s[nt][half * 2 + cc] * SCALE : -1e30f;
                    s[nt][half * 2 + cc] = v;
                    mx = fmaxf(mx, v);
                }
            }
            mx = fmaxf(mx, __shfl_xor_sync(0xffffffffu, mx, 1));
            mx = fmaxf(mx, __shfl_xor_sync(0xffffffffu, mx, 2));
            float mnew = fmaxf(m_i[half], mx);
            float alpha = __expf(m_i[half] - mnew);
            float sum = 0.f;
#pragma unroll
            for (int nt = 0; nt < 16; nt++) {
                if (nt < ntLo || nt > ntHi) continue;
#pragma unroll
                for (int cc = 0; cc < 2; cc++) {
                    float v = s[nt][half * 2 + cc];
                    float p = (v > -1e29f) ? __expf(v - mnew) : 0.f;
                    sum += p;
                    s[nt][half * 2 + cc] = p;
                }
            }
            sum += __shfl_xor_sync(0xffffffffu, sum, 1);
            sum += __shfl_xor_sync(0xffffffffu, sum, 2);
            l_i[half] = l_i[half] * alpha + sum;
            m_i[half] = mnew;
#pragma unroll
            for (int nt = 0; nt < 8; nt++) {
                o[nt][half * 2] *= alpha;
                o[nt][half * 2 + 1] *= alpha;
            }
        }

        // O += (Ph+Pl) . Vh (P repacked from score C-frags in registers)
#pragma unroll
        for (int ksp = 0; ksp < 8; ksp++) {
            if (ksp < kspLo || ksp > kspHi) continue;
            unsigned aph[4], apl[4];
            split2f(s[2 * ksp][0], s[2 * ksp][1], aph[0], apl[0]);
            split2f(s[2 * ksp][2], s[2 * ksp][3], aph[1], apl[1]);
            split2f(s[2 * ksp + 1][0], s[2 * ksp + 1][1], aph[2], apl[2]);
            split2f(s[2 * ksp + 1][2], s[2 * ksp + 1][3], aph[3], apl[3]);
#pragma unroll
            for (int ntp = 0; ntp < 4; ntp++) {
                unsigned bh4[4];
                uint32_t vbase = sbase + VPL * 4 + (ntp * 16) * 272 + bRow68 +
                                 ksp * 32 + bColH;
                ldsm_x4(bh4, vbase);
                mmaf(o[ntp * 2], aph, bh4);
                mmaf(o[ntp * 2], apl, bh4);
                mmaf(o[ntp * 2 + 1], aph, bh4 + 2);
                mmaf(o[ntp * 2 + 1], apl, bh4 + 2);
            }
        }
        __syncthreads();
    }

    // epilogue
#pragma unroll
    for (int half = 0; half < 2; half++) {
        const int rowg = q0 + qr + half * 8;
        const float invl = 1.f / l_i[half];
        const size_t ob = ((size_t)n * TT + rowg) * DM + h * HD;
#pragma unroll
        for (int nt = 0; nt < 8; nt++) {
            int d = nt * 8 + t4 * 2;
            *(float2*)(g_ctx + ob + d) =
                make_float2(o[nt][half * 2] * invl, o[nt][half * 2 + 1] * invl);
        }
    }
}

// ---------------------------------------------------------------------------
extern "C" void kernel_launch(void* const* d_in, const int* in_sizes, int n_in,
                              void* d_out, int out_size) {
    const float* x    = (const float*)d_in[0];   // [4,2048,512]
    const float* wqkv = (const float*)d_in[1];   // [1536,512]
    const float* outw = (const float*)d_in[2];   // [512,512]
    const float* outb = (const float*)d_in[3];   // [512]
    float* out = (float*)d_out;

    const int gemm_smem = 2 * GBUF * sizeof(unsigned);        // 61440
    const int att_smem = ATT_SMEM_U32 * sizeof(unsigned);     // 36864

    cudaFuncSetAttribute(gemm_hx<true>, cudaFuncAttributeMaxDynamicSharedMemorySize, gemm_smem);
    cudaFuncSetAttribute(gemm_hx<false>, cudaFuncAttributeMaxDynamicSharedMemorySize, gemm_smem);
    cudaFuncSetAttribute(attn_kernel, cudaFuncAttributeMaxDynamicSharedMemorySize, att_smem);

    rope_table_kernel<<<(TT * 32 + 255) / 256, 256>>>();
    gemm_hx<true><<<dim3(1536 / 128, 8192 / 128), 512, gemm_smem>>>(x, wqkv, nullptr, nullptr);
    attn_kernel<<<dim3(TT / 128, NH, NB), 256, att_smem>>>();
    gemm_hx<false><<<dim3(512 / 128, 8192 / 128), 512, gemm_smem>>>(nullptr, outw, outb, out);
}

// round 12
// speedup vs baseline: 1.2634x; 1.0669x over previous
#include <cuda_runtime.h>
#include <math.h>
#include <cstdint>

#define NB 4
#define TT 2048
#define DM 512
#define NH 8
#define HD 64
#define SCALE 0.125f

// Scratch (no allocation allowed)
__device__ float g_q[NB * NH * TT * HD];
__device__ float g_k[NB * NH * TT * HD];
__device__ float g_v[NB * NH * TT * HD];
__device__ float g_ctx[NB * TT * DM];
__device__ float g_rc[TT * 32];
__device__ float g_rs[TT * 32];

// pack two floats -> f16x2 (e0 in low half), rne
__device__ __forceinline__ unsigned pack2f(float e0, float e1) {
    unsigned r;
    asm("cvt.rn.f16x2.f32 %0, %1, %2;" : "=r"(r) : "f"(e1), "f"(e0));
    return r;
}
// split (f0,f1) into hi f16x2 + lo (residual) f16x2
__device__ __forceinline__ void split2f(float f0, float f1, unsigned& hi, unsigned& lo) {
    unsigned h = pack2f(f0, f1);
    float h0, h1;
    asm("{.reg .b16 x, y; mov.b32 {x, y}, %2; cvt.f32.f16 %0, x; cvt.f32.f16 %1, y;}"
        : "=f"(h0), "=f"(h1) : "r"(h));
    lo = pack2f(f0 - h0, f1 - h1);
    hi = h;
}
__device__ __forceinline__ void mmaf(float* c, const unsigned* a, const unsigned* b) {
    asm volatile(
        "mma.sync.aligned.m16n8k16.row.col.f32.f16.f16.f32 "
        "{%0,%1,%2,%3},{%4,%5,%6,%7},{%8,%9},{%0,%1,%2,%3};"
        : "+f"(c[0]), "+f"(c[1]), "+f"(c[2]), "+f"(c[3])
        : "r"(a[0]), "r"(a[1]), "r"(a[2]), "r"(a[3]), "r"(b[0]), "r"(b[1]));
}
__device__ __forceinline__ uint32_t smem_u32(const void* p) {
    uint32_t a;
    asm("{ .reg .u64 t; cvta.to.shared.u64 t, %1; cvt.u32.u64 %0, t; }" : "=r"(a) : "l"(p));
    return a;
}
__device__ __forceinline__ void ldsm_x4(unsigned* r, uint32_t addr) {
    asm volatile("ldmatrix.sync.aligned.m8n8.x4.shared.b16 {%0,%1,%2,%3}, [%4];"
                 : "=r"(r[0]), "=r"(r[1]), "=r"(r[2]), "=r"(r[3]) : "r"(addr));
}

// ---------------------------------------------------------------------------
// FP16x2 GEMM (R11 known-good): A split hi/lo, W single fp16.
// Block 128m x 128e, 512 threads = 16 warps (4m x 4e), warp tile 32x32.
// ---------------------------------------------------------------------------
#define GAH 0
#define GAL 2560
#define GWH 5120
#define GBUF 7680

template <bool QKV>
__global__ void __launch_bounds__(512, 1) gemm_hx(const float* __restrict__ A,
                                                  const float* __restrict__ W,
                                                  const float* __restrict__ bias,
                                                  float* __restrict__ out) {
    extern __shared__ unsigned gsm[];
    const uint32_t sbase = smem_u32(gsm);

    const int e0 = blockIdx.x * 128;
    const int m0 = blockIdx.y * 128;
    const int tid = threadIdx.x;
    const int wid = tid >> 5, lane = tid & 31;
    const int wm = wid >> 2, wn = wid & 3;   // 4m x 4e
    const int g = lane >> 2, t4 = lane & 3;

    const float* Ap = QKV ? A : (const float*)g_ctx;

    float acc[2][4][4];
#pragma unroll
    for (int mt = 0; mt < 2; mt++)
#pragma unroll
        for (int nt = 0; nt < 4; nt++)
#pragma unroll
            for (int r = 0; r < 4; r++) acc[mt][nt][r] = 0.f;

    float4 av[2], wv[2];

#define LDG_CHUNK(KC)                                                              \
    do {                                                                           \
        _Pragma("unroll") for (int i = 0; i < 2; i++) {                            \
            int idx = tid + i * 512;                                               \
            int r = idx >> 3, k4 = idx & 7;                                        \
            av[i] = *(const float4*)(Ap + (size_t)(m0 + r) * 512 + (KC) + k4 * 4); \
        }                                                                          \
        _Pragma("unroll") for (int i = 0; i < 2; i++) {                            \
            int idx = tid + i * 512;                                               \
            int r = idx >> 3, k4 = idx & 7;                                        \
            wv[i] = *(const float4*)(W + (size_t)(e0 + r) * 512 + (KC) + k4 * 4);  \
        }                                                                          \
    } while (0)

#define STS_CHUNK(BUF)                                                    \
    do {                                                                  \
        unsigned* b_ = (BUF);                                             \
        _Pragma("unroll") for (int i = 0; i < 2; i++) {                   \
            int idx = tid + i * 512;                                      \
            int r = idx >> 3, k4 = idx & 7;                               \
            unsigned h0, l0, h1, l1;                                      \
            split2f(av[i].x, av[i].y, h0, l0);                            \
            split2f(av[i].z, av[i].w, h1, l1);                            \
            *(uint2*)&b_[GAH + r * 20 + k4 * 2] = make_uint2(h0, h1);     \
            *(uint2*)&b_[GAL + r * 20 + k4 * 2] = make_uint2(l0, l1);     \
        }                                                                 \
        _Pragma("unroll") for (int i = 0; i < 2; i++) {                   \
            int idx = tid + i * 512;                                      \
            int r = idx >> 3, k4 = idx & 7;                               \
            unsigned h0 = pack2f(wv[i].x, wv[i].y);                       \
            unsigned h1 = pack2f(wv[i].z, wv[i].w);                       \
            *(uint2*)&b_[GWH + r * 20 + k4 * 2] = make_uint2(h0, h1);     \
        }                                                                 \
    } while (0)

    LDG_CHUNK(0);
    STS_CHUNK(gsm);
    __syncthreads();

    const uint32_t aRowOff = (uint32_t)(lane & 15) * 80;
    const uint32_t aColOff = (uint32_t)(lane >> 4) * 16;
    const uint32_t bRowOff = (uint32_t)((lane & 7) + ((lane >> 4) << 3)) * 80;
    const uint32_t bColOff = (uint32_t)((lane >> 3) & 1) * 16;

    int cur = 0;
    for (int kc = 0; kc < 512; kc += 32) {
        if (kc + 32 < 512) LDG_CHUNK(kc + 32);
        const uint32_t bb = sbase + cur * (GBUF * 4);
#pragma unroll
        for (int ks = 0; ks < 2; ks++) {
            const uint32_t kOff = ks * 32;
            unsigned ah[2][4], al[2][4], bh[2][4];
#pragma unroll
            for (int mt = 0; mt < 2; mt++) {
                uint32_t base = bb + (wm * 32 + mt * 16) * 80 + aRowOff + kOff + aColOff;
                ldsm_x4(ah[mt], base + GAH * 4);
                ldsm_x4(al[mt], base + GAL * 4);
            }
#pragma unroll
            for (int ntp = 0; ntp < 2; ntp++) {
                uint32_t base = bb + (wn * 32 + ntp * 16) * 80 + bRowOff + kOff + bColOff;
                ldsm_x4(bh[ntp], base + GWH * 4);
            }
#pragma unroll
            for (int mt = 0; mt < 2; mt++)
#pragma unroll
                for (int nt = 0; nt < 4; nt++) {
                    const unsigned* BH = &bh[nt >> 1][(nt & 1) * 2];
                    mmaf(acc[mt][nt], ah[mt], BH);
                    mmaf(acc[mt][nt], al[mt], BH);
                }
        }
        if (kc + 32 < 512) STS_CHUNK(gsm + (cur ^ 1) * GBUF);
        __syncthreads();
        cur ^= 1;
    }

    if (QKV) {
#pragma unroll
        for (int mt = 0; mt < 2; mt++)
#pragma unroll
            for (int half = 0; half < 2; half++) {
                int m = m0 + wm * 32 + mt * 16 + g + half * 8;
                int nbt = m >> 11, tt = m & 2047;
#pragma unroll
                for (int nt = 0; nt < 4; nt++) {
                    int e = e0 + wn * 32 + nt * 8 + t4 * 2;
                    int sec = e >> 9;
                    int h = (e >> 6) & 7;
                    int d = e & 63;
                    float* buf = (sec == 0) ? g_q : (sec == 1) ? g_k : g_v;
                    *(float2*)(buf + (((size_t)(nbt * NH + h)) * TT + tt) * HD + d) =
                        make_float2(acc[mt][nt][half * 2], acc[mt][nt][half * 2 + 1]);
                }
            }
    } else {
#pragma unroll
        for (int mt = 0; mt < 2; mt++)
#pragma unroll
            for (int half = 0; half < 2; half++) {
                int m = m0 + wm * 32 + mt * 16 + g + half * 8;
#pragma unroll
                for (int nt = 0; nt < 4; nt++) {
                    int e = e0 + wn * 32 + nt * 8 + t4 * 2;
                    float2 bv = *(const float2*)(bias + e);
                    *(float2*)(out + (size_t)m * 512 + e) =
                        make_float2(acc[mt][nt][half * 2] + bv.x,
                                    acc[mt][nt][half * 2 + 1] + bv.y);
                }
            }
    }
}

// ---------------------------------------------------------------------------
// RoPE trig table
// ---------------------------------------------------------------------------
__global__ void __launch_bounds__(256) rope_table_kernel() {
    int idx = blockIdx.x * 256 + threadIdx.x;
    if (idx >= TT * 32) return;
    int t = idx >> 5, lane = idx & 31;
    double inv_freq = pow(10000.0, -((double)(2 * lane) / 64.0));
    float ang = (float)t * (float)inv_freq;
    g_rc[idx] = (float)cos((double)ang);
    g_rs[idx] = (float)sin((double)ang);
}

// ---------------------------------------------------------------------------
// Sliding-window attention, pure fp16 operands (Q, K, V, P all single plane),
// ldmatrix, fused RoPE, register-resident P.
// ---------------------------------------------------------------------------
#define KPL 0
#define VPL 4608
#define ATT_SMEM_U32 9216

__global__ void __launch_bounds__(256) attn_kernel() {
    extern __shared__ unsigned sv[];
    const uint32_t sbase = smem_u32(sv);

    const int qt = blockIdx.x;
    const int h = blockIdx.y;
    const int n = blockIdx.z;
    const int q0 = qt * 128;
    const int tid = threadIdx.x;
    const int wid = tid >> 5, lane = tid & 31;
    const int g = lane >> 2, t4 = lane & 3;
    const int qr = wid * 16 + g;

    const size_t hb = ((size_t)(n * NH + h)) * TT * HD;
    const float* qg = g_q + hb;
    const float* kg = g_k + hb;
    const float* vg = g_v + hb;

    const uint32_t aRow36 = (uint32_t)(lane & 15) * 144;
    const uint32_t aColH = (uint32_t)(lane >> 4) * 16;
    const uint32_t bRow36 = (uint32_t)((lane & 7) + ((lane >> 4) << 3)) * 144;
    const uint32_t bRow68 = (uint32_t)((lane & 7) + ((lane >> 4) << 3)) * 272;
    const uint32_t bColH = (uint32_t)((lane >> 3) & 1) * 16;

    // stage Q with fused RoPE: single fp16 plane at KPL (stride 36)
#pragma unroll
    for (int i = 0; i < 4; i++) {
        int idx = tid + i * 256;
        int r = idx >> 3, d4 = idx & 7;
        const float* row = qg + (size_t)(q0 + r) * HD;
        float4 a = *(const float4*)(row + d4 * 4);
        float4 b = *(const float4*)(row + d4 * 4 + 32);
        const float4 cv = *(const float4*)(g_rc + (size_t)(q0 + r) * 32 + d4 * 4);
        const float4 sn = *(const float4*)(g_rs + (size_t)(q0 + r) * 32 + d4 * 4);
        float4 lo = make_float4(a.x * cv.x - b.x * sn.x, a.y * cv.y - b.y * sn.y,
                                a.z * cv.z - b.z * sn.z, a.w * cv.w - b.w * sn.w);
        float4 hi = make_float4(b.x * cv.x + a.x * sn.x, b.y * cv.y + a.y * sn.y,
                                b.z * cv.z + a.z * sn.z, b.w * cv.w + a.w * sn.w);
        *(uint2*)&sv[KPL + r * 36 + d4 * 2] =
            make_uint2(pack2f(lo.x, lo.y), pack2f(lo.z, lo.w));
        *(uint2*)&sv[KPL + r * 36 + (d4 + 8) * 2] =
            make_uint2(pack2f(hi.x, hi.y), pack2f(hi.z, hi.w));
    }
    __syncthreads();

    unsigned aqh[4][4];
#pragma unroll
    for (int ks = 0; ks < 4; ks++) {
        uint32_t base = sbase + (wid * 16) * 144 + aRow36 + ks * 32 + aColH;
        ldsm_x4(aqh[ks], base + KPL * 4);
    }
    __syncthreads();

    float m_i[2] = {-1e30f, -1e30f};
    float l_i[2] = {0.f, 0.f};
    float o[8][4];
#pragma unroll
    for (int nt = 0; nt < 8; nt++)
#pragma unroll
        for (int r = 0; r < 4; r++) o[nt][r] = 0.f;

    int c0 = qt - 1; if (c0 < 0) c0 = 0;
    int c1 = qt + 1; if (c1 > 15) c1 = 15;

    for (int c = c0; c <= c1; c++) {
        const int j0 = c * 128;

        const int rowlo = q0 + wid * 16;
        int ntLo = (rowlo - 127 - j0) >> 3;
        if (ntLo < 0) ntLo = 0;
        ntLo &= ~1;
        int ntHi = (rowlo + 15 + 128 - j0) >> 3;
        if (ntHi > 15) ntHi = 15;
        ntHi |= 1;
        const int kspLo = ntLo >> 1, kspHi = ntHi >> 1;

        // stage K with fused RoPE: single fp16 plane at KPL (stride 36)
#pragma unroll
        for (int i = 0; i < 4; i++) {
            int idx = tid + i * 256;
            int r = idx >> 3, d4 = idx & 7;
            const float* row = kg + (size_t)(j0 + r) * HD;
            float4 a = *(const float4*)(row + d4 * 4);
            float4 b = *(const float4*)(row + d4 * 4 + 32);
            const float4 cv = *(const float4*)(g_rc + (size_t)(j0 + r) * 32 + d4 * 4);
            const float4 sn = *(const float4*)(g_rs + (size_t)(j0 + r) * 32 + d4 * 4);
            float4 lo = make_float4(a.x * cv.x - b.x * sn.x, a.y * cv.y - b.y * sn.y,
                                    a.z * cv.z - b.z * sn.z, a.w * cv.w - b.w * sn.w);
            float4 hi = make_float4(b.x * cv.x + a.x * sn.x, b.y * cv.y + a.y * sn.y,
                                    b.z * cv.z + a.z * sn.z, b.w * cv.w + a.w * sn.w);
            *(uint2*)&sv[KPL + r * 36 + d4 * 2] =
                make_uint2(pack2f(lo.x, lo.y), pack2f(lo.z, lo.w));
            *(uint2*)&sv[KPL + r * 36 + (d4 + 8) * 2] =
                make_uint2(pack2f(hi.x, hi.y), pack2f(hi.z, hi.w));
        }
        // stage V transposed: single fp16 plane Vt[dim][keypair] at VPL (stride 68)
#pragma unroll
        for (int i = 0; i < 4; i++) {
            int idx = tid + i * 256;
            int rp = idx >> 4, d4 = idx & 15;
            float4 va = *(const float4*)(vg + (size_t)(j0 + 2 * rp) * HD + d4 * 4);
            float4 vb = *(const float4*)(vg + (size_t)(j0 + 2 * rp + 1) * HD + d4 * 4);
            sv[VPL + (d4 * 4 + 0) * 68 + rp] = pack2f(va.x, vb.x);
            sv[VPL + (d4 * 4 + 1) * 68 + rp] = pack2f(va.y, vb.y);
            sv[VPL + (d4 * 4 + 2) * 68 + rp] = pack2f(va.z, vb.z);
            sv[VPL + (d4 * 4 + 3) * 68 + rp] = pack2f(va.w, vb.w);
        }
        __syncthreads();

        // S = Q . K^T (live n-tile pairs, single fp16)
        float s[16][4];
#pragma unroll
        for (int nt = 0; nt < 16; nt++)
#pragma unroll
            for (int r = 0; r < 4; r++) s[nt][r] = 0.f;

#pragma unroll
        for (int ntp = 0; ntp < 8; ntp++) {
            if (ntp * 2 < ntLo || ntp * 2 > ntHi) continue;
#pragma unroll
            for (int ks = 0; ks < 4; ks++) {
                unsigned bh4[4];
                uint32_t base = sbase + (ntp * 16) * 144 + bRow36 + ks * 32 + bColH;
                ldsm_x4(bh4, base + KPL * 4);
                mmaf(s[ntp * 2], aqh[ks], bh4);
                mmaf(s[ntp * 2 + 1], aqh[ks], bh4 + 2);
            }
        }

        // mask + online softmax (P stays in s[] registers)
#pragma unroll
        for (int half = 0; half < 2; half++) {
            const int rowg = q0 + qr + half * 8;
            float mx = -1e30f;
#pragma unroll
            for (int nt = 0; nt < 16; nt++) {
                if (nt < ntLo || nt > ntHi) continue;
#pragma unroll
                for (int cc = 0; cc < 2; cc++) {
                    int colg = j0 + nt * 8 + t4 * 2 + cc;
                    bool valid = (colg >= rowg - 127) && (colg <= rowg + 128);
                    float v = valid ? s[nt][half * 2 + cc] * SCALE : -1e30f;
                    s[nt][half * 2 + cc] = v;
                    mx = fmaxf(mx, v);
                }
            }
            mx = fmaxf(mx, __shfl_xor_sync(0xffffffffu, mx, 1));
            mx = fmaxf(mx, __shfl_xor_sync(0xffffffffu, mx, 2));
            float mnew = fmaxf(m_i[half], mx);
            float alpha = __expf(m_i[half] - mnew);
            float sum = 0.f;
#pragma unroll
            for (int nt = 0; nt < 16; nt++) {
                if (nt < ntLo || nt > ntHi) continue;
#pragma unroll
                for (int cc = 0; cc < 2; cc++) {
                    float v = s[nt][half * 2 + cc];
                    float p = (v > -1e29f) ? __expf(v - mnew) : 0.f;
                    sum += p;
                    s[nt][half * 2 + cc] = p;
                }
            }
            sum += __shfl_xor_sync(0xffffffffu, sum, 1);
            sum += __shfl_xor_sync(0xffffffffu, sum, 2);
            l_i[half] = l_i[half] * alpha + sum;
            m_i[half] = mnew;
#pragma unroll
            for (int nt = 0; nt < 8; nt++) {
                o[nt][half * 2] *= alpha;
                o[nt][half * 2 + 1] *= alpha;
            }
        }

        // O += P . V (P repacked from score C-frags, single fp16)
#pragma unroll
        for (int ksp = 0; ksp < 8; ksp++) {
            if (ksp < kspLo || ksp > kspHi) continue;
            unsigned aph[4];
            aph[0] = pack2f(s[2 * ksp][0], s[2 * ksp][1]);
            aph[1] = pack2f(s[2 * ksp][2], s[2 * ksp][3]);
            aph[2] = pack2f(s[2 * ksp + 1][0], s[2 * ksp + 1][1]);
            aph[3] = pack2f(s[2 * ksp + 1][2], s[2 * ksp + 1][3]);
#pragma unroll
            for (int ntp = 0; ntp < 4; ntp++) {
                unsigned bh4[4];
                uint32_t vbase = sbase + VPL * 4 + (ntp * 16) * 272 + bRow68 +
                                 ksp * 32 + bColH;
                ldsm_x4(bh4, vbase);
                mmaf(o[ntp * 2], aph, bh4);
                mmaf(o[ntp * 2 + 1], aph, bh4 + 2);
            }
        }
        __syncthreads();
    }

    // epilogue
#pragma unroll
    for (int half = 0; half < 2; half++) {
        const int rowg = q0 + qr + half * 8;
        const float invl = 1.f / l_i[half];
        const size_t ob = ((size_t)n * TT + rowg) * DM + h * HD;
#pragma unroll
        for (int nt = 0; nt < 8; nt++) {
            int d = nt * 8 + t4 * 2;
            *(float2*)(g_ctx + ob + d) =
                make_float2(o[nt][half * 2] * invl, o[nt][half * 2 + 1] * invl);
        }
    }
}

// ---------------------------------------------------------------------------
extern "C" void kernel_launch(void* const* d_in, const int* in_sizes, int n_in,
                              void* d_out, int out_size) {
    const float* x    = (const float*)d_in[0];   // [4,2048,512]
    const float* wqkv = (const float*)d_in[1];   // [1536,512]
    const float* outw = (const float*)d_in[2];   // [512,512]
    const float* outb = (const float*)d_in[3];   // [512]
    float* out = (float*)d_out;

    const int gemm_smem = 2 * GBUF * sizeof(unsigned);        // 61440
    const int att_smem = ATT_SMEM_U32 * sizeof(unsigned);     // 36864

    cudaFuncSetAttribute(gemm_hx<true>, cudaFuncAttributeMaxDynamicSharedMemorySize, gemm_smem);
    cudaFuncSetAttribute(gemm_hx<false>, cudaFuncAttributeMaxDynamicSharedMemorySize, gemm_smem);
    cudaFuncSetAttribute(attn_kernel, cudaFuncAttributeMaxDynamicSharedMemorySize, att_smem);

    rope_table_kernel<<<(TT * 32 + 255) / 256, 256>>>();
    gemm_hx<true><<<dim3(1536 / 128, 8192 / 128), 512, gemm_smem>>>(x, wqkv, nullptr, nullptr);
    attn_kernel<<<dim3(TT / 128, NH, NB), 256, att_smem>>>();
    gemm_hx<false><<<dim3(512 / 128, 8192 / 128), 512, gemm_smem>>>(nullptr, outw, outb, out);
}

// round 13
// speedup vs baseline: 1.3965x; 1.1054x over previous
#include <cuda_runtime.h>
#include <cuda_fp16.h>
#include <math.h>
#include <cstdint>

#define NB 4
#define TT 2048
#define DM 512
#define NH 8
#define HD 64
#define SCALE 0.125f

// Scratch (no allocation allowed)
__device__ __half g_qh[NB * NH * TT * HD];
__device__ __half g_kh[NB * NH * TT * HD];
__device__ __half g_vh[NB * NH * TT * HD];
__device__ float g_ctx[NB * TT * DM];
__device__ float g_rc[TT * 32];
__device__ float g_rs[TT * 32];

// pack two floats -> f16x2 (e0 in low half), rne
__device__ __forceinline__ unsigned pack2f(float e0, float e1) {
    unsigned r;
    asm("cvt.rn.f16x2.f32 %0, %1, %2;" : "=r"(r) : "f"(e1), "f"(e0));
    return r;
}
// split (f0,f1) into hi f16x2 + lo (residual) f16x2
__device__ __forceinline__ void split2f(float f0, float f1, unsigned& hi, unsigned& lo) {
    unsigned h = pack2f(f0, f1);
    float h0, h1;
    asm("{.reg .b16 x, y; mov.b32 {x, y}, %2; cvt.f32.f16 %0, x; cvt.f32.f16 %1, y;}"
        : "=f"(h0), "=f"(h1) : "r"(h));
    lo = pack2f(f0 - h0, f1 - h1);
    hi = h;
}
__device__ __forceinline__ void mmaf(float* c, const unsigned* a, const unsigned* b) {
    asm volatile(
        "mma.sync.aligned.m16n8k16.row.col.f32.f16.f16.f32 "
        "{%0,%1,%2,%3},{%4,%5,%6,%7},{%8,%9},{%0,%1,%2,%3};"
        : "+f"(c[0]), "+f"(c[1]), "+f"(c[2]), "+f"(c[3])
        : "r"(a[0]), "r"(a[1]), "r"(a[2]), "r"(a[3]), "r"(b[0]), "r"(b[1]));
}
__device__ __forceinline__ uint32_t smem_u32(const void* p) {
    uint32_t a;
    asm("{ .reg .u64 t; cvta.to.shared.u64 t, %1; cvt.u32.u64 %0, t; }" : "=r"(a) : "l"(p));
    return a;
}
__device__ __forceinline__ void ldsm_x4(unsigned* r, uint32_t addr) {
    asm volatile("ldmatrix.sync.aligned.m8n8.x4.shared.b16 {%0,%1,%2,%3}, [%4];"
                 : "=r"(r[0]), "=r"(r[1]), "=r"(r[2]), "=r"(r[3]) : "r"(addr));
}
// load 4 consecutive halves -> float4
__device__ __forceinline__ float4 ld4h(const __half* p) {
    uint2 u = *(const uint2*)p;
    float2 f01 = __half22float2(*reinterpret_cast<__half2*>(&u.x));
    float2 f23 = __half22float2(*reinterpret_cast<__half2*>(&u.y));
    return make_float4(f01.x, f01.y, f23.x, f23.y);
}

// ---------------------------------------------------------------------------
// FP16 GEMM. QKV=true: A=x single fp16 plane, epilogue -> fp16 q/k/v.
//            QKV=false: A=ctx split hi/lo, epilogue -> fp32 out + bias.
// Block 128m x 128e, 512 threads = 16 warps (4m x 4e), warp tile 32x32.
// ---------------------------------------------------------------------------
#define GAH 0
#define GAL 2560
#define GWH 5120
#define GBUF 7680

template <bool QKV>
__global__ void __launch_bounds__(512, 1) gemm_hx(const float* __restrict__ A,
                                                  const float* __restrict__ W,
                                                  const float* __restrict__ bias,
                                                  float* __restrict__ out) {
    extern __shared__ unsigned gsm[];
    const uint32_t sbase = smem_u32(gsm);

    const int e0 = blockIdx.x * 128;
    const int m0 = blockIdx.y * 128;
    const int tid = threadIdx.x;
    const int wid = tid >> 5, lane = tid & 31;
    const int wm = wid >> 2, wn = wid & 3;   // 4m x 4e
    const int g = lane >> 2, t4 = lane & 3;

    const float* Ap = QKV ? A : (const float*)g_ctx;

    float acc[2][4][4];
#pragma unroll
    for (int mt = 0; mt < 2; mt++)
#pragma unroll
        for (int nt = 0; nt < 4; nt++)
#pragma unroll
            for (int r = 0; r < 4; r++) acc[mt][nt][r] = 0.f;

    float4 av[2], wv[2];

#define LDG_CHUNK(KC)                                                              \
    do {                                                                           \
        _Pragma("unroll") for (int i = 0; i < 2; i++) {                            \
            int idx = tid + i * 512;                                               \
            int r = idx >> 3, k4 = idx & 7;                                        \
            av[i] = *(const float4*)(Ap + (size_t)(m0 + r) * 512 + (KC) + k4 * 4); \
        }                                                                          \
        _Pragma("unroll") for (int i = 0; i < 2; i++) {                            \
            int idx = tid + i * 512;                                               \
            int r = idx >> 3, k4 = idx & 7;                                        \
            wv[i] = *(const float4*)(W + (size_t)(e0 + r) * 512 + (KC) + k4 * 4);  \
        }                                                                          \
    } while (0)

#define STS_CHUNK(BUF)                                                    \
    do {                                                                  \
        unsigned* b_ = (BUF);                                             \
        _Pragma("unroll") for (int i = 0; i < 2; i++) {                   \
            int idx = tid + i * 512;                                      \
            int r = idx >> 3, k4 = idx & 7;                               \
            if (QKV) {                                                    \
                unsigned h0 = pack2f(av[i].x, av[i].y);                   \
                unsigned h1 = pack2f(av[i].z, av[i].w);                   \
                *(uint2*)&b_[GAH + r * 20 + k4 * 2] = make_uint2(h0, h1); \
            } else {                                                      \
                unsigned h0, l0, h1, l1;                                  \
                split2f(av[i].x, av[i].y, h0, l0);                        \
                split2f(av[i].z, av[i].w, h1, l1);                        \
                *(uint2*)&b_[GAH + r * 20 + k4 * 2] = make_uint2(h0, h1); \
                *(uint2*)&b_[GAL + r * 20 + k4 * 2] = make_uint2(l0, l1); \
            }                                                             \
        }                                                                 \
        _Pragma("unroll") for (int i = 0; i < 2; i++) {                   \
            int idx = tid + i * 512;                                      \
            int r = idx >> 3, k4 = idx & 7;                               \
            unsigned h0 = pack2f(wv[i].x, wv[i].y);                       \
            unsigned h1 = pack2f(wv[i].z, wv[i].w);                       \
            *(uint2*)&b_[GWH + r * 20 + k4 * 2] = make_uint2(h0, h1);     \
        }                                                                 \
    } while (0)

    LDG_CHUNK(0);
    STS_CHUNK(gsm);
    __syncthreads();

    const uint32_t aRowOff = (uint32_t)(lane & 15) * 80;
    const uint32_t aColOff = (uint32_t)(lane >> 4) * 16;
    const uint32_t bRowOff = (uint32_t)((lane & 7) + ((lane >> 4) << 3)) * 80;
    const uint32_t bColOff = (uint32_t)((lane >> 3) & 1) * 16;

    int cur = 0;
    for (int kc = 0; kc < 512; kc += 32) {
        if (kc + 32 < 512) LDG_CHUNK(kc + 32);
        const uint32_t bb = sbase + cur * (GBUF * 4);
#pragma unroll
        for (int ks = 0; ks < 2; ks++) {
            const uint32_t kOff = ks * 32;
            unsigned ah[2][4], al[2][4], bh[2][4];
#pragma unroll
            for (int mt = 0; mt < 2; mt++) {
                uint32_t base = bb + (wm * 32 + mt * 16) * 80 + aRowOff + kOff + aColOff;
                ldsm_x4(ah[mt], base + GAH * 4);
                if (!QKV) ldsm_x4(al[mt], base + GAL * 4);
            }
#pragma unroll
            for (int ntp = 0; ntp < 2; ntp++) {
                uint32_t base = bb + (wn * 32 + ntp * 16) * 80 + bRowOff + kOff + bColOff;
                ldsm_x4(bh[ntp], base + GWH * 4);
            }
#pragma unroll
            for (int mt = 0; mt < 2; mt++)
#pragma unroll
                for (int nt = 0; nt < 4; nt++) {
                    const unsigned* BH = &bh[nt >> 1][(nt & 1) * 2];
                    mmaf(acc[mt][nt], ah[mt], BH);
                    if (!QKV) mmaf(acc[mt][nt], al[mt], BH);
                }
        }
        if (kc + 32 < 512) STS_CHUNK(gsm + (cur ^ 1) * GBUF);
        __syncthreads();
        cur ^= 1;
    }

    if (QKV) {
#pragma unroll
        for (int mt = 0; mt < 2; mt++)
#pragma unroll
            for (int half = 0; half < 2; half++) {
                int m = m0 + wm * 32 + mt * 16 + g + half * 8;
                int nbt = m >> 11, tt = m & 2047;
#pragma unroll
                for (int nt = 0; nt < 4; nt++) {
                    int e = e0 + wn * 32 + nt * 8 + t4 * 2;
                    int sec = e >> 9;
                    int h = (e >> 6) & 7;
                    int d = e & 63;
                    __half* buf = (sec == 0) ? g_qh : (sec == 1) ? g_kh : g_vh;
                    *(unsigned*)(buf + (((size_t)(nbt * NH + h)) * TT + tt) * HD + d) =
                        pack2f(acc[mt][nt][half * 2], acc[mt][nt][half * 2 + 1]);
                }
            }
    } else {
#pragma unroll
        for (int mt = 0; mt < 2; mt++)
#pragma unroll
            for (int half = 0; half < 2; half++) {
                int m = m0 + wm * 32 + mt * 16 + g + half * 8;
#pragma unroll
                for (int nt = 0; nt < 4; nt++) {
                    int e = e0 + wn * 32 + nt * 8 + t4 * 2;
                    float2 bv = *(const float2*)(bias + e);
                    *(float2*)(out + (size_t)m * 512 + e) =
                        make_float2(acc[mt][nt][half * 2] + bv.x,
                                    acc[mt][nt][half * 2 + 1] + bv.y);
                }
            }
    }
}

// ---------------------------------------------------------------------------
// RoPE trig table
// ---------------------------------------------------------------------------
__global__ void __launch_bounds__(256) rope_table_kernel() {
    int idx = blockIdx.x * 256 + threadIdx.x;
    if (idx >= TT * 32) return;
    int t = idx >> 5, lane = idx & 31;
    double inv_freq = pow(10000.0, -((double)(2 * lane) / 64.0));
    float ang = (float)t * (float)inv_freq;
    g_rc[idx] = (float)cos((double)ang);
    g_rs[idx] = (float)sin((double)ang);
}

// ---------------------------------------------------------------------------
// Sliding-window attention, pure fp16 operands, fp16 q/k/v global buffers,
// ldmatrix, fused RoPE, register-resident P.
// ---------------------------------------------------------------------------
#define KPL 0
#define VPL 4608
#define ATT_SMEM_U32 9216

__global__ void __launch_bounds__(256) attn_kernel() {
    extern __shared__ unsigned sv[];
    const uint32_t sbase = smem_u32(sv);

    const int qt = blockIdx.x;
    const int h = blockIdx.y;
    const int n = blockIdx.z;
    const int q0 = qt * 128;
    const int tid = threadIdx.x;
    const int wid = tid >> 5, lane = tid & 31;
    const int g = lane >> 2, t4 = lane & 3;
    const int qr = wid * 16 + g;

    const size_t hb = ((size_t)(n * NH + h)) * TT * HD;
    const __half* qg = g_qh + hb;
    const __half* kg = g_kh + hb;
    const __half* vg = g_vh + hb;

    const uint32_t aRow36 = (uint32_t)(lane & 15) * 144;
    const uint32_t aColH = (uint32_t)(lane >> 4) * 16;
    const uint32_t bRow36 = (uint32_t)((lane & 7) + ((lane >> 4) << 3)) * 144;
    const uint32_t bRow68 = (uint32_t)((lane & 7) + ((lane >> 4) << 3)) * 272;
    const uint32_t bColH = (uint32_t)((lane >> 3) & 1) * 16;

    // stage Q with fused RoPE: fp16 plane at KPL (stride 36)
#pragma unroll
    for (int i = 0; i < 4; i++) {
        int idx = tid + i * 256;
        int r = idx >> 3, d4 = idx & 7;
        const __half* row = qg + (size_t)(q0 + r) * HD;
        float4 a = ld4h(row + d4 * 4);
        float4 b = ld4h(row + d4 * 4 + 32);
        const float4 cv = *(const float4*)(g_rc + (size_t)(q0 + r) * 32 + d4 * 4);
        const float4 sn = *(const float4*)(g_rs + (size_t)(q0 + r) * 32 + d4 * 4);
        float4 lo = make_float4(a.x * cv.x - b.x * sn.x, a.y * cv.y - b.y * sn.y,
                                a.z * cv.z - b.z * sn.z, a.w * cv.w - b.w * sn.w);
        float4 hi = make_float4(b.x * cv.x + a.x * sn.x, b.y * cv.y + a.y * sn.y,
                                b.z * cv.z + a.z * sn.z, b.w * cv.w + a.w * sn.w);
        *(uint2*)&sv[KPL + r * 36 + d4 * 2] =
            make_uint2(pack2f(lo.x, lo.y), pack2f(lo.z, lo.w));
        *(uint2*)&sv[KPL + r * 36 + (d4 + 8) * 2] =
            make_uint2(pack2f(hi.x, hi.y), pack2f(hi.z, hi.w));
    }
    __syncthreads();

    unsigned aqh[4][4];
#pragma unroll
    for (int ks = 0; ks < 4; ks++) {
        uint32_t base = sbase + (wid * 16) * 144 + aRow36 + ks * 32 + aColH;
        ldsm_x4(aqh[ks], base + KPL * 4);
    }
    __syncthreads();

    float m_i[2] = {-1e30f, -1e30f};
    float l_i[2] = {0.f, 0.f};
    float o[8][4];
#pragma unroll
    for (int nt = 0; nt < 8; nt++)
#pragma unroll
        for (int r = 0; r < 4; r++) o[nt][r] = 0.f;

    int c0 = qt - 1; if (c0 < 0) c0 = 0;
    int c1 = qt + 1; if (c1 > 15) c1 = 15;

    for (int c = c0; c <= c1; c++) {
        const int j0 = c * 128;

        const int rowlo = q0 + wid * 16;
        int ntLo = (rowlo - 127 - j0) >> 3;
        if (ntLo < 0) ntLo = 0;
        ntLo &= ~1;
        int ntHi = (rowlo + 15 + 128 - j0) >> 3;
        if (ntHi > 15) ntHi = 15;
        ntHi |= 1;
        const int kspLo = ntLo >> 1, kspHi = ntHi >> 1;

        // stage K with fused RoPE (fp16 source)
#pragma unroll
        for (int i = 0; i < 4; i++) {
            int idx = tid + i * 256;
            int r = idx >> 3, d4 = idx & 7;
            const __half* row = kg + (size_t)(j0 + r) * HD;
            float4 a = ld4h(row + d4 * 4);
            float4 b = ld4h(row + d4 * 4 + 32);
            const float4 cv = *(const float4*)(g_rc + (size_t)(j0 + r) * 32 + d4 * 4);
            const float4 sn = *(const float4*)(g_rs + (size_t)(j0 + r) * 32 + d4 * 4);
            float4 lo = make_float4(a.x * cv.x - b.x * sn.x, a.y * cv.y - b.y * sn.y,
                                    a.z * cv.z - b.z * sn.z, a.w * cv.w - b.w * sn.w);
            float4 hi = make_float4(b.x * cv.x + a.x * sn.x, b.y * cv.y + a.y * sn.y,
                                    b.z * cv.z + a.z * sn.z, b.w * cv.w + a.w * sn.w);
            *(uint2*)&sv[KPL + r * 36 + d4 * 2] =
                make_uint2(pack2f(lo.x, lo.y), pack2f(lo.z, lo.w));
            *(uint2*)&sv[KPL + r * 36 + (d4 + 8) * 2] =
                make_uint2(pack2f(hi.x, hi.y), pack2f(hi.z, hi.w));
        }
        // stage V transposed (fp16 source, zero-convert half2 shuffles)
#pragma unroll
        for (int i = 0; i < 4; i++) {
            int idx = tid + i * 256;
            int rp = idx >> 4, d4 = idx & 15;
            uint2 ua = *(const uint2*)(vg + (size_t)(j0 + 2 * rp) * HD + d4 * 4);
            uint2 ub = *(const uint2*)(vg + (size_t)(j0 + 2 * rp + 1) * HD + d4 * 4);
            __half2 a01 = *reinterpret_cast<__half2*>(&ua.x);
            __half2 a23 = *reinterpret_cast<__half2*>(&ua.y);
            __half2 b01 = *reinterpret_cast<__half2*>(&ub.x);
            __half2 b23 = *reinterpret_cast<__half2*>(&ub.y);
            __half2 p0 = __lows2half2(a01, b01);
            __half2 p1 = __highs2half2(a01, b01);
            __half2 p2 = __lows2half2(a23, b23);
            __half2 p3 = __highs2half2(a23, b23);
            sv[VPL + (d4 * 4 + 0) * 68 + rp] = *reinterpret_cast<unsigned*>(&p0);
            sv[VPL + (d4 * 4 + 1) * 68 + rp] = *reinterpret_cast<unsigned*>(&p1);
            sv[VPL + (d4 * 4 + 2) * 68 + rp] = *reinterpret_cast<unsigned*>(&p2);
            sv[VPL + (d4 * 4 + 3) * 68 + rp] = *reinterpret_cast<unsigned*>(&p3);
        }
        __syncthreads();

        // S = Q . K^T (live n-tile pairs)
        float s[16][4];
#pragma unroll
        for (int nt = 0; nt < 16; nt++)
#pragma unroll
            for (int r = 0; r < 4; r++) s[nt][r] = 0.f;

#pragma unroll
        for (int ntp = 0; ntp < 8; ntp++) {
            if (ntp * 2 < ntLo || ntp * 2 > ntHi) continue;
#pragma unroll
            for (int ks = 0; ks < 4; ks++) {
                unsigned bh4[4];
                uint32_t base = sbase + (ntp * 16) * 144 + bRow36 + ks * 32 + bColH;
                ldsm_x4(bh4, base + KPL * 4);
                mmaf(s[ntp * 2], aqh[ks], bh4);
                mmaf(s[ntp * 2 + 1], aqh[ks], bh4 + 2);
            }
        }

        // mask + online softmax
#pragma unroll
        for (int half = 0; half < 2; half++) {
            const int rowg = q0 + qr + half * 8;
            float mx = -1e30f;
#pragma unroll
            for (int nt = 0; nt < 16; nt++) {
                if (nt < ntLo || nt > ntHi) continue;
#pragma unroll
                for (int cc = 0; cc < 2; cc++) {
                    int colg = j0 + nt * 8 + t4 * 2 + cc;
                    bool valid = (colg >= rowg - 127) && (colg <= rowg + 128);
                    float v = valid ? s[nt][half * 2 + cc] * SCALE : -1e30f;
                    s[nt][half * 2 + cc] = v;
                    mx = fmaxf(mx, v);
                }
            }
            mx = fmaxf(mx, __shfl_xor_sync(0xffffffffu, mx, 1));
            mx = fmaxf(mx, __shfl_xor_sync(0xffffffffu, mx, 2));
            float mnew = fmaxf(m_i[half], mx);
            float alpha = __expf(m_i[half] - mnew);
            float sum = 0.f;
#pragma unroll
            for (int nt = 0; nt < 16; nt++) {
                if (nt < ntLo || nt > ntHi) continue;
#pragma unroll
                for (int cc = 0; cc < 2; cc++) {
                    float v = s[nt][half * 2 + cc];
                    float p = (v > -1e29f) ? __expf(v - mnew) : 0.f;
                    sum += p;
                    s[nt][half * 2 + cc] = p;
                }
            }
            sum += __shfl_xor_sync(0xffffffffu, sum, 1);
            sum += __shfl_xor_sync(0xffffffffu, sum, 2);
            l_i[half] = l_i[half] * alpha + sum;
            m_i[half] = mnew;
#pragma unroll
            for (int nt = 0; nt < 8; nt++) {
                o[nt][half * 2] *= alpha;
                o[nt][half * 2 + 1] *= alpha;
            }
        }

        // O += P . V
#pragma unroll
        for (int ksp = 0; ksp < 8; ksp++) {
            if (ksp < kspLo || ksp > kspHi) continue;
            unsigned aph[4];
            aph[0] = pack2f(s[2 * ksp][0], s[2 * ksp][1]);
            aph[1] = pack2f(s[2 * ksp][2], s[2 * ksp][3]);
            aph[2] = pack2f(s[2 * ksp + 1][0], s[2 * ksp + 1][1]);
            aph[3] = pack2f(s[2 * ksp + 1][2], s[2 * ksp + 1][3]);
#pragma unroll
            for (int ntp = 0; ntp < 4; ntp++) {
                unsigned bh4[4];
                uint32_t vbase = sbase + VPL * 4 + (ntp * 16) * 272 + bRow68 +
                                 ksp * 32 + bColH;
                ldsm_x4(bh4, vbase);
                mmaf(o[ntp * 2], aph, bh4);
                mmaf(o[ntp * 2 + 1], aph, bh4 + 2);
            }
        }
        __syncthreads();
    }

    // epilogue
#pragma unroll
    for (int half = 0; half < 2; half++) {
        const int rowg = q0 + qr + half * 8;
        const float invl = 1.f / l_i[half];
        const size_t ob = ((size_t)n * TT + rowg) * DM + h * HD;
#pragma unroll
        for (int nt = 0; nt < 8; nt++) {
            int d = nt * 8 + t4 * 2;
            *(float2*)(g_ctx + ob + d) =
                make_float2(o[nt][half * 2] * invl, o[nt][half * 2 + 1] * invl);
        }
    }
}

// ---------------------------------------------------------------------------
extern "C" void kernel_launch(void* const* d_in, const int* in_sizes, int n_in,
                              void* d_out, int out_size) {
    const float* x    = (const float*)d_in[0];   // [4,2048,512]
    const float* wqkv = (const float*)d_in[1];   // [1536,512]
    const float* outw = (const float*)d_in[2];   // [512,512]
    const float* outb = (const float*)d_in[3];   // [512]
    float* out = (float*)d_out;

    const int gemm_smem = 2 * GBUF * sizeof(unsigned);        // 61440
    const int att_smem = ATT_SMEM_U32 * sizeof(unsigned);     // 36864

    cudaFuncSetAttribute(gemm_hx<true>, cudaFuncAttributeMaxDynamicSharedMemorySize, gemm_smem);
    cudaFuncSetAttribute(gemm_hx<false>, cudaFuncAttributeMaxDynamicSharedMemorySize, gemm_smem);
    cudaFuncSetAttribute(attn_kernel, cudaFuncAttributeMaxDynamicSharedMemorySize, att_smem);

    rope_table_kernel<<<(TT * 32 + 255) / 256, 256>>>();
    gemm_hx<true><<<dim3(1536 / 128, 8192 / 128), 512, gemm_smem>>>(x, wqkv, nullptr, nullptr);
    attn_kernel<<<dim3(TT / 128, NH, NB), 256, att_smem>>>();
    gemm_hx<false><<<dim3(512 / 128, 8192 / 128), 512, gemm_smem>>>(nullptr, outw, outb, out);
}

// round 14
// speedup vs baseline: 1.4661x; 1.0499x over previous
#include <cuda_runtime.h>
#include <cuda_fp16.h>
#include <math.h>
#include <cstdint>

#define NB 4
#define TT 2048
#define DM 512
#define NH 8
#define HD 64
#define SCALE 0.125f

// Scratch (no allocation allowed)
__device__ __half g_qh[NB * NH * TT * HD];
__device__ __half g_kh[NB * NH * TT * HD];
__device__ __half g_vh[NB * NH * TT * HD];
__device__ float g_ctx[NB * TT * DM];
__device__ float g_rc[TT * 32];
__device__ float g_rs[TT * 32];

// pack two floats -> f16x2 (e0 in low half), rne
__device__ __forceinline__ unsigned pack2f(float e0, float e1) {
    unsigned r;
    asm("cvt.rn.f16x2.f32 %0, %1, %2;" : "=r"(r) : "f"(e1), "f"(e0));
    return r;
}
// split (f0,f1) into hi f16x2 + lo (residual) f16x2
__device__ __forceinline__ void split2f(float f0, float f1, unsigned& hi, unsigned& lo) {
    unsigned h = pack2f(f0, f1);
    float h0, h1;
    asm("{.reg .b16 x, y; mov.b32 {x, y}, %2; cvt.f32.f16 %0, x; cvt.f32.f16 %1, y;}"
        : "=f"(h0), "=f"(h1) : "r"(h));
    lo = pack2f(f0 - h0, f1 - h1);
    hi = h;
}
__device__ __forceinline__ void mmaf(float* c, const unsigned* a, const unsigned* b) {
    asm volatile(
        "mma.sync.aligned.m16n8k16.row.col.f32.f16.f16.f32 "
        "{%0,%1,%2,%3},{%4,%5,%6,%7},{%8,%9},{%0,%1,%2,%3};"
        : "+f"(c[0]), "+f"(c[1]), "+f"(c[2]), "+f"(c[3])
        : "r"(a[0]), "r"(a[1]), "r"(a[2]), "r"(a[3]), "r"(b[0]), "r"(b[1]));
}
__device__ __forceinline__ uint32_t smem_u32(const void* p) {
    uint32_t a;
    asm("{ .reg .u64 t; cvta.to.shared.u64 t, %1; cvt.u32.u64 %0, t; }" : "=r"(a) : "l"(p));
    return a;
}
__device__ __forceinline__ void ldsm_x4(unsigned* r, uint32_t addr) {
    asm volatile("ldmatrix.sync.aligned.m8n8.x4.shared.b16 {%0,%1,%2,%3}, [%4];"
                 : "=r"(r[0]), "=r"(r[1]), "=r"(r[2]), "=r"(r[3]) : "r"(addr));
}
// load 4 consecutive halves -> float4
__device__ __forceinline__ float4 ld4h(const __half* p) {
    uint2 u = *(const uint2*)p;
    float2 f01 = __half22float2(*reinterpret_cast<__half2*>(&u.x));
    float2 f23 = __half22float2(*reinterpret_cast<__half2*>(&u.y));
    return make_float4(f01.x, f01.y, f23.x, f23.y);
}

// ---------------------------------------------------------------------------
// FP16 GEMM, K-chunk 64 (4 k16 steps per buffer, 8 barriers total).
// QKV=true: A=x single fp16, epilogue -> fp16 q/k/v.
// QKV=false: A=ctx split hi/lo, epilogue -> fp32 out + bias.
// Block 128m x 128e, 512 threads = 16 warps (4m x 4e), warp tile 32x32.
// smem rows: 64 halves = 32 u32 + 4 pad = stride 36 u32 (144B).
// ---------------------------------------------------------------------------
#define GAH 0
#define GAL 4608
#define GWH 9216
#define GBUF 13824

template <bool QKV>
__global__ void __launch_bounds__(512, 1) gemm_hx(const float* __restrict__ A,
                                                  const float* __restrict__ W,
                                                  const float* __restrict__ bias,
                                                  float* __restrict__ out) {
    extern __shared__ unsigned gsm[];
    const uint32_t sbase = smem_u32(gsm);

    const int e0 = blockIdx.x * 128;
    const int m0 = blockIdx.y * 128;
    const int tid = threadIdx.x;
    const int wid = tid >> 5, lane = tid & 31;
    const int wm = wid >> 2, wn = wid & 3;   // 4m x 4e
    const int g = lane >> 2, t4 = lane & 3;

    const float* Ap = QKV ? A : (const float*)g_ctx;

    float acc[2][4][4];
#pragma unroll
    for (int mt = 0; mt < 2; mt++)
#pragma unroll
        for (int nt = 0; nt < 4; nt++)
#pragma unroll
            for (int r = 0; r < 4; r++) acc[mt][nt][r] = 0.f;

    float4 av[4], wv[4];

#define LDG_CHUNK(KC)                                                              \
    do {                                                                           \
        _Pragma("unroll") for (int i = 0; i < 4; i++) {                            \
            int idx = tid + i * 512;                                               \
            int r = idx >> 4, c = idx & 15;                                        \
            av[i] = *(const float4*)(Ap + (size_t)(m0 + r) * 512 + (KC) + c * 4);  \
        }                                                                          \
        _Pragma("unroll") for (int i = 0; i < 4; i++) {                            \
            int idx = tid + i * 512;                                               \
            int r = idx >> 4, c = idx & 15;                                        \
            wv[i] = *(const float4*)(W + (size_t)(e0 + r) * 512 + (KC) + c * 4);   \
        }                                                                          \
    } while (0)

#define STS_CHUNK(BUF)                                                    \
    do {                                                                  \
        unsigned* b_ = (BUF);                                             \
        _Pragma("unroll") for (int i = 0; i < 4; i++) {                   \
            int idx = tid + i * 512;                                      \
            int r = idx >> 4, c = idx & 15;                               \
            if (QKV) {                                                    \
                unsigned h0 = pack2f(av[i].x, av[i].y);                   \
                unsigned h1 = pack2f(av[i].z, av[i].w);                   \
                *(uint2*)&b_[GAH + r * 36 + c * 2] = make_uint2(h0, h1);  \
            } else {                                                      \
                unsigned h0, l0, h1, l1;                                  \
                split2f(av[i].x, av[i].y, h0, l0);                        \
                split2f(av[i].z, av[i].w, h1, l1);                        \
                *(uint2*)&b_[GAH + r * 36 + c * 2] = make_uint2(h0, h1);  \
                *(uint2*)&b_[GAL + r * 36 + c * 2] = make_uint2(l0, l1);  \
            }                                                             \
        }                                                                 \
        _Pragma("unroll") for (int i = 0; i < 4; i++) {                   \
            int idx = tid + i * 512;                                      \
            int r = idx >> 4, c = idx & 15;                               \
            unsigned h0 = pack2f(wv[i].x, wv[i].y);                       \
            unsigned h1 = pack2f(wv[i].z, wv[i].w);                       \
            *(uint2*)&b_[GWH + r * 36 + c * 2] = make_uint2(h0, h1);      \
        }                                                                 \
    } while (0)

    LDG_CHUNK(0);
    STS_CHUNK(gsm);
    __syncthreads();

    const uint32_t aRowOff = (uint32_t)(lane & 15) * 144;
    const uint32_t aColOff = (uint32_t)(lane >> 4) * 16;
    const uint32_t bRowOff = (uint32_t)((lane & 7) + ((lane >> 4) << 3)) * 144;
    const uint32_t bColOff = (uint32_t)((lane >> 3) & 1) * 16;

    int cur = 0;
    for (int kc = 0; kc < 512; kc += 64) {
        if (kc + 64 < 512) LDG_CHUNK(kc + 64);
        const uint32_t bb = sbase + cur * (GBUF * 4);
#pragma unroll
        for (int ks = 0; ks < 4; ks++) {
            const uint32_t kOff = ks * 32;
            unsigned ah[2][4], al[2][4], bh[2][4];
#pragma unroll
            for (int mt = 0; mt < 2; mt++) {
                uint32_t base = bb + (wm * 32 + mt * 16) * 144 + aRowOff + kOff + aColOff;
                ldsm_x4(ah[mt], base + GAH * 4);
                if (!QKV) ldsm_x4(al[mt], base + GAL * 4);
            }
#pragma unroll
            for (int ntp = 0; ntp < 2; ntp++) {
                uint32_t base = bb + (wn * 32 + ntp * 16) * 144 + bRowOff + kOff + bColOff;
                ldsm_x4(bh[ntp], base + GWH * 4);
            }
#pragma unroll
            for (int mt = 0; mt < 2; mt++)
#pragma unroll
                for (int nt = 0; nt < 4; nt++) {
                    const unsigned* BH = &bh[nt >> 1][(nt & 1) * 2];
                    mmaf(acc[mt][nt], ah[mt], BH);
                    if (!QKV) mmaf(acc[mt][nt], al[mt], BH);
                }
        }
        if (kc + 64 < 512) STS_CHUNK(gsm + (cur ^ 1) * GBUF);
        __syncthreads();
        cur ^= 1;
    }

    if (QKV) {
#pragma unroll
        for (int mt = 0; mt < 2; mt++)
#pragma unroll
            for (int half = 0; half < 2; half++) {
                int m = m0 + wm * 32 + mt * 16 + g + half * 8;
                int nbt = m >> 11, tt = m & 2047;
#pragma unroll
                for (int nt = 0; nt < 4; nt++) {
                    int e = e0 + wn * 32 + nt * 8 + t4 * 2;
                    int sec = e >> 9;
                    int h = (e >> 6) & 7;
                    int d = e & 63;
                    __half* buf = (sec == 0) ? g_qh : (sec == 1) ? g_kh : g_vh;
                    *(unsigned*)(buf + (((size_t)(nbt * NH + h)) * TT + tt) * HD + d) =
                        pack2f(acc[mt][nt][half * 2], acc[mt][nt][half * 2 + 1]);
                }
            }
    } else {
#pragma unroll
        for (int mt = 0; mt < 2; mt++)
#pragma unroll
            for (int half = 0; half < 2; half++) {
                int m = m0 + wm * 32 + mt * 16 + g + half * 8;
#pragma unroll
                for (int nt = 0; nt < 4; nt++) {
                    int e = e0 + wn * 32 + nt * 8 + t4 * 2;
                    float2 bv = *(const float2*)(bias + e);
                    *(float2*)(out + (size_t)m * 512 + e) =
                        make_float2(acc[mt][nt][half * 2] + bv.x,
                                    acc[mt][nt][half * 2 + 1] + bv.y);
                }
            }
    }
}

// ---------------------------------------------------------------------------
// RoPE trig table
// ---------------------------------------------------------------------------
__global__ void __launch_bounds__(256) rope_table_kernel() {
    int idx = blockIdx.x * 256 + threadIdx.x;
    if (idx >= TT * 32) return;
    int t = idx >> 5, lane = idx & 31;
    double inv_freq = pow(10000.0, -((double)(2 * lane) / 64.0));
    float ang = (float)t * (float)inv_freq;
    g_rc[idx] = (float)cos((double)ang);
    g_rs[idx] = (float)sin((double)ang);
}

// ---------------------------------------------------------------------------
// Sliding-window attention (R13 known-good: pure fp16, fp16 q/k/v globals,
// ldmatrix, fused RoPE, register-resident P).
// ---------------------------------------------------------------------------
#define KPL 0
#define VPL 4608
#define ATT_SMEM_U32 9216

__global__ void __launch_bounds__(256) attn_kernel() {
    extern __shared__ unsigned sv[];
    const uint32_t sbase = smem_u32(sv);

    const int qt = blockIdx.x;
    const int h = blockIdx.y;
    const int n = blockIdx.z;
    const int q0 = qt * 128;
    const int tid = threadIdx.x;
    const int wid = tid >> 5, lane = tid & 31;
    const int g = lane >> 2, t4 = lane & 3;
    const int qr = wid * 16 + g;

    const size_t hb = ((size_t)(n * NH + h)) * TT * HD;
    const __half* qg = g_qh + hb;
    const __half* kg = g_kh + hb;
    const __half* vg = g_vh + hb;

    const uint32_t aRow36 = (uint32_t)(lane & 15) * 144;
    const uint32_t aColH = (uint32_t)(lane >> 4) * 16;
    const uint32_t bRow36 = (uint32_t)((lane & 7) + ((lane >> 4) << 3)) * 144;
    const uint32_t bRow68 = (uint32_t)((lane & 7) + ((lane >> 4) << 3)) * 272;
    const uint32_t bColH = (uint32_t)((lane >> 3) & 1) * 16;

    // stage Q with fused RoPE: fp16 plane at KPL (stride 36)
#pragma unroll
    for (int i = 0; i < 4; i++) {
        int idx = tid + i * 256;
        int r = idx >> 3, d4 = idx & 7;
        const __half* row = qg + (size_t)(q0 + r) * HD;
        float4 a = ld4h(row + d4 * 4);
        float4 b = ld4h(row + d4 * 4 + 32);
        const float4 cv = *(const float4*)(g_rc + (size_t)(q0 + r) * 32 + d4 * 4);
        const float4 sn = *(const float4*)(g_rs + (size_t)(q0 + r) * 32 + d4 * 4);
        float4 lo = make_float4(a.x * cv.x - b.x * sn.x, a.y * cv.y - b.y * sn.y,
                                a.z * cv.z - b.z * sn.z, a.w * cv.w - b.w * sn.w);
        float4 hi = make_float4(b.x * cv.x + a.x * sn.x, b.y * cv.y + a.y * sn.y,
                                b.z * cv.z + a.z * sn.z, b.w * cv.w + a.w * sn.w);
        *(uint2*)&sv[KPL + r * 36 + d4 * 2] =
            make_uint2(pack2f(lo.x, lo.y), pack2f(lo.z, lo.w));
        *(uint2*)&sv[KPL + r * 36 + (d4 + 8) * 2] =
            make_uint2(pack2f(hi.x, hi.y), pack2f(hi.z, hi.w));
    }
    __syncthreads();

    unsigned aqh[4][4];
#pragma unroll
    for (int ks = 0; ks < 4; ks++) {
        uint32_t base = sbase + (wid * 16) * 144 + aRow36 + ks * 32 + aColH;
        ldsm_x4(aqh[ks], base + KPL * 4);
    }
    __syncthreads();

    float m_i[2] = {-1e30f, -1e30f};
    float l_i[2] = {0.f, 0.f};
    float o[8][4];
#pragma unroll
    for (int nt = 0; nt < 8; nt++)
#pragma unroll
        for (int r = 0; r < 4; r++) o[nt][r] = 0.f;

    int c0 = qt - 1; if (c0 < 0) c0 = 0;
    int c1 = qt + 1; if (c1 > 15) c1 = 15;

    for (int c = c0; c <= c1; c++) {
        const int j0 = c * 128;

        const int rowlo = q0 + wid * 16;
        int ntLo = (rowlo - 127 - j0) >> 3;
        if (ntLo < 0) ntLo = 0;
        ntLo &= ~1;
        int ntHi = (rowlo + 15 + 128 - j0) >> 3;
        if (ntHi > 15) ntHi = 15;
        ntHi |= 1;
        const int kspLo = ntLo >> 1, kspHi = ntHi >> 1;

        // stage K with fused RoPE (fp16 source)
#pragma unroll
        for (int i = 0; i < 4; i++) {
            int idx = tid + i * 256;
            int r = idx >> 3, d4 = idx & 7;
            const __half* row = kg + (size_t)(j0 + r) * HD;
            float4 a = ld4h(row + d4 * 4);
            float4 b = ld4h(row + d4 * 4 + 32);
            const float4 cv = *(const float4*)(g_rc + (size_t)(j0 + r) * 32 + d4 * 4);
            const float4 sn = *(const float4*)(g_rs + (size_t)(j0 + r) * 32 + d4 * 4);
            float4 lo = make_float4(a.x * cv.x - b.x * sn.x, a.y * cv.y - b.y * sn.y,
                                    a.z * cv.z - b.z * sn.z, a.w * cv.w - b.w * sn.w);
            float4 hi = make_float4(b.x * cv.x + a.x * sn.x, b.y * cv.y + a.y * sn.y,
                                    b.z * cv.z + a.z * sn.z, b.w * cv.w + a.w * sn.w);
            *(uint2*)&sv[KPL + r * 36 + d4 * 2] =
                make_uint2(pack2f(lo.x, lo.y), pack2f(lo.z, lo.w));
            *(uint2*)&sv[KPL + r * 36 + (d4 + 8) * 2] =
                make_uint2(pack2f(hi.x, hi.y), pack2f(hi.z, hi.w));
        }
        // stage V transposed (fp16 source, zero-convert half2 shuffles)
#pragma unroll
        for (int i = 0; i < 4; i++) {
            int idx = tid + i * 256;
            int rp = idx >> 4, d4 = idx & 15;
            uint2 ua = *(const uint2*)(vg + (size_t)(j0 + 2 * rp) * HD + d4 * 4);
            uint2 ub = *(const uint2*)(vg + (size_t)(j0 + 2 * rp + 1) * HD + d4 * 4);
            __half2 a01 = *reinterpret_cast<__half2*>(&ua.x);
            __half2 a23 = *reinterpret_cast<__half2*>(&ua.y);
            __half2 b01 = *reinterpret_cast<__half2*>(&ub.x);
            __half2 b23 = *reinterpret_cast<__half2*>(&ub.y);
            __half2 p0 = __lows2half2(a01, b01);
            __half2 p1 = __highs2half2(a01, b01);
            __half2 p2 = __lows2half2(a23, b23);
            __half2 p3 = __highs2half2(a23, b23);
            sv[VPL + (d4 * 4 + 0) * 68 + rp] = *reinterpret_cast<unsigned*>(&p0);
            sv[VPL + (d4 * 4 + 1) * 68 + rp] = *reinterpret_cast<unsigned*>(&p1);
            sv[VPL + (d4 * 4 + 2) * 68 + rp] = *reinterpret_cast<unsigned*>(&p2);
            sv[VPL + (d4 * 4 + 3) * 68 + rp] = *reinterpret_cast<unsigned*>(&p3);
        }
        __syncthreads();

        // S = Q . K^T (live n-tile pairs)
        float s[16][4];
#pragma unroll
        for (int nt = 0; nt < 16; nt++)
#pragma unroll
            for (int r = 0; r < 4; r++) s[nt][r] = 0.f;

#pragma unroll
        for (int ntp = 0; ntp < 8; ntp++) {
            if (ntp * 2 < ntLo || ntp * 2 > ntHi) continue;
#pragma unroll
            for (int ks = 0; ks < 4; ks++) {
                unsigned bh4[4];
                uint32_t base = sbase + (ntp * 16) * 144 + bRow36 + ks * 32 + bColH;
                ldsm_x4(bh4, base + KPL * 4);
                mmaf(s[ntp * 2], aqh[ks], bh4);
                mmaf(s[ntp * 2 + 1], aqh[ks], bh4 + 2);
            }
        }

        // mask + online softmax
#pragma unroll
        for (int half = 0; half < 2; half++) {
            const int rowg = q0 + qr + half * 8;
            float mx = -1e30f;
#pragma unroll
            for (int nt = 0; nt < 16; nt++) {
                if (nt < ntLo || nt > ntHi) continue;
#pragma unroll
                for (int cc = 0; cc < 2; cc++) {
                    int colg = j0 + nt * 8 + t4 * 2 + cc;
                    bool valid = (colg >= rowg - 127) && (colg <= rowg + 128);
                    float v = valid ? s[nt][half * 2 + cc] * SCALE : -1e30f;
                    s[nt][half * 2 + cc] = v;
                    mx = fmaxf(mx, v);
                }
            }
            mx = fmaxf(mx, __shfl_xor_sync(0xffffffffu, mx, 1));
            mx = fmaxf(mx, __shfl_xor_sync(0xffffffffu, mx, 2));
            float mnew = fmaxf(m_i[half], mx);
            float alpha = __expf(m_i[half] - mnew);
            float sum = 0.f;
#pragma unroll
            for (int nt = 0; nt < 16; nt++) {
                if (nt < ntLo || nt > ntHi) continue;
#pragma unroll
                for (int cc = 0; cc < 2; cc++) {
                    float v = s[nt][half * 2 + cc];
                    float p = (v > -1e29f) ? __expf(v - mnew) : 0.f;
                    sum += p;
                    s[nt][half * 2 + cc] = p;
                }
            }
            sum += __shfl_xor_sync(0xffffffffu, sum, 1);
            sum += __shfl_xor_sync(0xffffffffu, sum, 2);
            l_i[half] = l_i[half] * alpha + sum;
            m_i[half] = mnew;
#pragma unroll
            for (int nt = 0; nt < 8; nt++) {
                o[nt][half * 2] *= alpha;
                o[nt][half * 2 + 1] *= alpha;
            }
        }

        // O += P . V
#pragma unroll
        for (int ksp = 0; ksp < 8; ksp++) {
            if (ksp < kspLo || ksp > kspHi) continue;
            unsigned aph[4];
            aph[0] = pack2f(s[2 * ksp][0], s[2 * ksp][1]);
            aph[1] = pack2f(s[2 * ksp][2], s[2 * ksp][3]);
            aph[2] = pack2f(s[2 * ksp + 1][0], s[2 * ksp + 1][1]);
            aph[3] = pack2f(s[2 * ksp + 1][2], s[2 * ksp + 1][3]);
#pragma unroll
            for (int ntp = 0; ntp < 4; ntp++) {
                unsigned bh4[4];
                uint32_t vbase = sbase + VPL * 4 + (ntp * 16) * 272 + bRow68 +
                                 ksp * 32 + bColH;
                ldsm_x4(bh4, vbase);
                mmaf(o[ntp * 2], aph, bh4);
                mmaf(o[ntp * 2 + 1], aph, bh4 + 2);
            }
        }
        __syncthreads();
    }

    // epilogue
#pragma unroll
    for (int half = 0; half < 2; half++) {
        const int rowg = q0 + qr + half * 8;
        const float invl = 1.f / l_i[half];
        const size_t ob = ((size_t)n * TT + rowg) * DM + h * HD;
#pragma unroll
        for (int nt = 0; nt < 8; nt++) {
            int d = nt * 8 + t4 * 2;
            *(float2*)(g_ctx + ob + d) =
                make_float2(o[nt][half * 2] * invl, o[nt][half * 2 + 1] * invl);
        }
    }
}

// ---------------------------------------------------------------------------
extern "C" void kernel_launch(void* const* d_in, const int* in_sizes, int n_in,
                              void* d_out, int out_size) {
    const float* x    = (const float*)d_in[0];   // [4,2048,512]
    const float* wqkv = (const float*)d_in[1];   // [1536,512]
    const float* outw = (const float*)d_in[2];   // [512,512]
    const float* outb = (const float*)d_in[3];   // [512]
    float* out = (float*)d_out;

    const int gemm_smem = 2 * GBUF * sizeof(unsigned);        // 110592
    const int att_smem = ATT_SMEM_U32 * sizeof(unsigned);     // 36864

    cudaFuncSetAttribute(gemm_hx<true>, cudaFuncAttributeMaxDynamicSharedMemorySize, gemm_smem);
    cudaFuncSetAttribute(gemm_hx<false>, cudaFuncAttributeMaxDynamicSharedMemorySize, gemm_smem);
    cudaFuncSetAttribute(attn_kernel, cudaFuncAttributeMaxDynamicSharedMemorySize, att_smem);

    rope_table_kernel<<<(TT * 32 + 255) / 256, 256>>>();
    gemm_hx<true><<<dim3(1536 / 128, 8192 / 128), 512, gemm_smem>>>(x, wqkv, nullptr, nullptr);
    attn_kernel<<<dim3(TT / 128, NH, NB), 256, att_smem>>>();
    gemm_hx<false><<<dim3(512 / 128, 8192 / 128), 512, gemm_smem>>>(nullptr, outw, outb, out);
}

// round 15
// speedup vs baseline: 1.5075x; 1.0282x over previous
#include <cuda_runtime.h>
#include <cuda_fp16.h>
#include <math.h>
#include <cstdint>

#define NB 4
#define TT 2048
#define DM 512
#define NH 8
#define HD 64
#define SCALE 0.125f

// Scratch (no allocation allowed)
__device__ __half g_qh[NB * NH * TT * HD];
__device__ __half g_kh[NB * NH * TT * HD];
__device__ __half g_vh[NB * NH * TT * HD];
__device__ float g_ctx[NB * TT * DM];
__device__ float g_rc[TT * 32];
__device__ float g_rs[TT * 32];

// pack two floats -> f16x2 (e0 in low half), rne
__device__ __forceinline__ unsigned pack2f(float e0, float e1) {
    unsigned r;
    asm("cvt.rn.f16x2.f32 %0, %1, %2;" : "=r"(r) : "f"(e1), "f"(e0));
    return r;
}
// split (f0,f1) into hi f16x2 + lo (residual) f16x2
__device__ __forceinline__ void split2f(float f0, float f1, unsigned& hi, unsigned& lo) {
    unsigned h = pack2f(f0, f1);
    float h0, h1;
    asm("{.reg .b16 x, y; mov.b32 {x, y}, %2; cvt.f32.f16 %0, x; cvt.f32.f16 %1, y;}"
        : "=f"(h0), "=f"(h1) : "r"(h));
    lo = pack2f(f0 - h0, f1 - h1);
    hi = h;
}
__device__ __forceinline__ void mmaf(float* c, const unsigned* a, const unsigned* b) {
    asm volatile(
        "mma.sync.aligned.m16n8k16.row.col.f32.f16.f16.f32 "
        "{%0,%1,%2,%3},{%4,%5,%6,%7},{%8,%9},{%0,%1,%2,%3};"
        : "+f"(c[0]), "+f"(c[1]), "+f"(c[2]), "+f"(c[3])
        : "r"(a[0]), "r"(a[1]), "r"(a[2]), "r"(a[3]), "r"(b[0]), "r"(b[1]));
}
__device__ __forceinline__ uint32_t smem_u32(const void* p) {
    uint32_t a;
    asm("{ .reg .u64 t; cvta.to.shared.u64 t, %1; cvt.u32.u64 %0, t; }" : "=r"(a) : "l"(p));
    return a;
}
__device__ __forceinline__ void ldsm_x4(unsigned* r, uint32_t addr) {
    asm volatile("ldmatrix.sync.aligned.m8n8.x4.shared.b16 {%0,%1,%2,%3}, [%4];"
                 : "=r"(r[0]), "=r"(r[1]), "=r"(r[2]), "=r"(r[3]) : "r"(addr));
}
// load 4 consecutive halves -> float4
__device__ __forceinline__ float4 ld4h(const __half* p) {
    uint2 u = *(const uint2*)p;
    float2 f01 = __half22float2(*reinterpret_cast<__half2*>(&u.x));
    float2 f23 = __half22float2(*reinterpret_cast<__half2*>(&u.y));
    return make_float4(f01.x, f01.y, f23.x, f23.y);
}

// ---------------------------------------------------------------------------
// FP16 GEMM (R14 known-good), K-chunk 64.
// ---------------------------------------------------------------------------
#define GAH 0
#define GAL 4608
#define GWH 9216
#define GBUF 13824

template <bool QKV>
__global__ void __launch_bounds__(512, 1) gemm_hx(const float* __restrict__ A,
                                                  const float* __restrict__ W,
                                                  const float* __restrict__ bias,
                                                  float* __restrict__ out) {
    extern __shared__ unsigned gsm[];
    const uint32_t sbase = smem_u32(gsm);

    const int e0 = blockIdx.x * 128;
    const int m0 = blockIdx.y * 128;
    const int tid = threadIdx.x;
    const int wid = tid >> 5, lane = tid & 31;
    const int wm = wid >> 2, wn = wid & 3;   // 4m x 4e
    const int g = lane >> 2, t4 = lane & 3;

    const float* Ap = QKV ? A : (const float*)g_ctx;

    float acc[2][4][4];
#pragma unroll
    for (int mt = 0; mt < 2; mt++)
#pragma unroll
        for (int nt = 0; nt < 4; nt++)
#pragma unroll
            for (int r = 0; r < 4; r++) acc[mt][nt][r] = 0.f;

    float4 av[4], wv[4];

#define LDG_CHUNK(KC)                                                              \
    do {                                                                           \
        _Pragma("unroll") for (int i = 0; i < 4; i++) {                            \
            int idx = tid + i * 512;                                               \
            int r = idx >> 4, c = idx & 15;                                        \
            av[i] = *(const float4*)(Ap + (size_t)(m0 + r) * 512 + (KC) + c * 4);  \
        }                                                                          \
        _Pragma("unroll") for (int i = 0; i < 4; i++) {                            \
            int idx = tid + i * 512;                                               \
            int r = idx >> 4, c = idx & 15;                                        \
            wv[i] = *(const float4*)(W + (size_t)(e0 + r) * 512 + (KC) + c * 4);   \
        }                                                                          \
    } while (0)

#define STS_CHUNK(BUF)                                                    \
    do {                                                                  \
        unsigned* b_ = (BUF);                                             \
        _Pragma("unroll") for (int i = 0; i < 4; i++) {                   \
            int idx = tid + i * 512;                                      \
            int r = idx >> 4, c = idx & 15;                               \
            if (QKV) {                                                    \
                unsigned h0 = pack2f(av[i].x, av[i].y);                   \
                unsigned h1 = pack2f(av[i].z, av[i].w);                   \
                *(uint2*)&b_[GAH + r * 36 + c * 2] = make_uint2(h0, h1);  \
            } else {                                                      \
                unsigned h0, l0, h1, l1;                                  \
                split2f(av[i].x, av[i].y, h0, l0);                        \
                split2f(av[i].z, av[i].w, h1, l1);                        \
                *(uint2*)&b_[GAH + r * 36 + c * 2] = make_uint2(h0, h1);  \
                *(uint2*)&b_[GAL + r * 36 + c * 2] = make_uint2(l0, l1);  \
            }                                                             \
        }                                                                 \
        _Pragma("unroll") for (int i = 0; i < 4; i++) {                   \
            int idx = tid + i * 512;                                      \
            int r = idx >> 4, c = idx & 15;                               \
            unsigned h0 = pack2f(wv[i].x, wv[i].y);                       \
            unsigned h1 = pack2f(wv[i].z, wv[i].w);                       \
            *(uint2*)&b_[GWH + r * 36 + c * 2] = make_uint2(h0, h1);      \
        }                                                                 \
    } while (0)

    LDG_CHUNK(0);
    STS_CHUNK(gsm);
    __syncthreads();

    const uint32_t aRowOff = (uint32_t)(lane & 15) * 144;
    const uint32_t aColOff = (uint32_t)(lane >> 4) * 16;
    const uint32_t bRowOff = (uint32_t)((lane & 7) + ((lane >> 4) << 3)) * 144;
    const uint32_t bColOff = (uint32_t)((lane >> 3) & 1) * 16;

    int cur = 0;
    for (int kc = 0; kc < 512; kc += 64) {
        if (kc + 64 < 512) LDG_CHUNK(kc + 64);
        const uint32_t bb = sbase + cur * (GBUF * 4);
#pragma unroll
        for (int ks = 0; ks < 4; ks++) {
            const uint32_t kOff = ks * 32;
            unsigned ah[2][4], al[2][4], bh[2][4];
#pragma unroll
            for (int mt = 0; mt < 2; mt++) {
                uint32_t base = bb + (wm * 32 + mt * 16) * 144 + aRowOff + kOff + aColOff;
                ldsm_x4(ah[mt], base + GAH * 4);
                if (!QKV) ldsm_x4(al[mt], base + GAL * 4);
            }
#pragma unroll
            for (int ntp = 0; ntp < 2; ntp++) {
                uint32_t base = bb + (wn * 32 + ntp * 16) * 144 + bRowOff + kOff + bColOff;
                ldsm_x4(bh[ntp], base + GWH * 4);
            }
#pragma unroll
            for (int mt = 0; mt < 2; mt++)
#pragma unroll
                for (int nt = 0; nt < 4; nt++) {
                    const unsigned* BH = &bh[nt >> 1][(nt & 1) * 2];
                    mmaf(acc[mt][nt], ah[mt], BH);
                    if (!QKV) mmaf(acc[mt][nt], al[mt], BH);
                }
        }
        if (kc + 64 < 512) STS_CHUNK(gsm + (cur ^ 1) * GBUF);
        __syncthreads();
        cur ^= 1;
    }

    if (QKV) {
#pragma unroll
        for (int mt = 0; mt < 2; mt++)
#pragma unroll
            for (int half = 0; half < 2; half++) {
                int m = m0 + wm * 32 + mt * 16 + g + half * 8;
                int nbt = m >> 11, tt = m & 2047;
#pragma unroll
                for (int nt = 0; nt < 4; nt++) {
                    int e = e0 + wn * 32 + nt * 8 + t4 * 2;
                    int sec = e >> 9;
                    int h = (e >> 6) & 7;
                    int d = e & 63;
                    __half* buf = (sec == 0) ? g_qh : (sec == 1) ? g_kh : g_vh;
                    *(unsigned*)(buf + (((size_t)(nbt * NH + h)) * TT + tt) * HD + d) =
                        pack2f(acc[mt][nt][half * 2], acc[mt][nt][half * 2 + 1]);
                }
            }
    } else {
#pragma unroll
        for (int mt = 0; mt < 2; mt++)
#pragma unroll
            for (int half = 0; half < 2; half++) {
                int m = m0 + wm * 32 + mt * 16 + g + half * 8;
#pragma unroll
                for (int nt = 0; nt < 4; nt++) {
                    int e = e0 + wn * 32 + nt * 8 + t4 * 2;
                    float2 bv = *(const float2*)(bias + e);
                    *(float2*)(out + (size_t)m * 512 + e) =
                        make_float2(acc[mt][nt][half * 2] + bv.x,
                                    acc[mt][nt][half * 2 + 1] + bv.y);
                }
            }
    }
}

// ---------------------------------------------------------------------------
// RoPE trig table
// ---------------------------------------------------------------------------
__global__ void __launch_bounds__(256) rope_table_kernel() {
    int idx = blockIdx.x * 256 + threadIdx.x;
    if (idx >= TT * 32) return;
    int t = idx >> 5, lane = idx & 31;
    double inv_freq = pow(10000.0, -((double)(2 * lane) / 64.0));
    float ang = (float)t * (float)inv_freq;
    g_rc[idx] = (float)cos((double)ang);
    g_rs[idx] = (float)sin((double)ang);
}

// ---------------------------------------------------------------------------
// Sliding-window attention: 256 q-rows per CTA, 512 threads = 16 warps,
// each warp owns 16 q rows. Key chunks of 128 over [2qt-1, 2qt+2].
// Pure fp16 operands, ldmatrix, fused RoPE, register-resident P.
// ---------------------------------------------------------------------------
#define KPL 0
#define VPL 4608
#define ATT_SMEM_U32 9216

__global__ void __launch_bounds__(512) attn_kernel() {
    extern __shared__ unsigned sv[];
    const uint32_t sbase = smem_u32(sv);

    const int qt = blockIdx.x;
    const int h = blockIdx.y;
    const int n = blockIdx.z;
    const int q0 = qt * 256;
    const int tid = threadIdx.x;
    const int wid = tid >> 5, lane = tid & 31;
    const int g = lane >> 2, t4 = lane & 3;
    const int qr = wid * 16 + g;   // 0..255 (+g)

    const size_t hb = ((size_t)(n * NH + h)) * TT * HD;
    const __half* qg = g_qh + hb;
    const __half* kg = g_kh + hb;
    const __half* vg = g_vh + hb;

    const uint32_t aRow36 = (uint32_t)(lane & 15) * 144;
    const uint32_t aColH = (uint32_t)(lane >> 4) * 16;
    const uint32_t bRow36 = (uint32_t)((lane & 7) + ((lane >> 4) << 3)) * 144;
    const uint32_t bRow68 = (uint32_t)((lane & 7) + ((lane >> 4) << 3)) * 272;
    const uint32_t bColH = (uint32_t)((lane >> 3) & 1) * 16;

    // ---- stage Q (256 rows) with fused RoPE across the whole smem buffer ----
#pragma unroll
    for (int i = 0; i < 4; i++) {
        int idx = tid + i * 512;          // 2048: 256 rows x 8 d4
        int r = idx >> 3, d4 = idx & 7;
        const __half* row = qg + (size_t)(q0 + r) * HD;
        float4 a = ld4h(row + d4 * 4);
        float4 b = ld4h(row + d4 * 4 + 32);
        const float4 cv = *(const float4*)(g_rc + (size_t)(q0 + r) * 32 + d4 * 4);
        const float4 sn = *(const float4*)(g_rs + (size_t)(q0 + r) * 32 + d4 * 4);
        float4 lo = make_float4(a.x * cv.x - b.x * sn.x, a.y * cv.y - b.y * sn.y,
                                a.z * cv.z - b.z * sn.z, a.w * cv.w - b.w * sn.w);
        float4 hi = make_float4(b.x * cv.x + a.x * sn.x, b.y * cv.y + a.y * sn.y,
                                b.z * cv.z + a.z * sn.z, b.w * cv.w + a.w * sn.w);
        *(uint2*)&sv[r * 36 + d4 * 2] =
            make_uint2(pack2f(lo.x, lo.y), pack2f(lo.z, lo.w));
        *(uint2*)&sv[r * 36 + (d4 + 8) * 2] =
            make_uint2(pack2f(hi.x, hi.y), pack2f(hi.z, hi.w));
    }
    __syncthreads();

    unsigned aqh[4][4];
#pragma unroll
    for (int ks = 0; ks < 4; ks++) {
        uint32_t base = sbase + (wid * 16) * 144 + aRow36 + ks * 32 + aColH;
        ldsm_x4(aqh[ks], base);
    }
    __syncthreads();

    float m_i[2] = {-1e30f, -1e30f};
    float l_i[2] = {0.f, 0.f};
    float o[8][4];
#pragma unroll
    for (int nt = 0; nt < 8; nt++)
#pragma unroll
        for (int r = 0; r < 4; r++) o[nt][r] = 0.f;

    int c0 = 2 * qt - 1; if (c0 < 0) c0 = 0;
    int c1 = 2 * qt + 2; if (c1 > 15) c1 = 15;

    for (int c = c0; c <= c1; c++) {
        const int j0 = c * 128;

        const int rowlo = q0 + wid * 16;
        int ntLo = (rowlo - 127 - j0) >> 3;
        if (ntLo < 0) ntLo = 0;
        ntLo &= ~1;
        int ntHi = (rowlo + 15 + 128 - j0) >> 3;
        if (ntHi > 15) ntHi = 15;
        ntHi |= 1;
        const int kspLo = ntLo >> 1, kspHi = ntHi >> 1;

        // stage K with fused RoPE (fp16 source), 128 rows at KPL (stride 36)
#pragma unroll
        for (int i = 0; i < 2; i++) {
            int idx = tid + i * 512;      // 1024: 128 rows x 8 d4
            int r = idx >> 3, d4 = idx & 7;
            const __half* row = kg + (size_t)(j0 + r) * HD;
            float4 a = ld4h(row + d4 * 4);
            float4 b = ld4h(row + d4 * 4 + 32);
            const float4 cv = *(const float4*)(g_rc + (size_t)(j0 + r) * 32 + d4 * 4);
            const float4 sn = *(const float4*)(g_rs + (size_t)(j0 + r) * 32 + d4 * 4);
            float4 lo = make_float4(a.x * cv.x - b.x * sn.x, a.y * cv.y - b.y * sn.y,
                                    a.z * cv.z - b.z * sn.z, a.w * cv.w - b.w * sn.w);
            float4 hi = make_float4(b.x * cv.x + a.x * sn.x, b.y * cv.y + a.y * sn.y,
                                    b.z * cv.z + a.z * sn.z, b.w * cv.w + a.w * sn.w);
            *(uint2*)&sv[KPL + r * 36 + d4 * 2] =
                make_uint2(pack2f(lo.x, lo.y), pack2f(lo.z, lo.w));
            *(uint2*)&sv[KPL + r * 36 + (d4 + 8) * 2] =
                make_uint2(pack2f(hi.x, hi.y), pack2f(hi.z, hi.w));
        }
        // stage V transposed (fp16 source, zero-convert half2 shuffles)
#pragma unroll
        for (int i = 0; i < 2; i++) {
            int idx = tid + i * 512;      // 1024: 64 keypairs x 16 d4
            int rp = idx >> 4, d4 = idx & 15;
            uint2 ua = *(const uint2*)(vg + (size_t)(j0 + 2 * rp) * HD + d4 * 4);
            uint2 ub = *(const uint2*)(vg + (size_t)(j0 + 2 * rp + 1) * HD + d4 * 4);
            __half2 a01 = *reinterpret_cast<__half2*>(&ua.x);
            __half2 a23 = *reinterpret_cast<__half2*>(&ua.y);
            __half2 b01 = *reinterpret_cast<__half2*>(&ub.x);
            __half2 b23 = *reinterpret_cast<__half2*>(&ub.y);
            __half2 p0 = __lows2half2(a01, b01);
            __half2 p1 = __highs2half2(a01, b01);
            __half2 p2 = __lows2half2(a23, b23);
            __half2 p3 = __highs2half2(a23, b23);
            sv[VPL + (d4 * 4 + 0) * 68 + rp] = *reinterpret_cast<unsigned*>(&p0);
            sv[VPL + (d4 * 4 + 1) * 68 + rp] = *reinterpret_cast<unsigned*>(&p1);
            sv[VPL + (d4 * 4 + 2) * 68 + rp] = *reinterpret_cast<unsigned*>(&p2);
            sv[VPL + (d4 * 4 + 3) * 68 + rp] = *reinterpret_cast<unsigned*>(&p3);
        }
        __syncthreads();

        // S = Q . K^T (live n-tile pairs)
        float s[16][4];
#pragma unroll
        for (int nt = 0; nt < 16; nt++)
#pragma unroll
            for (int r = 0; r < 4; r++) s[nt][r] = 0.f;

#pragma unroll
        for (int ntp = 0; ntp < 8; ntp++) {
            if (ntp * 2 + 1 < ntLo || ntp * 2 > ntHi) continue;
#pragma unroll
            for (int ks = 0; ks < 4; ks++) {
                unsigned bh4[4];
                uint32_t base = sbase + (ntp * 16) * 144 + bRow36 + ks * 32 + bColH;
                ldsm_x4(bh4, base + KPL * 4);
                mmaf(s[ntp * 2], aqh[ks], bh4);
                mmaf(s[ntp * 2 + 1], aqh[ks], bh4 + 2);
            }
        }

        // mask + online softmax
#pragma unroll
        for (int half = 0; half < 2; half++) {
            const int rowg = q0 + qr + half * 8;
            float mx = -1e30f;
#pragma unroll
            for (int nt = 0; nt < 16; nt++) {
                if (nt < ntLo || nt > ntHi) continue;
#pragma unroll
                for (int cc = 0; cc < 2; cc++) {
                    int colg = j0 + nt * 8 + t4 * 2 + cc;
                    bool valid = (colg >= rowg - 127) && (colg <= rowg + 128);
                    float v = valid ? s[nt][half * 2 + cc] * SCALE : -1e30f;
                    s[nt][half * 2 + cc] = v;
                    mx = fmaxf(mx, v);
                }
            }
            mx = fmaxf(mx, __shfl_xor_sync(0xffffffffu, mx, 1));
            mx = fmaxf(mx, __shfl_xor_sync(0xffffffffu, mx, 2));
            float mnew = fmaxf(m_i[half], mx);
            float alpha = __expf(m_i[half] - mnew);
            float sum = 0.f;
#pragma unroll
            for (int nt = 0; nt < 16; nt++) {
                if (nt < ntLo || nt > ntHi) continue;
#pragma unroll
                for (int cc = 0; cc < 2; cc++) {
                    float v = s[nt][half * 2 + cc];
                    float p = (v > -1e29f) ? __expf(v - mnew) : 0.f;
                    sum += p;
                    s[nt][half * 2 + cc] = p;
                }
            }
            sum += __shfl_xor_sync(0xffffffffu, sum, 1);
            sum += __shfl_xor_sync(0xffffffffu, sum, 2);
            l_i[half] = l_i[half] * alpha + sum;
            m_i[half] = mnew;
#pragma unroll
            for (int nt = 0; nt < 8; nt++) {
                o[nt][half * 2] *= alpha;
                o[nt][half * 2 + 1] *= alpha;
            }
        }

        // O += P . V
#pragma unroll
        for (int ksp = 0; ksp < 8; ksp++) {
            if (ksp < kspLo || ksp > kspHi) continue;
            unsigned aph[4];
            aph[0] = pack2f(s[2 * ksp][0], s[2 * ksp][1]);
            aph[1] = pack2f(s[2 * ksp][2], s[2 * ksp][3]);
            aph[2] = pack2f(s[2 * ksp + 1][0], s[2 * ksp + 1][1]);
            aph[3] = pack2f(s[2 * ksp + 1][2], s[2 * ksp + 1][3]);
#pragma unroll
            for (int ntp = 0; ntp < 4; ntp++) {
                unsigned bh4[4];
                uint32_t vbase = sbase + VPL * 4 + (ntp * 16) * 272 + bRow68 +
                                 ksp * 32 + bColH;
                ldsm_x4(bh4, vbase);
                mmaf(o[ntp * 2], aph, bh4);
                mmaf(o[ntp * 2 + 1], aph, bh4 + 2);
            }
        }
        __syncthreads();
    }

    // epilogue
#pragma unroll
    for (int half = 0; half < 2; half++) {
        const int rowg = q0 + qr + half * 8;
        const float invl = 1.f / l_i[half];
        const size_t ob = ((size_t)n * TT + rowg) * DM + h * HD;
#pragma unroll
        for (int nt = 0; nt < 8; nt++) {
            int d = nt * 8 + t4 * 2;
            *(float2*)(g_ctx + ob + d) =
                make_float2(o[nt][half * 2] * invl, o[nt][half * 2 + 1] * invl);
        }
    }
}

// ---------------------------------------------------------------------------
extern "C" void kernel_launch(void* const* d_in, const int* in_sizes, int n_in,
                              void* d_out, int out_size) {
    const float* x    = (const float*)d_in[0];   // [4,2048,512]
    const float* wqkv = (const float*)d_in[1];   // [1536,512]
    const float* outw = (const float*)d_in[2];   // [512,512]
    const float* outb = (const float*)d_in[3];   // [512]
    float* out = (float*)d_out;

    const int gemm_smem = 2 * GBUF * sizeof(unsigned);        // 110592
    const int att_smem = ATT_SMEM_U32 * sizeof(unsigned);     // 36864

    cudaFuncSetAttribute(gemm_hx<true>, cudaFuncAttributeMaxDynamicSharedMemorySize, gemm_smem);
    cudaFuncSetAttribute(gemm_hx<false>, cudaFuncAttributeMaxDynamicSharedMemorySize, gemm_smem);
    cudaFuncSetAttribute(attn_kernel, cudaFuncAttributeMaxDynamicSharedMemorySize, att_smem);

    rope_table_kernel<<<(TT * 32 + 255) / 256, 256>>>();
    gemm_hx<true><<<dim3(1536 / 128, 8192 / 128), 512, gemm_smem>>>(x, wqkv, nullptr, nullptr);
    attn_kernel<<<dim3(TT / 256, NH, NB), 512, att_smem>>>();
    gemm_hx<false><<<dim3(512 / 128, 8192 / 128), 512, gemm_smem>>>(nullptr, outw, outb, out);
}

// round 16
// speedup vs baseline: 1.5209x; 1.0089x over previous
#include <cuda_runtime.h>
#include <cuda_fp16.h>
#include <math.h>
#include <cstdint>

#define NB 4
#define TT 2048
#define DM 512
#define NH 8
#define HD 64
#define SCALE 0.125f

// Scratch (no allocation allowed)
__device__ __half g_qh[NB * NH * TT * HD];
__device__ __half g_kh[NB * NH * TT * HD];
__device__ __half g_vh[NB * NH * TT * HD];
__device__ float g_ctx[NB * TT * DM];
__device__ float g_rc[TT * 32];
__device__ float g_rs[TT * 32];
// pre-converted fp16 operands
__device__ __half g_xh[NB * TT * DM];
__device__ __half g_wqh[3 * DM * DM];
__device__ __half g_owh[DM * DM];

// pack two floats -> f16x2 (e0 in low half), rne
__device__ __forceinline__ unsigned pack2f(float e0, float e1) {
    unsigned r;
    asm("cvt.rn.f16x2.f32 %0, %1, %2;" : "=r"(r) : "f"(e1), "f"(e0));
    return r;
}
// split (f0,f1) into hi f16x2 + lo (residual) f16x2
__device__ __forceinline__ void split2f(float f0, float f1, unsigned& hi, unsigned& lo) {
    unsigned h = pack2f(f0, f1);
    float h0, h1;
    asm("{.reg .b16 x, y; mov.b32 {x, y}, %2; cvt.f32.f16 %0, x; cvt.f32.f16 %1, y;}"
        : "=f"(h0), "=f"(h1) : "r"(h));
    lo = pack2f(f0 - h0, f1 - h1);
    hi = h;
}
__device__ __forceinline__ void mmaf(float* c, const unsigned* a, const unsigned* b) {
    asm volatile(
        "mma.sync.aligned.m16n8k16.row.col.f32.f16.f16.f32 "
        "{%0,%1,%2,%3},{%4,%5,%6,%7},{%8,%9},{%0,%1,%2,%3};"
        : "+f"(c[0]), "+f"(c[1]), "+f"(c[2]), "+f"(c[3])
        : "r"(a[0]), "r"(a[1]), "r"(a[2]), "r"(a[3]), "r"(b[0]), "r"(b[1]));
}
__device__ __forceinline__ uint32_t smem_u32(const void* p) {
    uint32_t a;
    asm("{ .reg .u64 t; cvta.to.shared.u64 t, %1; cvt.u32.u64 %0, t; }" : "=r"(a) : "l"(p));
    return a;
}
__device__ __forceinline__ void ldsm_x4(unsigned* r, uint32_t addr) {
    asm volatile("ldmatrix.sync.aligned.m8n8.x4.shared.b16 {%0,%1,%2,%3}, [%4];"
                 : "=r"(r[0]), "=r"(r[1]), "=r"(r[2]), "=r"(r[3]) : "r"(addr));
}
// load 4 consecutive halves -> float4
__device__ __forceinline__ float4 ld4h(const __half* p) {
    uint2 u = *(const uint2*)p;
    float2 f01 = __half22float2(*reinterpret_cast<__half2*>(&u.x));
    float2 f23 = __half22float2(*reinterpret_cast<__half2*>(&u.y));
    return make_float4(f01.x, f01.y, f23.x, f23.y);
}

// ---------------------------------------------------------------------------
// fp32 -> fp16 convert (grid-stride over float4)
// ---------------------------------------------------------------------------
__global__ void __launch_bounds__(256) conv_h(const float* __restrict__ src,
                                              __half* __restrict__ dst, int n4) {
    int i = blockIdx.x * 256 + threadIdx.x;
    if (i >= n4) return;
    float4 v = ((const float4*)src)[i];
    ((uint2*)dst)[i] = make_uint2(pack2f(v.x, v.y), pack2f(v.z, v.w));
}

// ---------------------------------------------------------------------------
// FP16 GEMM, K-chunk 64, pre-converted fp16 W (both) and A (QKV path).
// QKV=true: A=g_xh fp16, epilogue -> fp16 q/k/v.
// QKV=false: A=g_ctx fp32 split hi/lo, epilogue -> fp32 out + bias.
// Block 128m x 128e, 512 threads = 16 warps (4m x 4e), warp tile 32x32.
// ---------------------------------------------------------------------------
#define GAH 0
#define GAL 4608
#define GWH 9216
#define GBUF 13824

template <bool QKV>
__global__ void __launch_bounds__(512, 1) gemm_hx(const float* __restrict__ bias,
                                                  float* __restrict__ out) {
    extern __shared__ unsigned gsm[];
    const uint32_t sbase = smem_u32(gsm);

    const int e0 = blockIdx.x * 128;
    const int m0 = blockIdx.y * 128;
    const int tid = threadIdx.x;
    const int wid = tid >> 5, lane = tid & 31;
    const int wm = wid >> 2, wn = wid & 3;   // 4m x 4e
    const int g = lane >> 2, t4 = lane & 3;

    const __half* Axh = g_xh;
    const float* Ap = (const float*)g_ctx;
    const __half* Wh = QKV ? g_wqh : g_owh;

    float acc[2][4][4];
#pragma unroll
    for (int mt = 0; mt < 2; mt++)
#pragma unroll
        for (int nt = 0; nt < 4; nt++)
#pragma unroll
            for (int r = 0; r < 4; r++) acc[mt][nt][r] = 0.f;

    uint4 avh[2], wvh[2];
    float4 av[4];

#define LDG_CHUNK(KC)                                                                \
    do {                                                                             \
        if (QKV) {                                                                   \
            _Pragma("unroll") for (int i = 0; i < 2; i++) {                          \
                int idx = tid + i * 512;                                             \
                int r = idx >> 3, c = idx & 7;                                       \
                avh[i] = *(const uint4*)(Axh + (size_t)(m0 + r) * 512 + (KC) + c * 8); \
            }                                                                        \
        } else {                                                                     \
            _Pragma("unroll") for (int i = 0; i < 4; i++) {                          \
                int idx = tid + i * 512;                                             \
                int r = idx >> 4, c = idx & 15;                                      \
                av[i] = *(const float4*)(Ap + (size_t)(m0 + r) * 512 + (KC) + c * 4); \
            }                                                                        \
        }                                                                            \
        _Pragma("unroll") for (int i = 0; i < 2; i++) {                              \
            int idx = tid + i * 512;                                                 \
            int r = idx >> 3, c = idx & 7;                                           \
            wvh[i] = *(const uint4*)(Wh + (size_t)(e0 + r) * 512 + (KC) + c * 8);    \
        }                                                                            \
    } while (0)

#define STS_CHUNK(BUF)                                                    \
    do {                                                                  \
        unsigned* b_ = (BUF);                                             \
        if (QKV) {                                                        \
            _Pragma("unroll") for (int i = 0; i < 2; i++) {               \
                int idx = tid + i * 512;                                  \
                int r = idx >> 3, c = idx & 7;                            \
                *(uint4*)&b_[GAH + r * 36 + c * 4] = avh[i];              \
            }                                                             \
        } else {                                                          \
            _Pragma("unroll") for (int i = 0; i < 4; i++) {               \
                int idx = tid + i * 512;                                  \
                int r = idx >> 4, c = idx & 15;                           \
                unsigned h0, l0, h1, l1;                                  \
                split2f(av[i].x, av[i].y, h0, l0);                        \
                split2f(av[i].z, av[i].w, h1, l1);                        \
                *(uint2*)&b_[GAH + r * 36 + c * 2] = make_uint2(h0, h1);  \
                *(uint2*)&b_[GAL + r * 36 + c * 2] = make_uint2(l0, l1);  \
            }                                                             \
        }                                                                 \
        _Pragma("unroll") for (int i = 0; i < 2; i++) {                   \
            int idx = tid + i * 512;                                      \
            int r = idx >> 3, c = idx & 7;                                \
            *(uint4*)&b_[GWH + r * 36 + c * 4] = wvh[i];                  \
        }                                                                 \
    } while (0)

    LDG_CHUNK(0);
    STS_CHUNK(gsm);
    __syncthreads();

    const uint32_t aRowOff = (uint32_t)(lane & 15) * 144;
    const uint32_t aColOff = (uint32_t)(lane >> 4) * 16;
    const uint32_t bRowOff = (uint32_t)((lane & 7) + ((lane >> 4) << 3)) * 144;
    const uint32_t bColOff = (uint32_t)((lane >> 3) & 1) * 16;

    int cur = 0;
    for (int kc = 0; kc < 512; kc += 64) {
        if (kc + 64 < 512) LDG_CHUNK(kc + 64);
        const uint32_t bb = sbase + cur * (GBUF * 4);
#pragma unroll
        for (int ks = 0; ks < 4; ks++) {
            const uint32_t kOff = ks * 32;
            unsigned ah[2][4], al[2][4], bh[2][4];
#pragma unroll
            for (int mt = 0; mt < 2; mt++) {
                uint32_t base = bb + (wm * 32 + mt * 16) * 144 + aRowOff + kOff + aColOff;
                ldsm_x4(ah[mt], base + GAH * 4);
                if (!QKV) ldsm_x4(al[mt], base + GAL * 4);
            }
#pragma unroll
            for (int ntp = 0; ntp < 2; ntp++) {
                uint32_t base = bb + (wn * 32 + ntp * 16) * 144 + bRowOff + kOff + bColOff;
                ldsm_x4(bh[ntp], base + GWH * 4);
            }
#pragma unroll
            for (int mt = 0; mt < 2; mt++)
#pragma unroll
                for (int nt = 0; nt < 4; nt++) {
                    const unsigned* BH = &bh[nt >> 1][(nt & 1) * 2];
                    mmaf(acc[mt][nt], ah[mt], BH);
                    if (!QKV) mmaf(acc[mt][nt], al[mt], BH);
                }
        }
        if (kc + 64 < 512) STS_CHUNK(gsm + (cur ^ 1) * GBUF);
        __syncthreads();
        cur ^= 1;
    }

    if (QKV) {
#pragma unroll
        for (int mt = 0; mt < 2; mt++)
#pragma unroll
            for (int half = 0; half < 2; half++) {
                int m = m0 + wm * 32 + mt * 16 + g + half * 8;
                int nbt = m >> 11, tt = m & 2047;
#pragma unroll
                for (int nt = 0; nt < 4; nt++) {
                    int e = e0 + wn * 32 + nt * 8 + t4 * 2;
                    int sec = e >> 9;
                    int h = (e >> 6) & 7;
                    int d = e & 63;
                    __half* buf = (sec == 0) ? g_qh : (sec == 1) ? g_kh : g_vh;
                    *(unsigned*)(buf + (((size_t)(nbt * NH + h)) * TT + tt) * HD + d) =
                        pack2f(acc[mt][nt][half * 2], acc[mt][nt][half * 2 + 1]);
                }
            }
    } else {
#pragma unroll
        for (int mt = 0; mt < 2; mt++)
#pragma unroll
            for (int half = 0; half < 2; half++) {
                int m = m0 + wm * 32 + mt * 16 + g + half * 8;
#pragma unroll
                for (int nt = 0; nt < 4; nt++) {
                    int e = e0 + wn * 32 + nt * 8 + t4 * 2;
                    float2 bv = *(const float2*)(bias + e);
                    *(float2*)(out + (size_t)m * 512 + e) =
                        make_float2(acc[mt][nt][half * 2] + bv.x,
                                    acc[mt][nt][half * 2 + 1] + bv.y);
                }
            }
    }
}

// ---------------------------------------------------------------------------
// RoPE trig table
// ---------------------------------------------------------------------------
__global__ void __launch_bounds__(256) rope_table_kernel() {
    int idx = blockIdx.x * 256 + threadIdx.x;
    if (idx >= TT * 32) return;
    int t = idx >> 5, lane = idx & 31;
    double inv_freq = pow(10000.0, -((double)(2 * lane) / 64.0));
    float ang = (float)t * (float)inv_freq;
    g_rc[idx] = (float)cos((double)ang);
    g_rs[idx] = (float)sin((double)ang);
}

// ---------------------------------------------------------------------------
// Sliding-window attention (R15 known-good): 256 q-rows, 512 threads,
// pure fp16 operands, ldmatrix, fused RoPE, register-resident P.
// ---------------------------------------------------------------------------
#define KPL 0
#define VPL 4608
#define ATT_SMEM_U32 9216

__global__ void __launch_bounds__(512) attn_kernel() {
    extern __shared__ unsigned sv[];
    const uint32_t sbase = smem_u32(sv);

    const int qt = blockIdx.x;
    const int h = blockIdx.y;
    const int n = blockIdx.z;
    const int q0 = qt * 256;
    const int tid = threadIdx.x;
    const int wid = tid >> 5, lane = tid & 31;
    const int g = lane >> 2, t4 = lane & 3;
    const int qr = wid * 16 + g;

    const size_t hb = ((size_t)(n * NH + h)) * TT * HD;
    const __half* qg = g_qh + hb;
    const __half* kg = g_kh + hb;
    const __half* vg = g_vh + hb;

    const uint32_t aRow36 = (uint32_t)(lane & 15) * 144;
    const uint32_t aColH = (uint32_t)(lane >> 4) * 16;
    const uint32_t bRow36 = (uint32_t)((lane & 7) + ((lane >> 4) << 3)) * 144;
    const uint32_t bRow68 = (uint32_t)((lane & 7) + ((lane >> 4) << 3)) * 272;
    const uint32_t bColH = (uint32_t)((lane >> 3) & 1) * 16;

    // stage Q (256 rows) with fused RoPE
#pragma unroll
    for (int i = 0; i < 4; i++) {
        int idx = tid + i * 512;
        int r = idx >> 3, d4 = idx & 7;
        const __half* row = qg + (size_t)(q0 + r) * HD;
        float4 a = ld4h(row + d4 * 4);
        float4 b = ld4h(row + d4 * 4 + 32);
        const float4 cv = *(const float4*)(g_rc + (size_t)(q0 + r) * 32 + d4 * 4);
        const float4 sn = *(const float4*)(g_rs + (size_t)(q0 + r) * 32 + d4 * 4);
        float4 lo = make_float4(a.x * cv.x - b.x * sn.x, a.y * cv.y - b.y * sn.y,
                                a.z * cv.z - b.z * sn.z, a.w * cv.w - b.w * sn.w);
        float4 hi = make_float4(b.x * cv.x + a.x * sn.x, b.y * cv.y + a.y * sn.y,
                                b.z * cv.z + a.z * sn.z, b.w * cv.w + a.w * sn.w);
        *(uint2*)&sv[r * 36 + d4 * 2] =
            make_uint2(pack2f(lo.x, lo.y), pack2f(lo.z, lo.w));
        *(uint2*)&sv[r * 36 + (d4 + 8) * 2] =
            make_uint2(pack2f(hi.x, hi.y), pack2f(hi.z, hi.w));
    }
    __syncthreads();

    unsigned aqh[4][4];
#pragma unroll
    for (int ks = 0; ks < 4; ks++) {
        uint32_t base = sbase + (wid * 16) * 144 + aRow36 + ks * 32 + aColH;
        ldsm_x4(aqh[ks], base);
    }
    __syncthreads();

    float m_i[2] = {-1e30f, -1e30f};
    float l_i[2] = {0.f, 0.f};
    float o[8][4];
#pragma unroll
    for (int nt = 0; nt < 8; nt++)
#pragma unroll
        for (int r = 0; r < 4; r++) o[nt][r] = 0.f;

    int c0 = 2 * qt - 1; if (c0 < 0) c0 = 0;
    int c1 = 2 * qt + 2; if (c1 > 15) c1 = 15;

    for (int c = c0; c <= c1; c++) {
        const int j0 = c * 128;

        const int rowlo = q0 + wid * 16;
        int ntLo = (rowlo - 127 - j0) >> 3;
        if (ntLo < 0) ntLo = 0;
        ntLo &= ~1;
        int ntHi = (rowlo + 15 + 128 - j0) >> 3;
        if (ntHi > 15) ntHi = 15;
        ntHi |= 1;
        const int kspLo = ntLo >> 1, kspHi = ntHi >> 1;

        // stage K with fused RoPE
#pragma unroll
        for (int i = 0; i < 2; i++) {
            int idx = tid + i * 512;
            int r = idx >> 3, d4 = idx & 7;
            const __half* row = kg + (size_t)(j0 + r) * HD;
            float4 a = ld4h(row + d4 * 4);
            float4 b = ld4h(row + d4 * 4 + 32);
            const float4 cv = *(const float4*)(g_rc + (size_t)(j0 + r) * 32 + d4 * 4);
            const float4 sn = *(const float4*)(g_rs + (size_t)(j0 + r) * 32 + d4 * 4);
            float4 lo = make_float4(a.x * cv.x - b.x * sn.x, a.y * cv.y - b.y * sn.y,
                                    a.z * cv.z - b.z * sn.z, a.w * cv.w - b.w * sn.w);
            float4 hi = make_float4(b.x * cv.x + a.x * sn.x, b.y * cv.y + a.y * sn.y,
                                    b.z * cv.z + a.z * sn.z, b.w * cv.w + a.w * sn.w);
            *(uint2*)&sv[KPL + r * 36 + d4 * 2] =
                make_uint2(pack2f(lo.x, lo.y), pack2f(lo.z, lo.w));
            *(uint2*)&sv[KPL + r * 36 + (d4 + 8) * 2] =
                make_uint2(pack2f(hi.x, hi.y), pack2f(hi.z, hi.w));
        }
        // stage V transposed (zero-convert half2 shuffles)
#pragma unroll
        for (int i = 0; i < 2; i++) {
            int idx = tid + i * 512;
            int rp = idx >> 4, d4 = idx & 15;
            uint2 ua = *(const uint2*)(vg + (size_t)(j0 + 2 * rp) * HD + d4 * 4);
            uint2 ub = *(const uint2*)(vg + (size_t)(j0 + 2 * rp + 1) * HD + d4 * 4);
            __half2 a01 = *reinterpret_cast<__half2*>(&ua.x);
            __half2 a23 = *reinterpret_cast<__half2*>(&ua.y);
            __half2 b01 = *reinterpret_cast<__half2*>(&ub.x);
            __half2 b23 = *reinterpret_cast<__half2*>(&ub.y);
            __half2 p0 = __lows2half2(a01, b01);
            __half2 p1 = __highs2half2(a01, b01);
            __half2 p2 = __lows2half2(a23, b23);
            __half2 p3 = __highs2half2(a23, b23);
            sv[VPL + (d4 * 4 + 0) * 68 + rp] = *reinterpret_cast<unsigned*>(&p0);
            sv[VPL + (d4 * 4 + 1) * 68 + rp] = *reinterpret_cast<unsigned*>(&p1);
            sv[VPL + (d4 * 4 + 2) * 68 + rp] = *reinterpret_cast<unsigned*>(&p2);
            sv[VPL + (d4 * 4 + 3) * 68 + rp] = *reinterpret_cast<unsigned*>(&p3);
        }
        __syncthreads();

        // S = Q . K^T
        float s[16][4];
#pragma unroll
        for (int nt = 0; nt < 16; nt++)
#pragma unroll
            for (int r = 0; r < 4; r++) s[nt][r] = 0.f;

#pragma unroll
        for (int ntp = 0; ntp < 8; ntp++) {
            if (ntp * 2 + 1 < ntLo || ntp * 2 > ntHi) continue;
#pragma unroll
            for (int ks = 0; ks < 4; ks++) {
                unsigned bh4[4];
                uint32_t base = sbase + (ntp * 16) * 144 + bRow36 + ks * 32 + bColH;
                ldsm_x4(bh4, base + KPL * 4);
                mmaf(s[ntp * 2], aqh[ks], bh4);
                mmaf(s[ntp * 2 + 1], aqh[ks], bh4 + 2);
            }
        }

        // mask + online softmax
#pragma unroll
        for (int half = 0; half < 2; half++) {
            const int rowg = q0 + qr + half * 8;
            float mx = -1e30f;
#pragma unroll
            for (int nt = 0; nt < 16; nt++) {
                if (nt < ntLo || nt > ntHi) continue;
#pragma unroll
                for (int cc = 0; cc < 2; cc++) {
                    int colg = j0 + nt * 8 + t4 * 2 + cc;
                    bool valid = (colg >= rowg - 127) && (colg <= rowg + 128);
                    float v = valid ? s[nt][half * 2 + cc] * SCALE : -1e30f;
                    s[nt][half * 2 + cc] = v;
                    mx = fmaxf(mx, v);
                }
            }
            mx = fmaxf(mx, __shfl_xor_sync(0xffffffffu, mx, 1));
            mx = fmaxf(mx, __shfl_xor_sync(0xffffffffu, mx, 2));
            float mnew = fmaxf(m_i[half], mx);
            float alpha = __expf(m_i[half] - mnew);
            float sum = 0.f;
#pragma unroll
            for (int nt = 0; nt < 16; nt++) {
                if (nt < ntLo || nt > ntHi) continue;
#pragma unroll
                for (int cc = 0; cc < 2; cc++) {
                    float v = s[nt][half * 2 + cc];
                    float p = (v > -1e29f) ? __expf(v - mnew) : 0.f;
                    sum += p;
                    s[nt][half * 2 + cc] = p;
                }
            }
            sum += __shfl_xor_sync(0xffffffffu, sum, 1);
            sum += __shfl_xor_sync(0xffffffffu, sum, 2);
            l_i[half] = l_i[half] * alpha + sum;
            m_i[half] = mnew;
#pragma unroll
            for (int nt = 0; nt < 8; nt++) {
                o[nt][half * 2] *= alpha;
                o[nt][half * 2 + 1] *= alpha;
            }
        }

        // O += P . V
#pragma unroll
        for (int ksp = 0; ksp < 8; ksp++) {
            if (ksp < kspLo || ksp > kspHi) continue;
            unsigned aph[4];
            aph[0] = pack2f(s[2 * ksp][0], s[2 * ksp][1]);
            aph[1] = pack2f(s[2 * ksp][2], s[2 * ksp][3]);
            aph[2] = pack2f(s[2 * ksp + 1][0], s[2 * ksp + 1][1]);
            aph[3] = pack2f(s[2 * ksp + 1][2], s[2 * ksp + 1][3]);
#pragma unroll
            for (int ntp = 0; ntp < 4; ntp++) {
                unsigned bh4[4];
                uint32_t vbase = sbase + VPL * 4 + (ntp * 16) * 272 + bRow68 +
                                 ksp * 32 + bColH;
                ldsm_x4(bh4, vbase);
                mmaf(o[ntp * 2], aph, bh4);
                mmaf(o[ntp * 2 + 1], aph, bh4 + 2);
            }
        }
        __syncthreads();
    }

    // epilogue
#pragma unroll
    for (int half = 0; half < 2; half++) {
        const int rowg = q0 + qr + half * 8;
        const float invl = 1.f / l_i[half];
        const size_t ob = ((size_t)n * TT + rowg) * DM + h * HD;
#pragma unroll
        for (int nt = 0; nt < 8; nt++) {
            int d = nt * 8 + t4 * 2;
            *(float2*)(g_ctx + ob + d) =
                make_float2(o[nt][half * 2] * invl, o[nt][half * 2 + 1] * invl);
        }
    }
}

// ---------------------------------------------------------------------------
extern "C" void kernel_launch(void* const* d_in, const int* in_sizes, int n_in,
                              void* d_out, int out_size) {
    const float* x    = (const float*)d_in[0];   // [4,2048,512]
    const float* wqkv = (const float*)d_in[1];   // [1536,512]
    const float* outw = (const float*)d_in[2];   // [512,512]
    const float* outb = (const float*)d_in[3];   // [512]
    float* out = (float*)d_out;

    const int gemm_smem = 2 * GBUF * sizeof(unsigned);        // 110592
    const int att_smem = ATT_SMEM_U32 * sizeof(unsigned);     // 36864

    cudaFuncSetAttribute(gemm_hx<true>, cudaFuncAttributeMaxDynamicSharedMemorySize, gemm_smem);
    cudaFuncSetAttribute(gemm_hx<false>, cudaFuncAttributeMaxDynamicSharedMemorySize, gemm_smem);
    cudaFuncSetAttribute(attn_kernel, cudaFuncAttributeMaxDynamicSharedMemorySize, att_smem);

    __half *xh, *wqh, *owh;
    cudaGetSymbolAddress((void**)&xh, g_xh);
    cudaGetSymbolAddress((void**)&wqh, g_wqh);
    cudaGetSymbolAddress((void**)&owh, g_owh);

    rope_table_kernel<<<(TT * 32 + 255) / 256, 256>>>();
    conv_h<<<(NB * TT * DM / 4 + 255) / 256, 256>>>(x, xh, NB * TT * DM / 4);
    conv_h<<<(3 * DM * DM / 4 + 255) / 256, 256>>>(wqkv, wqh, 3 * DM * DM / 4);
    conv_h<<<(DM * DM / 4 + 255) / 256, 256>>>(outw, owh, DM * DM / 4);

    gemm_hx<true><<<dim3(1536 / 128, 8192 / 128), 512, gemm_smem>>>(nullptr, nullptr);
    attn_kernel<<<dim3(TT / 256, NH, NB), 512, att_smem>>>();
    gemm_hx<false><<<dim3(512 / 128, 8192 / 128), 512, gemm_smem>>>(outb, out);
}

// round 17
// speedup vs baseline: 1.5353x; 1.0095x over previous
#include <cuda_runtime.h>
#include <cuda_fp16.h>
#include <math.h>
#include <cstdint>

#define NB 4
#define TT 2048
#define DM 512
#define NH 8
#define HD 64
#define SCALE 0.125f

// Scratch (no allocation allowed)
__device__ __half g_qh[NB * NH * TT * HD];
__device__ __half g_kh[NB * NH * TT * HD];
__device__ __half g_vh[NB * NH * TT * HD];
__device__ __half g_cth[NB * TT * DM];   // ctx hi plane
__device__ __half g_ctl[NB * TT * DM];   // ctx lo plane
__device__ float g_rc[TT * 32];
__device__ float g_rs[TT * 32];
// pre-converted fp16 operands
__device__ __half g_xh[NB * TT * DM];
__device__ __half g_wqh[3 * DM * DM];
__device__ __half g_owh[DM * DM];

// pack two floats -> f16x2 (e0 in low half), rne
__device__ __forceinline__ unsigned pack2f(float e0, float e1) {
    unsigned r;
    asm("cvt.rn.f16x2.f32 %0, %1, %2;" : "=r"(r) : "f"(e1), "f"(e0));
    return r;
}
// split (f0,f1) into hi f16x2 + lo (residual) f16x2
__device__ __forceinline__ void split2f(float f0, float f1, unsigned& hi, unsigned& lo) {
    unsigned h = pack2f(f0, f1);
    float h0, h1;
    asm("{.reg .b16 x, y; mov.b32 {x, y}, %2; cvt.f32.f16 %0, x; cvt.f32.f16 %1, y;}"
        : "=f"(h0), "=f"(h1) : "r"(h));
    lo = pack2f(f0 - h0, f1 - h1);
    hi = h;
}
__device__ __forceinline__ void mmaf(float* c, const unsigned* a, const unsigned* b) {
    asm volatile(
        "mma.sync.aligned.m16n8k16.row.col.f32.f16.f16.f32 "
        "{%0,%1,%2,%3},{%4,%5,%6,%7},{%8,%9},{%0,%1,%2,%3};"
        : "+f"(c[0]), "+f"(c[1]), "+f"(c[2]), "+f"(c[3])
        : "r"(a[0]), "r"(a[1]), "r"(a[2]), "r"(a[3]), "r"(b[0]), "r"(b[1]));
}
__device__ __forceinline__ uint32_t smem_u32(const void* p) {
    uint32_t a;
    asm("{ .reg .u64 t; cvta.to.shared.u64 t, %1; cvt.u32.u64 %0, t; }" : "=r"(a) : "l"(p));
    return a;
}
__device__ __forceinline__ void ldsm_x4(unsigned* r, uint32_t addr) {
    asm volatile("ldmatrix.sync.aligned.m8n8.x4.shared.b16 {%0,%1,%2,%3}, [%4];"
                 : "=r"(r[0]), "=r"(r[1]), "=r"(r[2]), "=r"(r[3]) : "r"(addr));
}
// load 4 consecutive halves -> float4
__device__ __forceinline__ float4 ld4h(const __half* p) {
    uint2 u = *(const uint2*)p;
    float2 f01 = __half22float2(*reinterpret_cast<__half2*>(&u.x));
    float2 f23 = __half22float2(*reinterpret_cast<__half2*>(&u.y));
    return make_float4(f01.x, f01.y, f23.x, f23.y);
}

// ---------------------------------------------------------------------------
// Fused prologue: rope trig table + 3 fp32->fp16 converts, region-branched.
// Region sizes (in work items): rope 65536; x 1048576 f4; wqkv 196608 f4;
// outw 65536 f4. Total 1376256 -> 5376 blocks of 256.
// ---------------------------------------------------------------------------
#define RT_N (TT * 32)
#define X4_N (NB * TT * DM / 4)
#define WQ4_N (3 * DM * DM / 4)
#define OW4_N (DM * DM / 4)
#define PREP_TOTAL (RT_N + X4_N + WQ4_N + OW4_N)

__global__ void __launch_bounds__(256) prep_kernel(const float* __restrict__ x,
                                                   const float* __restrict__ wqkv,
                                                   const float* __restrict__ outw) {
    int idx = blockIdx.x * 256 + threadIdx.x;
    if (idx < RT_N) {
        int t = idx >> 5, lane = idx & 31;
        double inv_freq = pow(10000.0, -((double)(2 * lane) / 64.0));
        float ang = (float)t * (float)inv_freq;
        g_rc[idx] = (float)cos((double)ang);
        g_rs[idx] = (float)sin((double)ang);
        return;
    }
    idx -= RT_N;
    const float* src;
    __half* dst;
    if (idx < X4_N) {
        src = x; dst = g_xh;
    } else if (idx < X4_N + WQ4_N) {
        idx -= X4_N; src = wqkv; dst = g_wqh;
    } else if (idx < X4_N + WQ4_N + OW4_N) {
        idx -= X4_N + WQ4_N; src = outw; dst = g_owh;
    } else return;
    float4 v = ((const float4*)src)[idx];
    ((uint2*)dst)[idx] = make_uint2(pack2f(v.x, v.y), pack2f(v.z, v.w));
}

// ---------------------------------------------------------------------------
// FP16 GEMM, K-chunk 64.
// QKV=true: A=g_xh fp16, W=g_wqh, epilogue -> fp16 q/k/v.
// QKV=false: A=ctx hi/lo fp16 planes, W=g_owh, epilogue -> fp32 out + bias.
// Block 128m x 128e, 512 threads = 16 warps (4m x 4e), warp tile 32x32.
// ---------------------------------------------------------------------------
#define GAH 0
#define GAL 4608
#define GWH 9216
#define GBUF 13824

template <bool QKV>
__global__ void __launch_bounds__(512, 1) gemm_hx(const float* __restrict__ bias,
                                                  float* __restrict__ out) {
    extern __shared__ unsigned gsm[];
    const uint32_t sbase = smem_u32(gsm);

    const int e0 = blockIdx.x * 128;
    const int m0 = blockIdx.y * 128;
    const int tid = threadIdx.x;
    const int wid = tid >> 5, lane = tid & 31;
    const int wm = wid >> 2, wn = wid & 3;   // 4m x 4e
    const int g = lane >> 2, t4 = lane & 3;

    const __half* Ah = QKV ? g_xh : g_cth;
    const __half* Al = g_ctl;
    const __half* Wh = QKV ? g_wqh : g_owh;

    float acc[2][4][4];
#pragma unroll
    for (int mt = 0; mt < 2; mt++)
#pragma unroll
        for (int nt = 0; nt < 4; nt++)
#pragma unroll
            for (int r = 0; r < 4; r++) acc[mt][nt][r] = 0.f;

    uint4 avh[2], avl[2], wvh[2];

#define LDG_CHUNK(KC)                                                                  \
    do {                                                                               \
        _Pragma("unroll") for (int i = 0; i < 2; i++) {                                \
            int idx = tid + i * 512;                                                   \
            int r = idx >> 3, c = idx & 7;                                             \
            avh[i] = *(const uint4*)(Ah + (size_t)(m0 + r) * 512 + (KC) + c * 8);      \
            if (!QKV)                                                                  \
                avl[i] = *(const uint4*)(Al + (size_t)(m0 + r) * 512 + (KC) + c * 8);  \
        }                                                                              \
        _Pragma("unroll") for (int i = 0; i < 2; i++) {                                \
            int idx = tid + i * 512;                                                   \
            int r = idx >> 3, c = idx & 7;                                             \
            wvh[i] = *(const uint4*)(Wh + (size_t)(e0 + r) * 512 + (KC) + c * 8);      \
        }                                                                              \
    } while (0)

#define STS_CHUNK(BUF)                                                    \
    do {                                                                  \
        unsigned* b_ = (BUF);                                             \
        _Pragma("unroll") for (int i = 0; i < 2; i++) {                   \
            int idx = tid + i * 512;                                      \
            int r = idx >> 3, c = idx & 7;                                \
            *(uint4*)&b_[GAH + r * 36 + c * 4] = avh[i];                  \
            if (!QKV) *(uint4*)&b_[GAL + r * 36 + c * 4] = avl[i];        \
        }                                                                 \
        _Pragma("unroll") for (int i = 0; i < 2; i++) {                   \
            int idx = tid + i * 512;                                      \
            int r = idx >> 3, c = idx & 7;                                \
            *(uint4*)&b_[GWH + r * 36 + c * 4] = wvh[i];                  \
        }                                                                 \
    } while (0)

    LDG_CHUNK(0);
    STS_CHUNK(gsm);
    __syncthreads();

    const uint32_t aRowOff = (uint32_t)(lane & 15) * 144;
    const uint32_t aColOff = (uint32_t)(lane >> 4) * 16;
    const uint32_t bRowOff = (uint32_t)((lane & 7) + ((lane >> 4) << 3)) * 144;
    const uint32_t bColOff = (uint32_t)((lane >> 3) & 1) * 16;

    int cur = 0;
    for (int kc = 0; kc < 512; kc += 64) {
        if (kc + 64 < 512) LDG_CHUNK(kc + 64);
        const uint32_t bb = sbase + cur * (GBUF * 4);
#pragma unroll
        for (int ks = 0; ks < 4; ks++) {
            const uint32_t kOff = ks * 32;
            unsigned ah[2][4], al[2][4], bh[2][4];
#pragma unroll
            for (int mt = 0; mt < 2; mt++) {
                uint32_t base = bb + (wm * 32 + mt * 16) * 144 + aRowOff + kOff + aColOff;
                ldsm_x4(ah[mt], base + GAH * 4);
                if (!QKV) ldsm_x4(al[mt], base + GAL * 4);
            }
#pragma unroll
            for (int ntp = 0; ntp < 2; ntp++) {
                uint32_t base = bb + (wn * 32 + ntp * 16) * 144 + bRowOff + kOff + bColOff;
                ldsm_x4(bh[ntp], base + GWH * 4);
            }
#pragma unroll
            for (int mt = 0; mt < 2; mt++)
#pragma unroll
                for (int nt = 0; nt < 4; nt++) {
                    const unsigned* BH = &bh[nt >> 1][(nt & 1) * 2];
                    mmaf(acc[mt][nt], ah[mt], BH);
                    if (!QKV) mmaf(acc[mt][nt], al[mt], BH);
                }
        }
        if (kc + 64 < 512) STS_CHUNK(gsm + (cur ^ 1) * GBUF);
        __syncthreads();
        cur ^= 1;
    }

    if (QKV) {
#pragma unroll
        for (int mt = 0; mt < 2; mt++)
#pragma unroll
            for (int half = 0; half < 2; half++) {
                int m = m0 + wm * 32 + mt * 16 + g + half * 8;
                int nbt = m >> 11, tt = m & 2047;
#pragma unroll
                for (int nt = 0; nt < 4; nt++) {
                    int e = e0 + wn * 32 + nt * 8 + t4 * 2;
                    int sec = e >> 9;
                    int h = (e >> 6) & 7;
                    int d = e & 63;
                    __half* buf = (sec == 0) ? g_qh : (sec == 1) ? g_kh : g_vh;
                    *(unsigned*)(buf + (((size_t)(nbt * NH + h)) * TT + tt) * HD + d) =
                        pack2f(acc[mt][nt][half * 2], acc[mt][nt][half * 2 + 1]);
                }
            }
    } else {
#pragma unroll
        for (int mt = 0; mt < 2; mt++)
#pragma unroll
            for (int half = 0; half < 2; half++) {
                int m = m0 + wm * 32 + mt * 16 + g + half * 8;
#pragma unroll
                for (int nt = 0; nt < 4; nt++) {
                    int e = e0 + wn * 32 + nt * 8 + t4 * 2;
                    float2 bv = *(const float2*)(bias + e);
                    *(float2*)(out + (size_t)m * 512 + e) =
                        make_float2(acc[mt][nt][half * 2] + bv.x,
                                    acc[mt][nt][half * 2 + 1] + bv.y);
                }
            }
    }
}

// ---------------------------------------------------------------------------
// Sliding-window attention (R15/R16 known-good core): 256 q-rows, 512 threads,
// pure fp16 operands, ldmatrix, fused RoPE, register-resident P.
// Epilogue writes ctx as fp16 hi/lo planes (bit-identical to fp32+later split).
// ---------------------------------------------------------------------------
#define KPL 0
#define VPL 4608
#define ATT_SMEM_U32 9216

__global__ void __launch_bounds__(512) attn_kernel() {
    extern __shared__ unsigned sv[];
    const uint32_t sbase = smem_u32(sv);

    const int qt = blockIdx.x;
    const int h = blockIdx.y;
    const int n = blockIdx.z;
    const int q0 = qt * 256;
    const int tid = threadIdx.x;
    const int wid = tid >> 5, lane = tid & 31;
    const int g = lane >> 2, t4 = lane & 3;
    const int qr = wid * 16 + g;

    const size_t hb = ((size_t)(n * NH + h)) * TT * HD;
    const __half* qg = g_qh + hb;
    const __half* kg = g_kh + hb;
    const __half* vg = g_vh + hb;

    const uint32_t aRow36 = (uint32_t)(lane & 15) * 144;
    const uint32_t aColH = (uint32_t)(lane >> 4) * 16;
    const uint32_t bRow36 = (uint32_t)((lane & 7) + ((lane >> 4) << 3)) * 144;
    const uint32_t bRow68 = (uint32_t)((lane & 7) + ((lane >> 4) << 3)) * 272;
    const uint32_t bColH = (uint32_t)((lane >> 3) & 1) * 16;

    // stage Q (256 rows) with fused RoPE
#pragma unroll
    for (int i = 0; i < 4; i++) {
        int idx = tid + i * 512;
        int r = idx >> 3, d4 = idx & 7;
        const __half* row = qg + (size_t)(q0 + r) * HD;
        float4 a = ld4h(row + d4 * 4);
        float4 b = ld4h(row + d4 * 4 + 32);
        const float4 cv = *(const float4*)(g_rc + (size_t)(q0 + r) * 32 + d4 * 4);
        const float4 sn = *(const float4*)(g_rs + (size_t)(q0 + r) * 32 + d4 * 4);
        float4 lo = make_float4(a.x * cv.x - b.x * sn.x, a.y * cv.y - b.y * sn.y,
                                a.z * cv.z - b.z * sn.z, a.w * cv.w - b.w * sn.w);
        float4 hi = make_float4(b.x * cv.x + a.x * sn.x, b.y * cv.y + a.y * sn.y,
                                b.z * cv.z + a.z * sn.z, b.w * cv.w + a.w * sn.w);
        *(uint2*)&sv[r * 36 + d4 * 2] =
            make_uint2(pack2f(lo.x, lo.y), pack2f(lo.z, lo.w));
        *(uint2*)&sv[r * 36 + (d4 + 8) * 2] =
            make_uint2(pack2f(hi.x, hi.y), pack2f(hi.z, hi.w));
    }
    __syncthreads();

    unsigned aqh[4][4];
#pragma unroll
    for (int ks = 0; ks < 4; ks++) {
        uint32_t base = sbase + (wid * 16) * 144 + aRow36 + ks * 32 + aColH;
        ldsm_x4(aqh[ks], base);
    }
    __syncthreads();

    float m_i[2] = {-1e30f, -1e30f};
    float l_i[2] = {0.f, 0.f};
    float o[8][4];
#pragma unroll
    for (int nt = 0; nt < 8; nt++)
#pragma unroll
        for (int r = 0; r < 4; r++) o[nt][r] = 0.f;

    int c0 = 2 * qt - 1; if (c0 < 0) c0 = 0;
    int c1 = 2 * qt + 2; if (c1 > 15) c1 = 15;

    for (int c = c0; c <= c1; c++) {
        const int j0 = c * 128;

        const int rowlo = q0 + wid * 16;
        int ntLo = (rowlo - 127 - j0) >> 3;
        if (ntLo < 0) ntLo = 0;
        ntLo &= ~1;
        int ntHi = (rowlo + 15 + 128 - j0) >> 3;
        if (ntHi > 15) ntHi = 15;
        ntHi |= 1;
        const int kspLo = ntLo >> 1, kspHi = ntHi >> 1;

        // stage K with fused RoPE
#pragma unroll
        for (int i = 0; i < 2; i++) {
            int idx = tid + i * 512;
            int r = idx >> 3, d4 = idx & 7;
            const __half* row = kg + (size_t)(j0 + r) * HD;
            float4 a = ld4h(row + d4 * 4);
            float4 b = ld4h(row + d4 * 4 + 32);
            const float4 cv = *(const float4*)(g_rc + (size_t)(j0 + r) * 32 + d4 * 4);
            const float4 sn = *(const float4*)(g_rs + (size_t)(j0 + r) * 32 + d4 * 4);
            float4 lo = make_float4(a.x * cv.x - b.x * sn.x, a.y * cv.y - b.y * sn.y,
                                    a.z * cv.z - b.z * sn.z, a.w * cv.w - b.w * sn.w);
            float4 hi = make_float4(b.x * cv.x + a.x * sn.x, b.y * cv.y + a.y * sn.y,
                                    b.z * cv.z + a.z * sn.z, b.w * cv.w + a.w * sn.w);
            *(uint2*)&sv[KPL + r * 36 + d4 * 2] =
                make_uint2(pack2f(lo.x, lo.y), pack2f(lo.z, lo.w));
            *(uint2*)&sv[KPL + r * 36 + (d4 + 8) * 2] =
                make_uint2(pack2f(hi.x, hi.y), pack2f(hi.z, hi.w));
        }
        // stage V transposed (zero-convert half2 shuffles)
#pragma unroll
        for (int i = 0; i < 2; i++) {
            int idx = tid + i * 512;
            int rp = idx >> 4, d4 = idx & 15;
            uint2 ua = *(const uint2*)(vg + (size_t)(j0 + 2 * rp) * HD + d4 * 4);
            uint2 ub = *(const uint2*)(vg + (size_t)(j0 + 2 * rp + 1) * HD + d4 * 4);
            __half2 a01 = *reinterpret_cast<__half2*>(&ua.x);
            __half2 a23 = *reinterpret_cast<__half2*>(&ua.y);
            __half2 b01 = *reinterpret_cast<__half2*>(&ub.x);
            __half2 b23 = *reinterpret_cast<__half2*>(&ub.y);
            __half2 p0 = __lows2half2(a01, b01);
            __half2 p1 = __highs2half2(a01, b01);
            __half2 p2 = __lows2half2(a23, b23);
            __half2 p3 = __highs2half2(a23, b23);
            sv[VPL + (d4 * 4 + 0) * 68 + rp] = *reinterpret_cast<unsigned*>(&p0);
            sv[VPL + (d4 * 4 + 1) * 68 + rp] = *reinterpret_cast<unsigned*>(&p1);
            sv[VPL + (d4 * 4 + 2) * 68 + rp] = *reinterpret_cast<unsigned*>(&p2);
            sv[VPL + (d4 * 4 + 3) * 68 + rp] = *reinterpret_cast<unsigned*>(&p3);
        }
        __syncthreads();

        // S = Q . K^T
        float s[16][4];
#pragma unroll
        for (int nt = 0; nt < 16; nt++)
#pragma unroll
            for (int r = 0; r < 4; r++) s[nt][r] = 0.f;

#pragma unroll
        for (int ntp = 0; ntp < 8; ntp++) {
            if (ntp * 2 + 1 < ntLo || ntp * 2 > ntHi) continue;
#pragma unroll
            for (int ks = 0; ks < 4; ks++) {
                unsigned bh4[4];
                uint32_t base = sbase + (ntp * 16) * 144 + bRow36 + ks * 32 + bColH;
                ldsm_x4(bh4, base + KPL * 4);
                mmaf(s[ntp * 2], aqh[ks], bh4);
                mmaf(s[ntp * 2 + 1], aqh[ks], bh4 + 2);
            }
        }

        // mask + online softmax
#pragma unroll
        for (int half = 0; half < 2; half++) {
            const int rowg = q0 + qr + half * 8;
            float mx = -1e30f;
#pragma unroll
            for (int nt = 0; nt < 16; nt++) {
                if (nt < ntLo || nt > ntHi) continue;
#pragma unroll
                for (int cc = 0; cc < 2; cc++) {
                    int colg = j0 + nt * 8 + t4 * 2 + cc;
                    bool valid = (colg >= rowg - 127) && (colg <= rowg + 128);
                    float v = valid ? s[nt][half * 2 + cc] * SCALE : -1e30f;
                    s[nt][half * 2 + cc] = v;
                    mx = fmaxf(mx, v);
                }
            }
            mx = fmaxf(mx, __shfl_xor_sync(0xffffffffu, mx, 1));
            mx = fmaxf(mx, __shfl_xor_sync(0xffffffffu, mx, 2));
            float mnew = fmaxf(m_i[half], mx);
            float alpha = __expf(m_i[half] - mnew);
            float sum = 0.f;
#pragma unroll
            for (int nt = 0; nt < 16; nt++) {
                if (nt < ntLo || nt > ntHi) continue;
#pragma unroll
                for (int cc = 0; cc < 2; cc++) {
                    float v = s[nt][half * 2 + cc];
                    float p = (v > -1e29f) ? __expf(v - mnew) : 0.f;
                    sum += p;
                    s[nt][half * 2 + cc] = p;
                }
            }
            sum += __shfl_xor_sync(0xffffffffu, sum, 1);
            sum += __shfl_xor_sync(0xffffffffu, sum, 2);
            l_i[half] = l_i[half] * alpha + sum;
            m_i[half] = mnew;
#pragma unroll
            for (int nt = 0; nt < 8; nt++) {
                o[nt][half * 2] *= alpha;
                o[nt][half * 2 + 1] *= alpha;
            }
        }

        // O += P . V
#pragma unroll
        for (int ksp = 0; ksp < 8; ksp++) {
            if (ksp < kspLo || ksp > kspHi) continue;
            unsigned aph[4];
            aph[0] = pack2f(s[2 * ksp][0], s[2 * ksp][1]);
            aph[1] = pack2f(s[2 * ksp][2], s[2 * ksp][3]);
            aph[2] = pack2f(s[2 * ksp + 1][0], s[2 * ksp + 1][1]);
            aph[3] = pack2f(s[2 * ksp + 1][2], s[2 * ksp + 1][3]);
#pragma unroll
            for (int ntp = 0; ntp < 4; ntp++) {
                unsigned bh4[4];
                uint32_t vbase = sbase + VPL * 4 + (ntp * 16) * 272 + bRow68 +
                                 ksp * 32 + bColH;
                ldsm_x4(bh4, vbase);
                mmaf(o[ntp * 2], aph, bh4);
                mmaf(o[ntp * 2 + 1], aph, bh4 + 2);
            }
        }
        __syncthreads();
    }

    // epilogue: normalize + split to fp16 hi/lo ctx planes (token-major)
#pragma unroll
    for (int half = 0; half < 2; half++) {
        const int rowg = q0 + qr + half * 8;
        const float invl = 1.f / l_i[half];
        const size_t ob = ((size_t)n * TT + rowg) * DM + h * HD;
#pragma unroll
        for (int nt = 0; nt < 8; nt++) {
            int d = nt * 8 + t4 * 2;
            unsigned hh, ll;
            split2f(o[nt][half * 2] * invl, o[nt][half * 2 + 1] * invl, hh, ll);
            ((unsigned*)g_cth)[(ob + d) >> 1] = hh;
            ((unsigned*)g_ctl)[(ob + d) >> 1] = ll;
        }
    }
}

// ---------------------------------------------------------------------------
extern "C" void kernel_launch(void* const* d_in, const int* in_sizes, int n_in,
                              void* d_out, int out_size) {
    const float* x    = (const float*)d_in[0];   // [4,2048,512]
    const float* wqkv = (const float*)d_in[1];   // [1536,512]
    const float* outw = (const float*)d_in[2];   // [512,512]
    const float* outb = (const float*)d_in[3];   // [512]
    float* out = (float*)d_out;

    const int gemm_smem = 2 * GBUF * sizeof(unsigned);        // 110592
    const int att_smem = ATT_SMEM_U32 * sizeof(unsigned);     // 36864

    cudaFuncSetAttribute(gemm_hx<true>, cudaFuncAttributeMaxDynamicSharedMemorySize, gemm_smem);
    cudaFuncSetAttribute(gemm_hx<false>, cudaFuncAttributeMaxDynamicSharedMemorySize, gemm_smem);
    cudaFuncSetAttribute(attn_kernel, cudaFuncAttributeMaxDynamicSharedMemorySize, att_smem);

    prep_kernel<<<(PREP_TOTAL + 255) / 256, 256>>>(x, wqkv, outw);
    gemm_hx<true><<<dim3(1536 / 128, 8192 / 128), 512, gemm_smem>>>(nullptr, nullptr);
    attn_kernel<<<dim3(TT / 256, NH, NB), 512, att_smem>>>();
    gemm_hx<false><<<dim3(512 / 128, 8192 / 128), 512, gemm_smem>>>(outb, out);
}